// round 10
// baseline (speedup 1.0000x reference)
#include <cuda_runtime.h>
#include <cuda_bf16.h>
#include <math.h>

// ---------------- scratch ----------------
__device__ float g_f0[32u * 32 * 128 * 128];   // fp32 NCHW ping
__device__ float g_f1[32u * 32 * 128 * 128];   // fp32 NCHW pong
__device__ unsigned g_b0[16777216];            // fragment-native bf16 planes ping
__device__ unsigned g_b1[16777216];            // fragment-native bf16 planes pong
__device__ uint4 g_wprep[60480];               // s1 mma weights
__device__ uint4 g_wprep2[106496];             // s2c mma weights
__device__ float g_S[4096];
__device__ float g_Sh[4096];
__device__ float g_Sw[4096];

// fragment-native plane format: per pixel, per 16-channel chunk, 16 words:
//   m = 4*tg + s;  s=0: hi ch(2tg,2tg+1)  s=1: hi ch(2tg+8,2tg+9)
//                  s=2: lo ch(2tg,2tg+1)  s=3: lo ch(2tg+8,2tg+9)
// word low half = even channel. pixel stride = C words.

__device__ __forceinline__ float activate(float v, int act) {
    switch (act) {
        case 1: return v > 0.f ? v : 0.2f * v;
        case 2: return v > 0.f ? v : 0.f;
        case 3: return fmaxf(v, 0.f) + log1pf(expf(-fabsf(v)));
        default: return v;
    }
}

__device__ __forceinline__ void split_bf16(float x, unsigned short& h, unsigned short& l) {
    h = __bfloat16_as_ushort(__float2bfloat16(x));
    float hf = __uint_as_float((unsigned)h << 16);
    l = __bfloat16_as_ushort(__float2bfloat16(x - hf));
}
__device__ __forceinline__ unsigned pack_us(unsigned short a, unsigned short b) {
    return ((unsigned)b << 16) | (unsigned)a;
}
__device__ __forceinline__ unsigned pack2_bf16(float e_lo, float e_hi) {
    return ((unsigned)__bfloat16_as_ushort(__float2bfloat16(e_hi)) << 16)
         | (unsigned)__bfloat16_as_ushort(__float2bfloat16(e_lo));
}
// pack hi/lo words for a channel pair (even, odd)
__device__ __forceinline__ void pack_pair(float v0, float v1, unsigned& wh, unsigned& wl) {
    unsigned short h0, l0, h1, l1;
    split_bf16(v0, h0, l0);
    split_bf16(v1, h1, l1);
    wh = pack_us(h0, h1);
    wl = pack_us(l0, l1);
}

__device__ __forceinline__ void cp_async4(void* sdst, const void* gsrc, bool pred) {
    unsigned saddr = (unsigned)__cvta_generic_to_shared(sdst);
    int sz = pred ? 4 : 0;
    asm volatile("cp.async.ca.shared.global [%0], [%1], 4, %2;\n"
                 :: "r"(saddr), "l"(gsrc), "r"(sz));
}
__device__ __forceinline__ void cp_async16(void* sdst, const void* gsrc, bool pred) {
    unsigned saddr = (unsigned)__cvta_generic_to_shared(sdst);
    int sz = pred ? 16 : 0;
    asm volatile("cp.async.cg.shared.global [%0], [%1], 16, %2;\n"
                 :: "r"(saddr), "l"(gsrc), "r"(sz));
}
__device__ __forceinline__ void cp_commit() { asm volatile("cp.async.commit_group;\n"); }
__device__ __forceinline__ void cp_wait0() { asm volatile("cp.async.wait_group 0;\n"); }

__device__ __forceinline__ void mma16816(float* d, const unsigned* a, unsigned b0, unsigned b1) {
    asm volatile("mma.sync.aligned.m16n8k16.row.col.f32.bf16.bf16.f32 "
                 "{%0,%1,%2,%3},{%4,%5,%6,%7},{%8,%9},{%0,%1,%2,%3};"
                 : "+f"(d[0]), "+f"(d[1]), "+f"(d[2]), "+f"(d[3])
                 : "r"(a[0]), "r"(a[1]), "r"(a[2]), "r"(a[3]), "r"(b0), "r"(b1));
}

// =====================================================================
// s1 weight prep (3 layers/launch)
// =====================================================================
__global__ void prep_many(const float* __restrict__ w0, const float* __restrict__ w1,
                          const float* __restrict__ w2, uint4* __restrict__ dstb,
                          int off0, int off1, int off2,
                          int C0, int OC0, int C1, int OC1, int C2, int OC2)
{
    int layer = blockIdx.y;
    const float* w = layer == 0 ? w0 : layer == 1 ? w1 : w2;
    uint4* dst = dstb + (layer == 0 ? off0 : layer == 1 ? off1 : off2);
    int C = layer == 0 ? C0 : layer == 1 ? C1 : C2;
    int OC = layer == 0 ? OC0 : layer == 1 ? OC1 : OC2;
    int OCg = OC >> 3;
    int total = (C >> 4) * 9 * OCg * 32;
    int idx = blockIdx.x * 256 + threadIdx.x;
    if (idx >= total) return;
    int l = idx & 31;
    int q = idx >> 5;
    int og = q % OCg; q /= OCg;
    int t = q % 9;
    int kc = q / 9;
    int tg = l & 3, gg = l >> 2;
    int n = og * 8 + gg;
    float h[4], lo[4];
#pragma unroll
    for (int kk = 0; kk < 4; kk++) {
        int k = (kk < 2) ? (2 * tg + kk) : (2 * tg + 8 + (kk - 2));
        int ic = (kc << 4) + k;
        float e = w[((size_t)n * C + ic) * 9 + t];
        unsigned hb = (unsigned)__bfloat16_as_ushort(__float2bfloat16(e)) << 16;
        h[kk] = __uint_as_float(hb);
        lo[kk] = e - h[kk];
    }
    uint4 r;
    r.x = pack2_bf16(h[0], h[1]);
    r.y = pack2_bf16(h[2], h[3]);
    r.z = pack2_bf16(lo[0], lo[1]);
    r.w = pack2_bf16(lo[2], lo[3]);
    dst[idx] = r;
}

// =====================================================================
// s2c weight prep: stride-2 3x3 -> 2x2 over 4C phase channels (q*C+c).
// =====================================================================
__global__ void prep_s2c(const float* __restrict__ w0, const float* __restrict__ w1,
                         const float* __restrict__ w2, uint4* __restrict__ dstb,
                         int off0, int off1, int off2,
                         int C0, int OC0, int C1, int OC1, int C2, int OC2)
{
    int layer = blockIdx.y;
    const float* w = layer == 0 ? w0 : layer == 1 ? w1 : w2;
    uint4* dst = dstb + (layer == 0 ? off0 : layer == 1 ? off1 : off2);
    int C = layer == 0 ? C0 : layer == 1 ? C1 : C2;
    int OC = layer == 0 ? OC0 : layer == 1 ? OC1 : OC2;
    int OCg = OC >> 3;
    int KC = (4 * C) >> 4;
    int total = KC * 4 * OCg * 32;
    int idx = blockIdx.x * 256 + threadIdx.x;
    if (idx >= total) return;
    int l = idx & 31;
    int q = idx >> 5;
    int og = q % OCg; q /= OCg;
    int t = q % 4;
    int kc = q / 4;
    int dy = t >> 1, dx = t & 1;
    int tg = l & 3, gg = l >> 2;
    int n = og * 8 + gg;
    float h[4], lo[4];
#pragma unroll
    for (int kk = 0; kk < 4; kk++) {
        int k = (kk < 2) ? (2 * tg + kk) : (2 * tg + 8 + (kk - 2));
        int ch = (kc << 4) + k;
        int qph = ch / C, c = ch - qph * C;
        int a = qph >> 1, bph = qph & 1;
        int ky = 2 * dy + a, kx = 2 * dx + bph;
        float e = (ky < 3 && kx < 3) ? w[((size_t)n * C + c) * 9 + ky * 3 + kx] : 0.f;
        unsigned hb = (unsigned)__bfloat16_as_ushort(__float2bfloat16(e)) << 16;
        h[kk] = __uint_as_float(hb);
        lo[kk] = e - h[kk];
    }
    uint4 r;
    r.x = pack2_bf16(h[0], h[1]);
    r.y = pack2_bf16(h[2], h[3]);
    r.z = pack2_bf16(lo[0], lo[1]);
    r.w = pack2_bf16(lo[2], lo[3]);
    dst[idx] = r;
}

// =====================================================================
// tensor-core stride-1 3x3 SAME conv (bf16x3 split).
// in: fragment-native planes. out mode 0: fp32 NCHW; mode 1: planes.
// =====================================================================
#define SINW (324 * 16)
#define MMA_SW (9 * 4 * 32)
#define MMA_SMEM (2 * SINW * 4 + 2 * MMA_SW * 16)

__global__ void __launch_bounds__(256, 2) conv_mma_s1(
    const unsigned* __restrict__ in, const uint4* __restrict__ wp,
    const float* __restrict__ bias, float* __restrict__ fout,
    unsigned* __restrict__ bout, int C, int OC, int H, int W, int act, int mode)
{
    const int KC = C >> 4;
    const int tilesX = W >> 4;
    const int x0 = (blockIdx.x % tilesX) << 4;
    const int y0 = (blockIdx.x / tilesX) << 4;
    const int oc0 = blockIdx.y << 5;
    const int b = blockIdx.z;
    const int OCg = OC >> 3;
    int nf = OCg - (oc0 >> 3); if (nf > 4) nf = 4;

    extern __shared__ __align__(16) unsigned char dsm[];
    unsigned* s_in = (unsigned*)dsm;                 // [2][SINW]
    uint4* s_w = (uint4*)(dsm + 2 * SINW * 4);       // [2][MMA_SW]

    const unsigned* inb = in + (size_t)b * H * W * C;
    const int tid = threadIdx.x, lane = tid & 31, wid = tid >> 5;
    const int g = lane >> 2, tg = lane & 3;

    float d[2][4][4];
#pragma unroll
    for (int i = 0; i < 2; i++)
#pragma unroll
        for (int j = 0; j < 4; j++)
#pragma unroll
            for (int r = 0; r < 4; r++) d[i][j][r] = 0.f;

    auto stage = [&](int buf, int kc) {
        unsigned* si = s_in + buf * SINW;
        for (int i = tid; i < 324 * 4; i += 256) {
            int sp = i >> 2, q = i & 3;
            int r = sp / 18, c = sp - r * 18;
            int iy = y0 - 1 + r, ix = x0 - 1 + c;
            bool p = (unsigned)iy < (unsigned)H && (unsigned)ix < (unsigned)W;
            cp_async16(si + sp * 16 + q * 4,
                       inb + ((size_t)iy * W + ix) * C + (kc << 4) + (q << 2), p);
        }
        uint4* sw = s_w + buf * MMA_SW;
        const uint4* wsrc = wp + (size_t)kc * 9 * OCg * 32;
        int tot = 9 * nf * 32;
        for (int i = tid; i < tot; i += 256) {
            int l = i & 31;
            int q = i >> 5;
            int ogl = q % nf;
            int t = q / nf;
            cp_async16(sw + (t * 4 + ogl) * 32 + l,
                       wsrc + ((size_t)t * OCg + (oc0 >> 3) + ogl) * 32 + l, true);
        }
    };

    auto compute = [&](int buf) {
        unsigned* si = s_in + buf * SINW;
        uint4* sw = s_w + buf * MMA_SW;
#pragma unroll
        for (int t = 0; t < 9; t++) {
            const int dy = t / 3, dx = t - 3 * (t / 3);
            unsigned ah[2][4], al[2][4];
#pragma unroll
            for (int i = 0; i < 2; i++) {
                int sp0 = (2 * wid + i + dy) * 18 + g + dx;
                uint4 va = *(const uint4*)(si + sp0 * 16 + 4 * tg);
                uint4 vb = *(const uint4*)(si + (sp0 + 8) * 16 + 4 * tg);
                ah[i][0] = va.x; ah[i][2] = va.y; al[i][0] = va.z; al[i][2] = va.w;
                ah[i][1] = vb.x; ah[i][3] = vb.y; al[i][1] = vb.z; al[i][3] = vb.w;
            }
            for (int j = 0; j < nf; j++) {
                uint4 bw = sw[(t * 4 + j) * 32 + lane];
#pragma unroll
                for (int i = 0; i < 2; i++) {
                    mma16816(d[i][j], ah[i], bw.x, bw.y);
                    mma16816(d[i][j], al[i], bw.x, bw.y);
                    mma16816(d[i][j], ah[i], bw.z, bw.w);
                }
            }
        }
    };

    stage(0, 0);
    cp_commit();
    for (int kc = 0; kc < KC; kc++) {
        int buf = kc & 1;
        cp_wait0();
        __syncthreads();
        if (kc + 1 < KC) stage(buf ^ 1, kc + 1);
        cp_commit();
        compute(buf);
    }

    if (mode == 0) {
#pragma unroll
        for (int i = 0; i < 2; i++) {
            int y = y0 + 2 * wid + i;
            for (int j = 0; j < nf; j++) {
                int oc = oc0 + 8 * j + 2 * tg;
                float b0 = bias[oc], b1 = bias[oc + 1];
                size_t base0 = (((size_t)b * OC + oc) * H + y) * W + x0;
                size_t base1 = base0 + (size_t)H * W;
                fout[base0 + g]     = activate(d[i][j][0] + b0, act);
                fout[base1 + g]     = activate(d[i][j][1] + b1, act);
                fout[base0 + g + 8] = activate(d[i][j][2] + b0, act);
                fout[base1 + g + 8] = activate(d[i][j][3] + b1, act);
            }
        }
    } else {
        // fragment-order uint4 stores: lane (g,tg) owns words 4tg..4tg+3 of
        // each 16-chunk for pixels x0+g and x0+g+8.
        unsigned* bo = bout + (size_t)b * H * W * OC;
        const int nchunk = nf >> 1;
#pragma unroll
        for (int i = 0; i < 2; i++) {
            int y = y0 + 2 * wid + i;
            for (int cc = 0; cc < nchunk; cc++) {
                int j0 = 2 * cc, j1 = 2 * cc + 1;
                int oca = oc0 + 16 * cc + 2 * tg;
                float ba0 = bias[oca], ba1 = bias[oca + 1];
                float bb0 = bias[oca + 8], bb1 = bias[oca + 9];
                size_t wbase = (size_t)oc0 + 16 * cc + 4 * tg;
#pragma unroll
                for (int half = 0; half < 2; half++) {
                    int r0 = 2 * half;
                    float va0 = activate(d[i][j0][r0] + ba0, act);
                    float va1 = activate(d[i][j0][r0 + 1] + ba1, act);
                    float vb0 = activate(d[i][j1][r0] + bb0, act);
                    float vb1 = activate(d[i][j1][r0 + 1] + bb1, act);
                    uint4 u;
                    pack_pair(va0, va1, u.x, u.z);
                    pack_pair(vb0, vb1, u.y, u.w);
                    size_t px = (size_t)y * W + x0 + g + 8 * half;
                    *(uint4*)(bo + px * OC + wbase) = u;
                }
            }
        }
    }
}

// =====================================================================
// tensor-core stride-2 conv as 2x2 s2c over CC=4C channels.
// in: fragment-native planes at 2Hout x 2Wout (phase gather in staging).
// out mode 0: fp32 NCHW (+act). mode 1: planes.
// =====================================================================
#define SINW2 (289 * 16)
#define MMA_SW2 (4 * 4 * 32)
#define MMA_SMEM2 (2 * SINW2 * 4 + 2 * MMA_SW2 * 16)

__global__ void __launch_bounds__(256, 2) conv_mma_s2c(
    const unsigned* __restrict__ in, const uint4* __restrict__ wp,
    const float* __restrict__ bias, float* __restrict__ fout,
    unsigned* __restrict__ bout, int C, int OC, int Hout, int Wout,
    int act, int mode)
{
    const int CC = 4 * C;
    const int KC = CC >> 4;
    const int Hin = Hout * 2, Win = Wout * 2;
    const int tilesX = Wout >> 4;
    const int x0 = (blockIdx.x % tilesX) << 4;
    const int y0 = (blockIdx.x / tilesX) << 4;
    const int oc0 = blockIdx.y << 5;
    const int b = blockIdx.z;
    const int OCg = OC >> 3;
    int nf = OCg - (oc0 >> 3); if (nf > 4) nf = 4;

    extern __shared__ __align__(16) unsigned char dsm[];
    unsigned* s_in = (unsigned*)dsm;
    uint4* s_w = (uint4*)(dsm + 2 * SINW2 * 4);

    const unsigned* inb = in + (size_t)b * Hin * Win * C;
    const int tid = threadIdx.x, lane = tid & 31, wid = tid >> 5;
    const int g = lane >> 2, tg = lane & 3;

    float d[2][4][4];
#pragma unroll
    for (int i = 0; i < 2; i++)
#pragma unroll
        for (int j = 0; j < 4; j++)
#pragma unroll
            for (int r = 0; r < 4; r++) d[i][j][r] = 0.f;

    auto stage = [&](int buf, int kc) {
        unsigned* si = s_in + buf * SINW2;
        int qph = (kc << 4) / C;
        int c0 = (kc << 4) - qph * C;
        int pa = qph >> 1, pb = qph & 1;
        for (int i = tid; i < 289 * 4; i += 256) {
            int sp = i >> 2, q = i & 3;
            int r = sp / 17, c = sp - r * 17;
            int sy = 2 * (y0 + r) + pa, sx = 2 * (x0 + c) + pb;
            bool p = sy < Hin && sx < Win;
            cp_async16(si + sp * 16 + q * 4,
                       inb + ((size_t)sy * Win + sx) * C + c0 + (q << 2), p);
        }
        uint4* sw = s_w + buf * MMA_SW2;
        const uint4* wsrc = wp + (size_t)kc * 4 * OCg * 32;
        int tot = 4 * nf * 32;
        for (int i = tid; i < tot; i += 256) {
            int l = i & 31;
            int q = i >> 5;
            int ogl = q % nf;
            int t = q / nf;
            cp_async16(sw + (t * 4 + ogl) * 32 + l,
                       wsrc + ((size_t)t * OCg + (oc0 >> 3) + ogl) * 32 + l, true);
        }
    };

    auto compute = [&](int buf) {
        unsigned* si = s_in + buf * SINW2;
        uint4* sw = s_w + buf * MMA_SW2;
#pragma unroll
        for (int t = 0; t < 4; t++) {
            const int dy = t >> 1, dx = t & 1;
            unsigned ah[2][4], al[2][4];
#pragma unroll
            for (int i = 0; i < 2; i++) {
                int sp0 = (2 * wid + i + dy) * 17 + g + dx;
                uint4 va = *(const uint4*)(si + sp0 * 16 + 4 * tg);
                uint4 vb = *(const uint4*)(si + (sp0 + 8) * 16 + 4 * tg);
                ah[i][0] = va.x; ah[i][2] = va.y; al[i][0] = va.z; al[i][2] = va.w;
                ah[i][1] = vb.x; ah[i][3] = vb.y; al[i][1] = vb.z; al[i][3] = vb.w;
            }
            for (int j = 0; j < nf; j++) {
                uint4 bw = sw[(t * 4 + j) * 32 + lane];
#pragma unroll
                for (int i = 0; i < 2; i++) {
                    mma16816(d[i][j], ah[i], bw.x, bw.y);
                    mma16816(d[i][j], al[i], bw.x, bw.y);
                    mma16816(d[i][j], ah[i], bw.z, bw.w);
                }
            }
        }
    };

    stage(0, 0);
    cp_commit();
    for (int kc = 0; kc < KC; kc++) {
        int buf = kc & 1;
        cp_wait0();
        __syncthreads();
        if (kc + 1 < KC) stage(buf ^ 1, kc + 1);
        cp_commit();
        compute(buf);
    }

    if (mode == 0) {
#pragma unroll
        for (int i = 0; i < 2; i++) {
            int y = y0 + 2 * wid + i;
            for (int j = 0; j < nf; j++) {
                int oc = oc0 + 8 * j + 2 * tg;
                float b0 = bias[oc], b1 = bias[oc + 1];
                size_t base0 = (((size_t)b * OC + oc) * Hout + y) * Wout + x0;
                size_t base1 = base0 + (size_t)Hout * Wout;
                fout[base0 + g]     = activate(d[i][j][0] + b0, act);
                fout[base1 + g]     = activate(d[i][j][1] + b1, act);
                fout[base0 + g + 8] = activate(d[i][j][2] + b0, act);
                fout[base1 + g + 8] = activate(d[i][j][3] + b1, act);
            }
        }
    } else {
        unsigned* bo = bout + (size_t)b * Hout * Wout * OC;
        const int nchunk = nf >> 1;
#pragma unroll
        for (int i = 0; i < 2; i++) {
            int y = y0 + 2 * wid + i;
            for (int cc = 0; cc < nchunk; cc++) {
                int j0 = 2 * cc, j1 = 2 * cc + 1;
                int oca = oc0 + 16 * cc + 2 * tg;
                float ba0 = bias[oca], ba1 = bias[oca + 1];
                float bb0 = bias[oca + 8], bb1 = bias[oca + 9];
                size_t wbase = (size_t)oc0 + 16 * cc + 4 * tg;
#pragma unroll
                for (int half = 0; half < 2; half++) {
                    int r0 = 2 * half;
                    float va0 = activate(d[i][j0][r0] + ba0, act);
                    float va1 = activate(d[i][j0][r0 + 1] + ba1, act);
                    float vb0 = activate(d[i][j1][r0] + bb0, act);
                    float vb1 = activate(d[i][j1][r0 + 1] + bb1, act);
                    uint4 u;
                    pack_pair(va0, va1, u.x, u.z);
                    pack_pair(vb0, vb1, u.y, u.w);
                    size_t px = (size_t)y * Wout + x0 + g + 8 * half;
                    *(uint4*)(bo + px * OC + wbase) = u;
                }
            }
        }
    }
}

// =====================================================================
// e0: fp32 NCHW in (C=3) -> fragment-native planes.
// thread (g) owns channels {16cc + 8p + 2g + e} -> one uint4 per chunk.
// =====================================================================
__global__ void __launch_bounds__(256, 2) conv_e0(
    const float* __restrict__ in, const float* __restrict__ wgt,
    const float* __restrict__ bias, unsigned* __restrict__ bout,
    int C, int OC, int H, int W, int act)
{
    constexpr int NT = 256;
    constexpr int ICB = 4;
    constexpr int SROW = 34;
    constexpr int SIN = 18 * SROW;

    const int tilesX = W >> 5;
    const int x0 = (blockIdx.x % tilesX) << 5;
    const int y0 = (blockIdx.x / tilesX) << 4;
    const int oc0 = blockIdx.y * 32;
    const int b = blockIdx.z;

    __shared__ __align__(16) float s_in[2][ICB][SIN];
    __shared__ __align__(16) float s_w[2][ICB][32 * 12];

    const int tid = threadIdx.x;
    const int g = tid >> 6;
    const int sp = tid & 63;
    const int ty = sp >> 3, tx = sp & 7;

    // remapped channel ownership: o = cc*4 + p*2 + e -> ocl = 16cc + 8p + 2g + e
    int ocl[8];
#pragma unroll
    for (int o = 0; o < 8; o++)
        ocl[o] = 16 * (o >> 2) + 8 * ((o >> 1) & 1) + 2 * g + (o & 1);

    float acc[8][2][4];
#pragma unroll
    for (int o = 0; o < 8; o++)
#pragma unroll
        for (int dy = 0; dy < 2; dy++)
#pragma unroll
            for (int dx = 0; dx < 4; dx++) acc[o][dy][dx] = 0.f;

    const float* inb = in + (size_t)b * C * H * W;
    const float* wb = wgt + (size_t)oc0 * C * 9;

    auto stage_copy = [&](int buf, int ic0, int cnt) {
        const float* ins = inb + (size_t)ic0 * H * W;
        for (int i = tid; i < cnt * SIN; i += NT) {
            int ch = i / SIN, r2 = i - ch * SIN;
            int r = r2 / SROW, c2 = r2 - r * SROW;
            int iy = y0 - 1 + r, ix = x0 - 1 + c2;
            bool p = (unsigned)iy < (unsigned)H && (unsigned)ix < (unsigned)W;
            cp_async4(&s_in[buf][ch][r2], ins + (size_t)ch * H * W + (size_t)iy * W + ix, p);
        }
        for (int i = tid; i < cnt * 32 * 9; i += NT) {
            int ch = i / (32 * 9), r2 = i - ch * (32 * 9);
            int o = r2 / 9, j2 = r2 - o * 9;
            cp_async4(&s_w[buf][ch][o * 12 + j2],
                      wb + ((size_t)o * C + ic0 + ch) * 9 + j2, true);
        }
    };

    const int sbase = (2 * ty) * SROW + 4 * tx;

    auto compute_ch = [&](int buf, int ch) {
        float rr[4][6];
        const float* si = &s_in[buf][ch][sbase];
#pragma unroll
        for (int r = 0; r < 4; r++) {
            const float2* p = (const float2*)(si + r * SROW);
            float2 a = p[0], b2 = p[1], c2 = p[2];
            rr[r][0] = a.x; rr[r][1] = a.y; rr[r][2] = b2.x;
            rr[r][3] = b2.y; rr[r][4] = c2.x; rr[r][5] = c2.y;
        }
#pragma unroll
        for (int o = 0; o < 8; o++) {
            const float4* wp = (const float4*)&s_w[buf][ch][ocl[o] * 12];
            float4 wa = wp[0];
            float4 wc = wp[1];
            float w8 = ((const float*)wp)[8];
#pragma unroll
            for (int dy = 0; dy < 2; dy++)
#pragma unroll
                for (int dx = 0; dx < 4; dx++) {
                    float s = acc[o][dy][dx];
                    s += wa.x * rr[dy + 0][dx + 0];
                    s += wa.y * rr[dy + 0][dx + 1];
                    s += wa.z * rr[dy + 0][dx + 2];
                    s += wa.w * rr[dy + 1][dx + 0];
                    s += wc.x * rr[dy + 1][dx + 1];
                    s += wc.y * rr[dy + 1][dx + 2];
                    s += wc.z * rr[dy + 2][dx + 0];
                    s += wc.w * rr[dy + 2][dx + 1];
                    s += w8   * rr[dy + 2][dx + 2];
                    acc[o][dy][dx] = s;
                }
        }
    };

    const int nst = (C + ICB - 1) / ICB;
    stage_copy(0, 0, C < ICB ? C : ICB);
    cp_commit();
    for (int s = 0; s < nst; s++) {
        int buf = s & 1;
        cp_wait0();
        __syncthreads();
        int icn = (s + 1) * ICB;
        if (icn < C) {
            int cn = C - icn; if (cn > ICB) cn = ICB;
            stage_copy(buf ^ 1, icn, cn);
        }
        cp_commit();
        int cnt = C - s * ICB; if (cnt > ICB) cnt = ICB;
        for (int j = 0; j < cnt; j++) compute_ch(buf, j);
    }

    float bv[8];
#pragma unroll
    for (int o = 0; o < 8; o++) bv[o] = bias[oc0 + ocl[o]];
    unsigned* bo = bout + (size_t)b * H * W * OC;
#pragma unroll
    for (int dy = 0; dy < 2; dy++)
#pragma unroll
        for (int dx = 0; dx < 4; dx++) {
            int y = y0 + 2 * ty + dy, x = x0 + 4 * tx + dx;
            float v[8];
#pragma unroll
            for (int o = 0; o < 8; o++) v[o] = activate(acc[o][dy][dx] + bv[o], act);
            unsigned* bb = bo + ((size_t)y * W + x) * OC + oc0;
#pragma unroll
            for (int cc = 0; cc < 2; cc++) {
                uint4 u;
                pack_pair(v[cc * 4 + 0], v[cc * 4 + 1], u.x, u.z);
                pack_pair(v[cc * 4 + 2], v[cc * 4 + 3], u.y, u.w);
                *(uint4*)(bb + 16 * cc + 4 * g) = u;
            }
        }
}

// =====================================================================
// transposed conv 3x3 stride-2 SAME (pad_a=2). fp32 NCHW in -> planes. relu.
// thread (g) owns channels {8p + 2g + e} of chunk oc0 -> one uint4.
// =====================================================================
__global__ void __launch_bounds__(256, 3) tconv_s2(
    const float* __restrict__ in, const float* __restrict__ wgt,
    const float* __restrict__ bias, unsigned* __restrict__ bout,
    int C, int OC, int Hout, int Wout)
{
    constexpr int NT = 256;
    constexpr int ICB = 4;
    constexpr int SIN = 9 * 9;

    const int Hin = Hout >> 1, Win = Wout >> 1;
    const int tilesX = Wout >> 4;
    const int x0 = (blockIdx.x % tilesX) << 4;
    const int y0 = (blockIdx.x / tilesX) << 4;
    const int oc0 = blockIdx.y * 16;
    const int b = blockIdx.z;
    const int Y0 = y0 >> 1, X0 = x0 >> 1;

    __shared__ __align__(16) float s_in[2][ICB][SIN + 3];
    __shared__ __align__(16) float s_w[2][ICB][16 * 12];

    const int tid = threadIdx.x;
    const int g = tid >> 6;
    const int sp = tid & 63;
    const int ty = sp >> 3, tx = sp & 7;

    int ocl[4];
#pragma unroll
    for (int o = 0; o < 4; o++)
        ocl[o] = 8 * ((o >> 1) & 1) + 2 * g + (o & 1);

    float acc[4][4];
#pragma unroll
    for (int o = 0; o < 4; o++)
#pragma unroll
        for (int p = 0; p < 4; p++) acc[o][p] = 0.f;

    const float* inb = in + (size_t)b * C * Hin * Win;
    const float* wb = wgt + (size_t)oc0 * C * 9;

    auto stage_copy = [&](int buf, int ic0, int cnt) {
        const float* ins = inb + (size_t)ic0 * Hin * Win;
        for (int i = tid; i < cnt * SIN; i += NT) {
            int ch = i / SIN, r2 = i - ch * SIN;
            int r = r2 / 9, c2 = r2 - r * 9;
            int iy = Y0 - 1 + r, ix = X0 - 1 + c2;
            bool p = (unsigned)iy < (unsigned)Hin && (unsigned)ix < (unsigned)Win;
            cp_async4(&s_in[buf][ch][r2], ins + (size_t)ch * Hin * Win + (size_t)iy * Win + ix, p);
        }
        for (int i = tid; i < cnt * 16 * 9; i += NT) {
            int ch = i / (16 * 9), r2 = i - ch * (16 * 9);
            int o = r2 / 9, j2 = r2 - o * 9;
            cp_async4(&s_w[buf][ch][o * 12 + j2],
                      wb + ((size_t)o * C + ic0 + ch) * 9 + j2, true);
        }
    };

    auto compute_ch = [&](int buf, int ch) {
        const float* si = s_in[buf][ch];
        float r00 = si[ty * 9 + tx];
        float r01 = si[ty * 9 + tx + 1];
        float r10 = si[(ty + 1) * 9 + tx];
        float r11 = si[(ty + 1) * 9 + tx + 1];
#pragma unroll
        for (int o = 0; o < 4; o++) {
            const float4* wp = (const float4*)&s_w[buf][ch][ocl[o] * 12];
            float4 wa = wp[0];
            float4 wc = wp[1];
            float w8 = ((const float*)wp)[8];
            acc[o][0] += wa.x * r00 + wa.z * r01 + wc.z * r10 + w8 * r11;
            acc[o][1] += wa.y * r01 + wc.w * r11;
            acc[o][2] += wa.w * r10 + wc.y * r11;
            acc[o][3] += wc.x * r11;
        }
    };

    const int nst = (C + ICB - 1) / ICB;
    stage_copy(0, 0, C < ICB ? C : ICB);
    cp_commit();
    for (int s = 0; s < nst; s++) {
        int buf = s & 1;
        cp_wait0();
        __syncthreads();
        int icn = (s + 1) * ICB;
        if (icn < C) {
            int cn = C - icn; if (cn > ICB) cn = ICB;
            stage_copy(buf ^ 1, icn, cn);
        }
        cp_commit();
        int cnt = C - s * ICB; if (cnt > ICB) cnt = ICB;
        if (cnt == ICB) {
#pragma unroll
            for (int j = 0; j < ICB; j++) compute_ch(buf, j);
        } else {
            for (int j = 0; j < cnt; j++) compute_ch(buf, j);
        }
    }

    float bv[4];
#pragma unroll
    for (int o = 0; o < 4; o++) bv[o] = bias[oc0 + ocl[o]];
    unsigned* bo = bout + (size_t)b * Hout * Wout * OC;
#pragma unroll
    for (int dy = 0; dy < 2; dy++)
#pragma unroll
        for (int dx = 0; dx < 2; dx++) {
            int y = y0 + 2 * ty + dy, x = x0 + 2 * tx + dx;
            float v[4];
#pragma unroll
            for (int o = 0; o < 4; o++) {
                float t = acc[o][dy * 2 + dx] + bv[o];
                v[o] = t > 0.f ? t : 0.f;
            }
            uint4 u;
            pack_pair(v[0], v[1], u.x, u.z);
            pack_pair(v[2], v[3], u.y, u.w);
            *(uint4*)(bo + ((size_t)y * Wout + x) * OC + oc0 + 4 * g) = u;
        }
}

// ---------------- keypoint bottleneck (fp32 NCHW) ----------------
__global__ void bn_stats(const float* __restrict__ R, float* __restrict__ S,
                         float* __restrict__ Sh, float* __restrict__ Sw)
{
    int bk = blockIdx.x;
    int t = threadIdx.x;
    float v = R[(size_t)bk * 256 + t];
    float a = v;
    float bsum = v * (float)(t >> 4);
    float c = v * (float)(t & 15);
#pragma unroll
    for (int off = 16; off > 0; off >>= 1) {
        a += __shfl_down_sync(0xffffffffu, a, off);
        bsum += __shfl_down_sync(0xffffffffu, bsum, off);
        c += __shfl_down_sync(0xffffffffu, c, off);
    }
    __shared__ float sa[8], sb[8], sc[8];
    int wid = t >> 5;
    if ((t & 31) == 0) { sa[wid] = a; sb[wid] = bsum; sc[wid] = c; }
    __syncthreads();
    if (t == 0) {
        float ta = 0.f, tb = 0.f, tc = 0.f;
        for (int i = 0; i < 8; i++) { ta += sa[i]; tb += sb[i]; tc += sc[i]; }
        S[bk] = ta; Sh[bk] = tb; Sw[bk] = tc;
    }
}

__global__ void bn_maps(const float* __restrict__ S, const float* __restrict__ Sh,
                        const float* __restrict__ Sw, float* __restrict__ maps)
{
    int bk = blockIdx.x;
    int b = bk >> 7;
    float s = S[bk];
    float denom = S[(b << 7) | 127];
    float mu = s * (1.f / 256.f);
    float inv = 1.f / denom;
    float c0 = Sh[bk] * inv;
    float c1 = Sw[bk] * inv;
    int t = threadIdx.x;
    float h = (float)(t >> 4), w = (float)(t & 15);
    float dh = h - c0, dw = w - c1;
    maps[(size_t)bk * 256 + t] = mu * expf(-0.5f * (dh * dh + dw * dw));
}

// ---------------- launch ----------------
extern "C" void kernel_launch(void* const* d_in, const int* in_sizes, int n_in,
                              void* d_out, int out_size)
{
    (void)in_sizes; (void)n_in; (void)out_size;
    const float* x = (const float*)d_in[0];
    const float* ew[7]; const float* eb[7];
    for (int j = 0; j < 7; j++) {
        ew[j] = (const float*)d_in[1 + 2 * j];
        eb[j] = (const float*)d_in[2 + 2 * j];
    }
    const float* dw[6]; const float* db[6];
    for (int j = 0; j < 6; j++) {
        dw[j] = (const float*)d_in[15 + 2 * j];
        db[j] = (const float*)d_in[16 + 2 * j];
    }
    float* out = (float*)d_out;

    float *F0, *F1, *S, *Sh, *Sw;
    unsigned *B0, *B1;
    uint4 *wprep, *wprep2;
    cudaGetSymbolAddress((void**)&F0, g_f0);
    cudaGetSymbolAddress((void**)&F1, g_f1);
    cudaGetSymbolAddress((void**)&B0, g_b0);
    cudaGetSymbolAddress((void**)&B1, g_b1);
    cudaGetSymbolAddress((void**)&wprep, g_wprep);
    cudaGetSymbolAddress((void**)&wprep2, g_wprep2);
    cudaGetSymbolAddress((void**)&S, g_S);
    cudaGetSymbolAddress((void**)&Sh, g_Sh);
    cudaGetSymbolAddress((void**)&Sw, g_Sw);

    static bool attr_set = false;
    if (!attr_set) {
        cudaFuncSetAttribute(conv_mma_s1, cudaFuncAttributeMaxDynamicSharedMemorySize, MMA_SMEM);
        cudaFuncSetAttribute(conv_mma_s2c, cudaFuncAttributeMaxDynamicSharedMemorySize, MMA_SMEM2);
        attr_set = true;
    }

    const int B = 32;
    const int OFF_E1 = 0, OFF_E3 = 2304, OFF_E5 = 11520;
    const int OFF_D1 = 48384, OFF_D3 = 57600, OFF_D5 = 59904;
    const int OFF2_E2 = 0, OFF2_E4 = 8192, OFF2_E6 = 40960;

    // 1: s1 enc weight prep
    prep_many<<<dim3(144, 3, 1), 256>>>(ew[1], ew[3], ew[5], wprep,
                                        OFF_E1, OFF_E3, OFF_E5, 32, 32, 64, 64, 128, 128);
    // 2: s1 dec weight prep
    prep_many<<<dim3(36, 3, 1), 256>>>(dw[1], dw[3], dw[5], wprep,
                                       OFF_D1, OFF_D3, OFF_D5, 64, 64, 32, 32, 16, 16);
    // 3: s2c weight prep (e2, e4, e6)
    prep_s2c<<<dim3(256, 3, 1), 256>>>(ew[2], ew[4], ew[6], wprep2,
                                       OFF2_E2, OFF2_E4, OFF2_E6,
                                       32, 64, 64, 128, 128, 128);
    // 4: e0 -> B0
    conv_e0<<<dim3(32, 1, B), 256>>>(x, ew[0], eb[0], B0, 3, 32, 128, 128, 0);
    // 5: e1 s1: B0 -> B1
    conv_mma_s1<<<dim3(64, 1, B), 256, MMA_SMEM>>>(B0, wprep + OFF_E1, eb[1],
                                                   nullptr, B1, 32, 32, 128, 128, 0, 1);
    // 6: e2 s2c: B1 -> B0   <-- profiled
    conv_mma_s2c<<<dim3(16, 2, B), 256, MMA_SMEM2>>>(B1, wprep2 + OFF2_E2, eb[2],
                                                     nullptr, B0, 32, 64, 64, 64, 1, 1);
    // e3 s1: B0 -> B1
    conv_mma_s1<<<dim3(16, 2, B), 256, MMA_SMEM>>>(B0, wprep + OFF_E3, eb[3],
                                                   nullptr, B1, 64, 64, 64, 64, 1, 1);
    // e4 s2c: B1 -> B0
    conv_mma_s2c<<<dim3(4, 4, B), 256, MMA_SMEM2>>>(B1, wprep2 + OFF2_E4, eb[4],
                                                    nullptr, B0, 64, 128, 32, 32, 1, 1);
    // e5 s1: B0 -> B1
    conv_mma_s1<<<dim3(4, 4, B), 256, MMA_SMEM>>>(B0, wprep + OFF_E5, eb[5],
                                                  nullptr, B1, 128, 128, 32, 32, 1, 1);
    // e6 s2c: B1 -> F1 (fp32 NCHW, softplus)
    conv_mma_s2c<<<dim3(1, 4, B), 256, MMA_SMEM2>>>(B1, wprep2 + OFF2_E6, eb[6],
                                                    F1, nullptr, 128, 128, 16, 16, 3, 0);
    // ---- keypoint bottleneck ----
    bn_stats<<<4096, 256>>>(F1, S, Sh, Sw);
    bn_maps<<<4096, 256>>>(S, Sh, Sw, F0);
    // ---- decoder ----
    tconv_s2<<<dim3(4, 4, B), 256>>>(F0, dw[0], db[0], B0, 128, 64, 32, 32);
    conv_mma_s1<<<dim3(4, 2, B), 256, MMA_SMEM>>>(B0, wprep + OFF_D1, db[1],
                                                  F0, nullptr, 64, 64, 32, 32, 2, 0);
    tconv_s2<<<dim3(16, 2, B), 256>>>(F0, dw[2], db[2], B0, 64, 32, 64, 64);
    conv_mma_s1<<<dim3(16, 1, B), 256, MMA_SMEM>>>(B0, wprep + OFF_D3, db[3],
                                                   F0, nullptr, 32, 32, 64, 64, 2, 0);
    tconv_s2<<<dim3(64, 1, B), 256>>>(F0, dw[4], db[4], B0, 32, 16, 128, 128);
    conv_mma_s1<<<dim3(64, 1, B), 256, MMA_SMEM>>>(B0, wprep + OFF_D5, db[5],
                                                   out, nullptr, 16, 16, 128, 128, 2, 0);
}

// round 11
// speedup vs baseline: 1.6781x; 1.6781x over previous
#include <cuda_runtime.h>
#include <cuda_bf16.h>
#include <math.h>

// ---------------- scratch ----------------
__device__ float g_f0[32u * 32 * 128 * 128];              // fp32 NCHW ping
__device__ float g_f1[32u * 32 * 128 * 128];              // fp32 NCHW pong
__device__ unsigned short g_b0[33554432];                 // bf16 std planes ping
__device__ unsigned short g_b1[33554432];                 // bf16 std planes pong
__device__ uint4 g_wprep[60480];                          // s1 mma weights
__device__ uint4 g_wprep2[106496];                        // s2c mma weights
__device__ float g_S[4096];
__device__ float g_Sh[4096];
__device__ float g_Sw[4096];

__device__ __forceinline__ float activate(float v, int act) {
    switch (act) {
        case 1: return v > 0.f ? v : 0.2f * v;
        case 2: return v > 0.f ? v : 0.f;
        case 3: return fmaxf(v, 0.f) + log1pf(expf(-fabsf(v)));
        default: return v;
    }
}

__device__ __forceinline__ void split_bf16(float x, unsigned short& h, unsigned short& l) {
    h = __bfloat16_as_ushort(__float2bfloat16(x));
    float hf = __uint_as_float((unsigned)h << 16);
    l = __bfloat16_as_ushort(__float2bfloat16(x - hf));
}
__device__ __forceinline__ unsigned pack_us(unsigned short a, unsigned short b) {
    return ((unsigned)b << 16) | (unsigned)a;
}
__device__ __forceinline__ unsigned pack2_bf16(float e_lo, float e_hi) {
    return ((unsigned)__bfloat16_as_ushort(__float2bfloat16(e_hi)) << 16)
         | (unsigned)__bfloat16_as_ushort(__float2bfloat16(e_lo));
}

__device__ __forceinline__ void cp_async4(void* sdst, const void* gsrc, bool pred) {
    unsigned saddr = (unsigned)__cvta_generic_to_shared(sdst);
    int sz = pred ? 4 : 0;
    asm volatile("cp.async.ca.shared.global [%0], [%1], 4, %2;\n"
                 :: "r"(saddr), "l"(gsrc), "r"(sz));
}
__device__ __forceinline__ void cp_async16(void* sdst, const void* gsrc, bool pred) {
    unsigned saddr = (unsigned)__cvta_generic_to_shared(sdst);
    int sz = pred ? 16 : 0;
    asm volatile("cp.async.cg.shared.global [%0], [%1], 16, %2;\n"
                 :: "r"(saddr), "l"(gsrc), "r"(sz));
}
__device__ __forceinline__ void cp_commit() { asm volatile("cp.async.commit_group;\n"); }
__device__ __forceinline__ void cp_wait0() { asm volatile("cp.async.wait_group 0;\n"); }

__device__ __forceinline__ void mma16816(float* d, const unsigned* a, unsigned b0, unsigned b1) {
    asm volatile("mma.sync.aligned.m16n8k16.row.col.f32.bf16.bf16.f32 "
                 "{%0,%1,%2,%3},{%4,%5,%6,%7},{%8,%9},{%0,%1,%2,%3};"
                 : "+f"(d[0]), "+f"(d[1]), "+f"(d[2]), "+f"(d[3])
                 : "r"(a[0]), "r"(a[1]), "r"(a[2]), "r"(a[3]), "r"(b0), "r"(b1));
}

// =====================================================================
// s1 weight prep (3 layers/launch)
// =====================================================================
__global__ void prep_many(const float* __restrict__ w0, const float* __restrict__ w1,
                          const float* __restrict__ w2, uint4* __restrict__ dstb,
                          int off0, int off1, int off2,
                          int C0, int OC0, int C1, int OC1, int C2, int OC2)
{
    int layer = blockIdx.y;
    const float* w = layer == 0 ? w0 : layer == 1 ? w1 : w2;
    uint4* dst = dstb + (layer == 0 ? off0 : layer == 1 ? off1 : off2);
    int C = layer == 0 ? C0 : layer == 1 ? C1 : C2;
    int OC = layer == 0 ? OC0 : layer == 1 ? OC1 : OC2;
    int OCg = OC >> 3;
    int total = (C >> 4) * 9 * OCg * 32;
    int idx = blockIdx.x * 256 + threadIdx.x;
    if (idx >= total) return;
    int l = idx & 31;
    int q = idx >> 5;
    int og = q % OCg; q /= OCg;
    int t = q % 9;
    int kc = q / 9;
    int tg = l & 3, gg = l >> 2;
    int n = og * 8 + gg;
    float h[4], lo[4];
#pragma unroll
    for (int kk = 0; kk < 4; kk++) {
        int k = (kk < 2) ? (2 * tg + kk) : (2 * tg + 8 + (kk - 2));
        int ic = (kc << 4) + k;
        float e = w[((size_t)n * C + ic) * 9 + t];
        unsigned hb = (unsigned)__bfloat16_as_ushort(__float2bfloat16(e)) << 16;
        h[kk] = __uint_as_float(hb);
        lo[kk] = e - h[kk];
    }
    uint4 r;
    r.x = pack2_bf16(h[0], h[1]);
    r.y = pack2_bf16(h[2], h[3]);
    r.z = pack2_bf16(lo[0], lo[1]);
    r.w = pack2_bf16(lo[2], lo[3]);
    dst[idx] = r;
}

// =====================================================================
// s2c weight prep: stride-2 3x3 -> 2x2 over 4C phase channels (q*C+c).
// =====================================================================
__global__ void prep_s2c(const float* __restrict__ w0, const float* __restrict__ w1,
                         const float* __restrict__ w2, uint4* __restrict__ dstb,
                         int off0, int off1, int off2,
                         int C0, int OC0, int C1, int OC1, int C2, int OC2)
{
    int layer = blockIdx.y;
    const float* w = layer == 0 ? w0 : layer == 1 ? w1 : w2;
    uint4* dst = dstb + (layer == 0 ? off0 : layer == 1 ? off1 : off2);
    int C = layer == 0 ? C0 : layer == 1 ? C1 : C2;
    int OC = layer == 0 ? OC0 : layer == 1 ? OC1 : OC2;
    int OCg = OC >> 3;
    int KC = (4 * C) >> 4;
    int total = KC * 4 * OCg * 32;
    int idx = blockIdx.x * 256 + threadIdx.x;
    if (idx >= total) return;
    int l = idx & 31;
    int q = idx >> 5;
    int og = q % OCg; q /= OCg;
    int t = q % 4;
    int kc = q / 4;
    int dy = t >> 1, dx = t & 1;
    int tg = l & 3, gg = l >> 2;
    int n = og * 8 + gg;
    float h[4], lo[4];
#pragma unroll
    for (int kk = 0; kk < 4; kk++) {
        int k = (kk < 2) ? (2 * tg + kk) : (2 * tg + 8 + (kk - 2));
        int ch = (kc << 4) + k;
        int qph = ch / C, c = ch - qph * C;
        int a = qph >> 1, bph = qph & 1;
        int ky = 2 * dy + a, kx = 2 * dx + bph;
        float e = (ky < 3 && kx < 3) ? w[((size_t)n * C + c) * 9 + ky * 3 + kx] : 0.f;
        unsigned hb = (unsigned)__bfloat16_as_ushort(__float2bfloat16(e)) << 16;
        h[kk] = __uint_as_float(hb);
        lo[kk] = e - h[kk];
    }
    uint4 r;
    r.x = pack2_bf16(h[0], h[1]);
    r.y = pack2_bf16(h[2], h[3]);
    r.z = pack2_bf16(lo[0], lo[1]);
    r.w = pack2_bf16(lo[2], lo[3]);
    dst[idx] = r;
}

// =====================================================================
// tensor-core stride-1 3x3 SAME conv (bf16x3 split). Templated NF.
// in: std bf16 planes [px][2][C].
// out mode 0: fp32 NCHW; mode 1: std bf16 planes.
// =====================================================================
#define SINW (324 * 12)
#define MMA_SW (9 * 4 * 32)
#define MMA_SMEM (2 * 2 * SINW * 4 + 2 * MMA_SW * 16)

template <int NF>
__global__ void __launch_bounds__(256, 2) conv_mma_s1(
    const unsigned short* __restrict__ in, const uint4* __restrict__ wp,
    const float* __restrict__ bias, float* __restrict__ fout,
    unsigned short* __restrict__ bout, int C, int OC, int H, int W, int act, int mode)
{
    const int KC = C >> 4;
    const int tilesX = W >> 4;
    const int x0 = (blockIdx.x % tilesX) << 4;
    const int y0 = (blockIdx.x / tilesX) << 4;
    const int oc0 = blockIdx.y * (NF * 8);
    const int b = blockIdx.z;
    const int OCg = OC >> 3;

    extern __shared__ __align__(16) unsigned char dsm[];
    unsigned* s_hi = (unsigned*)dsm;
    unsigned* s_lo = s_hi + 2 * SINW;
    uint4* s_w = (uint4*)(dsm + 4 * 4 * SINW);

    const unsigned short* inb = in + (size_t)b * H * W * 2 * C;
    const int tid = threadIdx.x, lane = tid & 31, wid = tid >> 5;
    const int g = lane >> 2, tg = lane & 3;

    float d[2][NF][4];
#pragma unroll
    for (int i = 0; i < 2; i++)
#pragma unroll
        for (int j = 0; j < NF; j++)
#pragma unroll
            for (int r = 0; r < 4; r++) d[i][j][r] = 0.f;

    auto stage = [&](int buf, int kc) {
        unsigned* hi = s_hi + buf * SINW;
        unsigned* lo = s_lo + buf * SINW;
        for (int i = tid; i < 648; i += 256) {
            int sp = i >> 1, q = i & 1;
            int r = sp / 18, c = sp - r * 18;
            int iy = y0 - 1 + r, ix = x0 - 1 + c;
            bool p = (unsigned)iy < (unsigned)H && (unsigned)ix < (unsigned)W;
            const unsigned short* src = inb + ((size_t)iy * W + ix) * 2 * C + (kc << 4) + (q << 3);
            cp_async16(hi + sp * 12 + q * 4, src, p);
            cp_async16(lo + sp * 12 + q * 4, src + C, p);
        }
        uint4* sw = s_w + buf * MMA_SW;
        const uint4* wsrc = wp + (size_t)kc * 9 * OCg * 32;
        const int tot = 9 * NF * 32;
        for (int i = tid; i < tot; i += 256) {
            int l = i & 31;
            int q = i >> 5;
            int ogl = q % NF;
            int t = q / NF;
            cp_async16(sw + (t * 4 + ogl) * 32 + l,
                       wsrc + ((size_t)t * OCg + (oc0 >> 3) + ogl) * 32 + l, true);
        }
    };

    auto compute = [&](int buf) {
        unsigned* hi = s_hi + buf * SINW;
        unsigned* lo = s_lo + buf * SINW;
        uint4* sw = s_w + buf * MMA_SW;
#pragma unroll
        for (int t = 0; t < 9; t++) {
            const int dy = t / 3, dx = t - 3 * (t / 3);
            unsigned ah[2][4], al[2][4];
#pragma unroll
            for (int i = 0; i < 2; i++) {
                int sp0 = (2 * wid + i + dy) * 18 + g + dx;
                const unsigned* h0 = hi + sp0 * 12;
                const unsigned* l0 = lo + sp0 * 12;
                ah[i][0] = h0[tg];       ah[i][1] = h0[96 + tg];
                ah[i][2] = h0[tg + 4];   ah[i][3] = h0[96 + tg + 4];
                al[i][0] = l0[tg];       al[i][1] = l0[96 + tg];
                al[i][2] = l0[tg + 4];   al[i][3] = l0[96 + tg + 4];
            }
#pragma unroll
            for (int j = 0; j < NF; j++) {
                uint4 bw = sw[(t * 4 + j) * 32 + lane];
#pragma unroll
                for (int i = 0; i < 2; i++) {
                    mma16816(d[i][j], ah[i], bw.x, bw.y);
                    mma16816(d[i][j], al[i], bw.x, bw.y);
                    mma16816(d[i][j], ah[i], bw.z, bw.w);
                }
            }
        }
    };

    stage(0, 0);
    cp_commit();
    for (int kc = 0; kc < KC; kc++) {
        int buf = kc & 1;
        cp_wait0();
        __syncthreads();
        if (kc + 1 < KC) stage(buf ^ 1, kc + 1);
        cp_commit();
        compute(buf);
    }

    if (mode == 0) {
#pragma unroll
        for (int i = 0; i < 2; i++) {
            int y = y0 + 2 * wid + i;
#pragma unroll
            for (int j = 0; j < NF; j++) {
                int oc = oc0 + 8 * j + 2 * tg;
                float b0 = bias[oc], b1 = bias[oc + 1];
                size_t base0 = (((size_t)b * OC + oc) * H + y) * W + x0;
                size_t base1 = base0 + (size_t)H * W;
                fout[base0 + g]     = activate(d[i][j][0] + b0, act);
                fout[base1 + g]     = activate(d[i][j][1] + b1, act);
                fout[base0 + g + 8] = activate(d[i][j][2] + b0, act);
                fout[base1 + g + 8] = activate(d[i][j][3] + b1, act);
            }
        }
    } else {
        // std bf16 planes [px][2][OC], 4B-pair stores
        unsigned short* bo = bout + (size_t)b * H * W * 2 * OC;
#pragma unroll
        for (int i = 0; i < 2; i++) {
            int y = y0 + 2 * wid + i;
#pragma unroll
            for (int j = 0; j < NF; j++) {
                int oc = oc0 + 8 * j + 2 * tg;
                float b0 = bias[oc], b1 = bias[oc + 1];
                float v0 = activate(d[i][j][0] + b0, act);
                float v1 = activate(d[i][j][1] + b1, act);
                float v2 = activate(d[i][j][2] + b0, act);
                float v3 = activate(d[i][j][3] + b1, act);
                size_t px0 = (size_t)y * W + x0 + g;
                size_t px1 = px0 + 8;
                unsigned short h0, l0, h1, l1;
                split_bf16(v0, h0, l0); split_bf16(v1, h1, l1);
                size_t a0 = px0 * 2 * OC + oc;
                *(unsigned*)(bo + a0) = pack_us(h0, h1);
                *(unsigned*)(bo + a0 + OC) = pack_us(l0, l1);
                split_bf16(v2, h0, l0); split_bf16(v3, h1, l1);
                size_t a1 = px1 * 2 * OC + oc;
                *(unsigned*)(bo + a1) = pack_us(h0, h1);
                *(unsigned*)(bo + a1 + OC) = pack_us(l0, l1);
            }
        }
    }
}

// =====================================================================
// tensor-core stride-2 conv as 2x2 s2c over CC=4C channels. Templated NF.
// in: STD bf16 planes at Hin=2Hout x Win=2Wout (phase gather in staging).
// out mode 0: fp32 NCHW (+act). mode 1: std bf16 planes.
// =====================================================================
#define SINW2 (289 * 12)
#define MMA_SW2 (4 * 4 * 32)
#define MMA_SMEM2 (2 * 2 * SINW2 * 4 + 2 * MMA_SW2 * 16)

template <int NF>
__global__ void __launch_bounds__(256, 2) conv_mma_s2c(
    const unsigned short* __restrict__ in, const uint4* __restrict__ wp,
    const float* __restrict__ bias, float* __restrict__ fout,
    unsigned short* __restrict__ bout, int C, int OC, int Hout, int Wout,
    int act, int mode)
{
    const int CC = 4 * C;
    const int KC = CC >> 4;
    const int Hin = Hout * 2, Win = Wout * 2;
    const int tilesX = Wout >> 4;
    const int x0 = (blockIdx.x % tilesX) << 4;
    const int y0 = (blockIdx.x / tilesX) << 4;
    const int oc0 = blockIdx.y * (NF * 8);
    const int b = blockIdx.z;
    const int OCg = OC >> 3;

    extern __shared__ __align__(16) unsigned char dsm[];
    unsigned* s_hi = (unsigned*)dsm;
    unsigned* s_lo = s_hi + 2 * SINW2;
    uint4* s_w = (uint4*)(dsm + 4 * 4 * SINW2);

    const unsigned short* inb = in + (size_t)b * Hin * Win * 2 * C;
    const int tid = threadIdx.x, lane = tid & 31, wid = tid >> 5;
    const int g = lane >> 2, tg = lane & 3;

    float d[2][NF][4];
#pragma unroll
    for (int i = 0; i < 2; i++)
#pragma unroll
        for (int j = 0; j < NF; j++)
#pragma unroll
            for (int r = 0; r < 4; r++) d[i][j][r] = 0.f;

    auto stage = [&](int buf, int kc) {
        unsigned* hi = s_hi + buf * SINW2;
        unsigned* lo = s_lo + buf * SINW2;
        int qph = (kc << 4) / C;
        int c0 = (kc << 4) - qph * C;
        int pa = qph >> 1, pb = qph & 1;
        for (int i = tid; i < 578; i += 256) {
            int sp = i >> 1, q = i & 1;
            int r = sp / 17, c = sp - r * 17;
            int sy = 2 * (y0 + r) + pa, sx = 2 * (x0 + c) + pb;
            bool p = sy < Hin && sx < Win;
            const unsigned short* src = inb + ((size_t)sy * Win + sx) * 2 * C + c0 + (q << 3);
            cp_async16(hi + sp * 12 + q * 4, src, p);
            cp_async16(lo + sp * 12 + q * 4, src + C, p);
        }
        uint4* sw = s_w + buf * MMA_SW2;
        const uint4* wsrc = wp + (size_t)kc * 4 * OCg * 32;
        const int tot = 4 * NF * 32;
        for (int i = tid; i < tot; i += 256) {
            int l = i & 31;
            int q = i >> 5;
            int ogl = q % NF;
            int t = q / NF;
            cp_async16(sw + (t * 4 + ogl) * 32 + l,
                       wsrc + ((size_t)t * OCg + (oc0 >> 3) + ogl) * 32 + l, true);
        }
    };

    auto compute = [&](int buf) {
        unsigned* hi = s_hi + buf * SINW2;
        unsigned* lo = s_lo + buf * SINW2;
        uint4* sw = s_w + buf * MMA_SW2;
#pragma unroll
        for (int t = 0; t < 4; t++) {
            const int dy = t >> 1, dx = t & 1;
            unsigned ah[2][4], al[2][4];
#pragma unroll
            for (int i = 0; i < 2; i++) {
                int sp0 = (2 * wid + i + dy) * 17 + g + dx;
                const unsigned* h0 = hi + sp0 * 12;
                const unsigned* l0 = lo + sp0 * 12;
                ah[i][0] = h0[tg];       ah[i][1] = h0[96 + tg];
                ah[i][2] = h0[tg + 4];   ah[i][3] = h0[96 + tg + 4];
                al[i][0] = l0[tg];       al[i][1] = l0[96 + tg];
                al[i][2] = l0[tg + 4];   al[i][3] = l0[96 + tg + 4];
            }
#pragma unroll
            for (int j = 0; j < NF; j++) {
                uint4 bw = sw[(t * 4 + j) * 32 + lane];
#pragma unroll
                for (int i = 0; i < 2; i++) {
                    mma16816(d[i][j], ah[i], bw.x, bw.y);
                    mma16816(d[i][j], al[i], bw.x, bw.y);
                    mma16816(d[i][j], ah[i], bw.z, bw.w);
                }
            }
        }
    };

    stage(0, 0);
    cp_commit();
    for (int kc = 0; kc < KC; kc++) {
        int buf = kc & 1;
        cp_wait0();
        __syncthreads();
        if (kc + 1 < KC) stage(buf ^ 1, kc + 1);
        cp_commit();
        compute(buf);
    }

    if (mode == 0) {
#pragma unroll
        for (int i = 0; i < 2; i++) {
            int y = y0 + 2 * wid + i;
#pragma unroll
            for (int j = 0; j < NF; j++) {
                int oc = oc0 + 8 * j + 2 * tg;
                float b0 = bias[oc], b1 = bias[oc + 1];
                size_t base0 = (((size_t)b * OC + oc) * Hout + y) * Wout + x0;
                size_t base1 = base0 + (size_t)Hout * Wout;
                fout[base0 + g]     = activate(d[i][j][0] + b0, act);
                fout[base1 + g]     = activate(d[i][j][1] + b1, act);
                fout[base0 + g + 8] = activate(d[i][j][2] + b0, act);
                fout[base1 + g + 8] = activate(d[i][j][3] + b1, act);
            }
        }
    } else {
        unsigned short* bo = bout + (size_t)b * Hout * Wout * 2 * OC;
#pragma unroll
        for (int i = 0; i < 2; i++) {
            int y = y0 + 2 * wid + i;
#pragma unroll
            for (int j = 0; j < NF; j++) {
                int oc = oc0 + 8 * j + 2 * tg;
                float b0 = bias[oc], b1 = bias[oc + 1];
                float v0 = activate(d[i][j][0] + b0, act);
                float v1 = activate(d[i][j][1] + b1, act);
                float v2 = activate(d[i][j][2] + b0, act);
                float v3 = activate(d[i][j][3] + b1, act);
                size_t px0 = (size_t)y * Wout + x0 + g;
                size_t px1 = px0 + 8;
                unsigned short h0, l0, h1, l1;
                split_bf16(v0, h0, l0); split_bf16(v1, h1, l1);
                size_t a0 = px0 * 2 * OC + oc;
                *(unsigned*)(bo + a0) = pack_us(h0, h1);
                *(unsigned*)(bo + a0 + OC) = pack_us(l0, l1);
                split_bf16(v2, h0, l0); split_bf16(v3, h1, l1);
                size_t a1 = px1 * 2 * OC + oc;
                *(unsigned*)(bo + a1) = pack_us(h0, h1);
                *(unsigned*)(bo + a1 + OC) = pack_us(l0, l1);
            }
        }
    }
}

// =====================================================================
// e0: fp32 NCHW in (C=3) -> std bf16 planes.
// =====================================================================
__global__ void __launch_bounds__(256, 2) conv_e0(
    const float* __restrict__ in, const float* __restrict__ wgt,
    const float* __restrict__ bias, unsigned short* __restrict__ bout,
    int C, int OC, int H, int W, int act)
{
    constexpr int NT = 256;
    constexpr int ICB = 4;
    constexpr int SROW = 34;
    constexpr int SIN = 18 * SROW;

    const int tilesX = W >> 5;
    const int x0 = (blockIdx.x % tilesX) << 5;
    const int y0 = (blockIdx.x / tilesX) << 4;
    const int oc0 = blockIdx.y * 32;
    const int b = blockIdx.z;

    __shared__ __align__(16) float s_in[2][ICB][SIN];
    __shared__ __align__(16) float s_w[2][ICB][32 * 12];

    const int tid = threadIdx.x;
    const int g = tid >> 6;
    const int sp = tid & 63;
    const int ty = sp >> 3, tx = sp & 7;

    float acc[8][2][4];
#pragma unroll
    for (int o = 0; o < 8; o++)
#pragma unroll
        for (int dy = 0; dy < 2; dy++)
#pragma unroll
            for (int dx = 0; dx < 4; dx++) acc[o][dy][dx] = 0.f;

    const float* inb = in + (size_t)b * C * H * W;
    const float* wb = wgt + (size_t)oc0 * C * 9;

    auto stage_copy = [&](int buf, int ic0, int cnt) {
        const float* ins = inb + (size_t)ic0 * H * W;
        for (int i = tid; i < cnt * SIN; i += NT) {
            int ch = i / SIN, r2 = i - ch * SIN;
            int r = r2 / SROW, c2 = r2 - r * SROW;
            int iy = y0 - 1 + r, ix = x0 - 1 + c2;
            bool p = (unsigned)iy < (unsigned)H && (unsigned)ix < (unsigned)W;
            cp_async4(&s_in[buf][ch][r2], ins + (size_t)ch * H * W + (size_t)iy * W + ix, p);
        }
        for (int i = tid; i < cnt * 32 * 9; i += NT) {
            int ch = i / (32 * 9), r2 = i - ch * (32 * 9);
            int o = r2 / 9, j2 = r2 - o * 9;
            cp_async4(&s_w[buf][ch][o * 12 + j2],
                      wb + ((size_t)o * C + ic0 + ch) * 9 + j2, true);
        }
    };

    const int sbase = (2 * ty) * SROW + 4 * tx;

    auto compute_ch = [&](int buf, int ch) {
        float rr[4][6];
        const float* si = &s_in[buf][ch][sbase];
#pragma unroll
        for (int r = 0; r < 4; r++) {
            const float2* p = (const float2*)(si + r * SROW);
            float2 a = p[0], b2 = p[1], c2 = p[2];
            rr[r][0] = a.x; rr[r][1] = a.y; rr[r][2] = b2.x;
            rr[r][3] = b2.y; rr[r][4] = c2.x; rr[r][5] = c2.y;
        }
#pragma unroll
        for (int o = 0; o < 8; o++) {
            const float4* wp = (const float4*)&s_w[buf][ch][(g * 8 + o) * 12];
            float4 wa = wp[0];
            float4 wc = wp[1];
            float w8 = ((const float*)wp)[8];
#pragma unroll
            for (int dy = 0; dy < 2; dy++)
#pragma unroll
                for (int dx = 0; dx < 4; dx++) {
                    float s = acc[o][dy][dx];
                    s += wa.x * rr[dy + 0][dx + 0];
                    s += wa.y * rr[dy + 0][dx + 1];
                    s += wa.z * rr[dy + 0][dx + 2];
                    s += wa.w * rr[dy + 1][dx + 0];
                    s += wc.x * rr[dy + 1][dx + 1];
                    s += wc.y * rr[dy + 1][dx + 2];
                    s += wc.z * rr[dy + 2][dx + 0];
                    s += wc.w * rr[dy + 2][dx + 1];
                    s += w8   * rr[dy + 2][dx + 2];
                    acc[o][dy][dx] = s;
                }
        }
    };

    const int nst = (C + ICB - 1) / ICB;
    stage_copy(0, 0, C < ICB ? C : ICB);
    cp_commit();
    for (int s = 0; s < nst; s++) {
        int buf = s & 1;
        cp_wait0();
        __syncthreads();
        int icn = (s + 1) * ICB;
        if (icn < C) {
            int cn = C - icn; if (cn > ICB) cn = ICB;
            stage_copy(buf ^ 1, icn, cn);
        }
        cp_commit();
        int cnt = C - s * ICB; if (cnt > ICB) cnt = ICB;
        for (int j = 0; j < cnt; j++) compute_ch(buf, j);
    }

    float bv[8];
#pragma unroll
    for (int o = 0; o < 8; o++) bv[o] = bias[oc0 + g * 8 + o];
    unsigned short* bo = bout + (size_t)b * H * W * 2 * OC;
#pragma unroll
    for (int dy = 0; dy < 2; dy++)
#pragma unroll
        for (int dx = 0; dx < 4; dx++) {
            int y = y0 + 2 * ty + dy, x = x0 + 4 * tx + dx;
            float v[8];
            unsigned short h[8], l[8];
#pragma unroll
            for (int o = 0; o < 8; o++) {
                v[o] = activate(acc[o][dy][dx] + bv[o], act);
                split_bf16(v[o], h[o], l[o]);
            }
            unsigned short* bb = bo + ((size_t)y * W + x) * 2 * OC + oc0 + g * 8;
            uint4 H4, L4;
            H4.x = pack_us(h[0], h[1]); H4.y = pack_us(h[2], h[3]);
            H4.z = pack_us(h[4], h[5]); H4.w = pack_us(h[6], h[7]);
            L4.x = pack_us(l[0], l[1]); L4.y = pack_us(l[2], l[3]);
            L4.z = pack_us(l[4], l[5]); L4.w = pack_us(l[6], l[7]);
            *(uint4*)bb = H4;
            *(uint4*)(bb + OC) = L4;
        }
}

// =====================================================================
// transposed conv 3x3 stride-2 SAME (pad_a=2). fp32 NCHW in -> std bf16. relu.
// =====================================================================
__global__ void __launch_bounds__(256, 3) tconv_s2(
    const float* __restrict__ in, const float* __restrict__ wgt,
    const float* __restrict__ bias, unsigned short* __restrict__ bout,
    int C, int OC, int Hout, int Wout)
{
    constexpr int NT = 256;
    constexpr int ICB = 4;
    constexpr int SIN = 9 * 9;

    const int Hin = Hout >> 1, Win = Wout >> 1;
    const int tilesX = Wout >> 4;
    const int x0 = (blockIdx.x % tilesX) << 4;
    const int y0 = (blockIdx.x / tilesX) << 4;
    const int oc0 = blockIdx.y * 16;
    const int b = blockIdx.z;
    const int Y0 = y0 >> 1, X0 = x0 >> 1;

    __shared__ __align__(16) float s_in[2][ICB][SIN + 3];
    __shared__ __align__(16) float s_w[2][ICB][16 * 12];

    const int tid = threadIdx.x;
    const int g = tid >> 6;
    const int sp = tid & 63;
    const int ty = sp >> 3, tx = sp & 7;

    float acc[4][4];
#pragma unroll
    for (int o = 0; o < 4; o++)
#pragma unroll
        for (int p = 0; p < 4; p++) acc[o][p] = 0.f;

    const float* inb = in + (size_t)b * C * Hin * Win;
    const float* wb = wgt + (size_t)oc0 * C * 9;

    auto stage_copy = [&](int buf, int ic0, int cnt) {
        const float* ins = inb + (size_t)ic0 * Hin * Win;
        for (int i = tid; i < cnt * SIN; i += NT) {
            int ch = i / SIN, r2 = i - ch * SIN;
            int r = r2 / 9, c2 = r2 - r * 9;
            int iy = Y0 - 1 + r, ix = X0 - 1 + c2;
            bool p = (unsigned)iy < (unsigned)Hin && (unsigned)ix < (unsigned)Win;
            cp_async4(&s_in[buf][ch][r2], ins + (size_t)ch * Hin * Win + (size_t)iy * Win + ix, p);
        }
        for (int i = tid; i < cnt * 16 * 9; i += NT) {
            int ch = i / (16 * 9), r2 = i - ch * (16 * 9);
            int o = r2 / 9, j2 = r2 - o * 9;
            cp_async4(&s_w[buf][ch][o * 12 + j2],
                      wb + ((size_t)o * C + ic0 + ch) * 9 + j2, true);
        }
    };

    auto compute_ch = [&](int buf, int ch) {
        const float* si = s_in[buf][ch];
        float r00 = si[ty * 9 + tx];
        float r01 = si[ty * 9 + tx + 1];
        float r10 = si[(ty + 1) * 9 + tx];
        float r11 = si[(ty + 1) * 9 + tx + 1];
#pragma unroll
        for (int o = 0; o < 4; o++) {
            const float4* wp = (const float4*)&s_w[buf][ch][(g * 4 + o) * 12];
            float4 wa = wp[0];
            float4 wc = wp[1];
            float w8 = ((const float*)wp)[8];
            acc[o][0] += wa.x * r00 + wa.z * r01 + wc.z * r10 + w8 * r11;
            acc[o][1] += wa.y * r01 + wc.w * r11;
            acc[o][2] += wa.w * r10 + wc.y * r11;
            acc[o][3] += wc.x * r11;
        }
    };

    const int nst = (C + ICB - 1) / ICB;
    stage_copy(0, 0, C < ICB ? C : ICB);
    cp_commit();
    for (int s = 0; s < nst; s++) {
        int buf = s & 1;
        cp_wait0();
        __syncthreads();
        int icn = (s + 1) * ICB;
        if (icn < C) {
            int cn = C - icn; if (cn > ICB) cn = ICB;
            stage_copy(buf ^ 1, icn, cn);
        }
        cp_commit();
        int cnt = C - s * ICB; if (cnt > ICB) cnt = ICB;
        if (cnt == ICB) {
#pragma unroll
            for (int j = 0; j < ICB; j++) compute_ch(buf, j);
        } else {
            for (int j = 0; j < cnt; j++) compute_ch(buf, j);
        }
    }

    float bv[4];
#pragma unroll
    for (int o = 0; o < 4; o++) bv[o] = bias[oc0 + g * 4 + o];
    unsigned short* bo = bout + (size_t)b * Hout * Wout * 2 * OC;
#pragma unroll
    for (int dy = 0; dy < 2; dy++)
#pragma unroll
        for (int dx = 0; dx < 2; dx++) {
            int y = y0 + 2 * ty + dy, x = x0 + 2 * tx + dx;
            size_t px = (size_t)y * Wout + x;
            float v[4];
#pragma unroll
            for (int o = 0; o < 4; o++) {
                float t = acc[o][dy * 2 + dx] + bv[o];
                v[o] = t > 0.f ? t : 0.f;
            }
            unsigned short h[4], l[4];
#pragma unroll
            for (int o = 0; o < 4; o++) split_bf16(v[o], h[o], l[o]);
            unsigned short* bb = bo + px * 2 * OC + oc0 + g * 4;
            *(uint2*)bb = make_uint2(pack_us(h[0], h[1]), pack_us(h[2], h[3]));
            *(uint2*)(bb + OC) = make_uint2(pack_us(l[0], l[1]), pack_us(l[2], l[3]));
        }
}

// ---------------- keypoint bottleneck (fp32 NCHW) ----------------
__global__ void bn_stats(const float* __restrict__ R, float* __restrict__ S,
                         float* __restrict__ Sh, float* __restrict__ Sw)
{
    int bk = blockIdx.x;
    int t = threadIdx.x;
    float v = R[(size_t)bk * 256 + t];
    float a = v;
    float bsum = v * (float)(t >> 4);
    float c = v * (float)(t & 15);
#pragma unroll
    for (int off = 16; off > 0; off >>= 1) {
        a += __shfl_down_sync(0xffffffffu, a, off);
        bsum += __shfl_down_sync(0xffffffffu, bsum, off);
        c += __shfl_down_sync(0xffffffffu, c, off);
    }
    __shared__ float sa[8], sb[8], sc[8];
    int wid = t >> 5;
    if ((t & 31) == 0) { sa[wid] = a; sb[wid] = bsum; sc[wid] = c; }
    __syncthreads();
    if (t == 0) {
        float ta = 0.f, tb = 0.f, tc = 0.f;
        for (int i = 0; i < 8; i++) { ta += sa[i]; tb += sb[i]; tc += sc[i]; }
        S[bk] = ta; Sh[bk] = tb; Sw[bk] = tc;
    }
}

__global__ void bn_maps(const float* __restrict__ S, const float* __restrict__ Sh,
                        const float* __restrict__ Sw, float* __restrict__ maps)
{
    int bk = blockIdx.x;
    int b = bk >> 7;
    float s = S[bk];
    float denom = S[(b << 7) | 127];
    float mu = s * (1.f / 256.f);
    float inv = 1.f / denom;
    float c0 = Sh[bk] * inv;
    float c1 = Sw[bk] * inv;
    int t = threadIdx.x;
    float h = (float)(t >> 4), w = (float)(t & 15);
    float dh = h - c0, dw = w - c1;
    maps[(size_t)bk * 256 + t] = mu * expf(-0.5f * (dh * dh + dw * dw));
}

// ---------------- launch ----------------
extern "C" void kernel_launch(void* const* d_in, const int* in_sizes, int n_in,
                              void* d_out, int out_size)
{
    (void)in_sizes; (void)n_in; (void)out_size;
    const float* x = (const float*)d_in[0];
    const float* ew[7]; const float* eb[7];
    for (int j = 0; j < 7; j++) {
        ew[j] = (const float*)d_in[1 + 2 * j];
        eb[j] = (const float*)d_in[2 + 2 * j];
    }
    const float* dw[6]; const float* db[6];
    for (int j = 0; j < 6; j++) {
        dw[j] = (const float*)d_in[15 + 2 * j];
        db[j] = (const float*)d_in[16 + 2 * j];
    }
    float* out = (float*)d_out;

    float *F0, *F1, *S, *Sh, *Sw;
    unsigned short *B0, *B1;
    uint4 *wprep, *wprep2;
    cudaGetSymbolAddress((void**)&F0, g_f0);
    cudaGetSymbolAddress((void**)&F1, g_f1);
    cudaGetSymbolAddress((void**)&B0, g_b0);
    cudaGetSymbolAddress((void**)&B1, g_b1);
    cudaGetSymbolAddress((void**)&wprep, g_wprep);
    cudaGetSymbolAddress((void**)&wprep2, g_wprep2);
    cudaGetSymbolAddress((void**)&S, g_S);
    cudaGetSymbolAddress((void**)&Sh, g_Sh);
    cudaGetSymbolAddress((void**)&Sw, g_Sw);

    static bool attr_set = false;
    if (!attr_set) {
        cudaFuncSetAttribute(conv_mma_s1<4>, cudaFuncAttributeMaxDynamicSharedMemorySize, MMA_SMEM);
        cudaFuncSetAttribute(conv_mma_s1<2>, cudaFuncAttributeMaxDynamicSharedMemorySize, MMA_SMEM);
        cudaFuncSetAttribute(conv_mma_s2c<4>, cudaFuncAttributeMaxDynamicSharedMemorySize, MMA_SMEM2);
        attr_set = true;
    }

    const int B = 32;
    const int OFF_E1 = 0, OFF_E3 = 2304, OFF_E5 = 11520;
    const int OFF_D1 = 48384, OFF_D3 = 57600, OFF_D5 = 59904;
    const int OFF2_E2 = 0, OFF2_E4 = 8192, OFF2_E6 = 40960;

    // 1: s1 enc weight prep
    prep_many<<<dim3(144, 3, 1), 256>>>(ew[1], ew[3], ew[5], wprep,
                                        OFF_E1, OFF_E3, OFF_E5, 32, 32, 64, 64, 128, 128);
    // 2: s1 dec weight prep
    prep_many<<<dim3(36, 3, 1), 256>>>(dw[1], dw[3], dw[5], wprep,
                                       OFF_D1, OFF_D3, OFF_D5, 64, 64, 32, 32, 16, 16);
    // 3: s2c weight prep (e2, e4, e6)
    prep_s2c<<<dim3(256, 3, 1), 256>>>(ew[2], ew[4], ew[6], wprep2,
                                       OFF2_E2, OFF2_E4, OFF2_E6,
                                       32, 64, 64, 128, 128, 128);
    // 4: e0 -> B0 (std planes)
    conv_e0<<<dim3(32, 1, B), 256>>>(x, ew[0], eb[0], B0, 3, 32, 128, 128, 0);
    // 5: e1 s1: B0 -> B1
    conv_mma_s1<4><<<dim3(64, 1, B), 256, MMA_SMEM>>>(B0, wprep + OFF_E1, eb[1],
                                                      nullptr, B1, 32, 32, 128, 128, 0, 1);
    // 6: e2 s2c: B1 -> B0   <-- profiled
    conv_mma_s2c<4><<<dim3(16, 2, B), 256, MMA_SMEM2>>>(B1, wprep2 + OFF2_E2, eb[2],
                                                        nullptr, B0, 32, 64, 64, 64, 1, 1);
    // e3 s1: B0 -> B1
    conv_mma_s1<4><<<dim3(16, 2, B), 256, MMA_SMEM>>>(B0, wprep + OFF_E3, eb[3],
                                                      nullptr, B1, 64, 64, 64, 64, 1, 1);
    // e4 s2c: B1 -> B0
    conv_mma_s2c<4><<<dim3(4, 4, B), 256, MMA_SMEM2>>>(B1, wprep2 + OFF2_E4, eb[4],
                                                       nullptr, B0, 64, 128, 32, 32, 1, 1);
    // e5 s1: B0 -> B1
    conv_mma_s1<4><<<dim3(4, 4, B), 256, MMA_SMEM>>>(B0, wprep + OFF_E5, eb[5],
                                                     nullptr, B1, 128, 128, 32, 32, 1, 1);
    // e6 s2c: B1 -> F1 (fp32 NCHW, softplus)
    conv_mma_s2c<4><<<dim3(1, 4, B), 256, MMA_SMEM2>>>(B1, wprep2 + OFF2_E6, eb[6],
                                                       F1, nullptr, 128, 128, 16, 16, 3, 0);
    // ---- keypoint bottleneck ----
    bn_stats<<<4096, 256>>>(F1, S, Sh, Sw);
    bn_maps<<<4096, 256>>>(S, Sh, Sw, F0);
    // ---- decoder ----
    tconv_s2<<<dim3(4, 4, B), 256>>>(F0, dw[0], db[0], B0, 128, 64, 32, 32);
    conv_mma_s1<4><<<dim3(4, 2, B), 256, MMA_SMEM>>>(B0, wprep + OFF_D1, db[1],
                                                     F0, nullptr, 64, 64, 32, 32, 2, 0);
    tconv_s2<<<dim3(16, 2, B), 256>>>(F0, dw[2], db[2], B0, 64, 32, 64, 64);
    conv_mma_s1<4><<<dim3(16, 1, B), 256, MMA_SMEM>>>(B0, wprep + OFF_D3, db[3],
                                                      F0, nullptr, 32, 32, 64, 64, 2, 0);
    tconv_s2<<<dim3(64, 1, B), 256>>>(F0, dw[4], db[4], B0, 32, 16, 128, 128);
    conv_mma_s1<2><<<dim3(64, 1, B), 256, MMA_SMEM>>>(B0, wprep + OFF_D5, db[5],
                                                      out, nullptr, 16, 16, 128, 128, 2, 0);
}

// round 13
// speedup vs baseline: 2.0612x; 1.2283x over previous
#include <cuda_runtime.h>
#include <cuda_bf16.h>
#include <math.h>

// ---------------- scratch ----------------
__device__ float g_f1[32u * 32 * 128 * 128];              // fp32 NCHW (e6 out)
__device__ unsigned short g_b0[33554432];                 // bf16 std planes ping
__device__ unsigned short g_b1[33554432];                 // bf16 std planes pong
__device__ uint4 g_wprep[60480];                          // s1 mma weights
__device__ uint4 g_wprep2[106496];                        // s2c mma weights
__device__ uint4 g_wprep3[43008];                         // t2c mma weights
__device__ float g_S[4096];
__device__ float g_Sh[4096];
__device__ float g_Sw[4096];

__device__ __forceinline__ float activate(float v, int act) {
    switch (act) {
        case 1: return v > 0.f ? v : 0.2f * v;
        case 2: return v > 0.f ? v : 0.f;
        case 3: return fmaxf(v, 0.f) + log1pf(expf(-fabsf(v)));
        default: return v;
    }
}

__device__ __forceinline__ void split_bf16(float x, unsigned short& h, unsigned short& l) {
    h = __bfloat16_as_ushort(__float2bfloat16(x));
    float hf = __uint_as_float((unsigned)h << 16);
    l = __bfloat16_as_ushort(__float2bfloat16(x - hf));
}
__device__ __forceinline__ unsigned pack_us(unsigned short a, unsigned short b) {
    return ((unsigned)b << 16) | (unsigned)a;
}
__device__ __forceinline__ unsigned pack2_bf16(float e_lo, float e_hi) {
    return ((unsigned)__bfloat16_as_ushort(__float2bfloat16(e_hi)) << 16)
         | (unsigned)__bfloat16_as_ushort(__float2bfloat16(e_lo));
}

__device__ __forceinline__ void cp_async4(void* sdst, const void* gsrc, bool pred) {
    unsigned saddr = (unsigned)__cvta_generic_to_shared(sdst);
    int sz = pred ? 4 : 0;
    asm volatile("cp.async.ca.shared.global [%0], [%1], 4, %2;\n"
                 :: "r"(saddr), "l"(gsrc), "r"(sz));
}
__device__ __forceinline__ void cp_async16(void* sdst, const void* gsrc, bool pred) {
    unsigned saddr = (unsigned)__cvta_generic_to_shared(sdst);
    int sz = pred ? 16 : 0;
    asm volatile("cp.async.cg.shared.global [%0], [%1], 16, %2;\n"
                 :: "r"(saddr), "l"(gsrc), "r"(sz));
}
__device__ __forceinline__ void cp_commit() { asm volatile("cp.async.commit_group;\n"); }
__device__ __forceinline__ void cp_wait0() { asm volatile("cp.async.wait_group 0;\n"); }

__device__ __forceinline__ void mma16816(float* d, const unsigned* a, unsigned b0, unsigned b1) {
    asm volatile("mma.sync.aligned.m16n8k16.row.col.f32.bf16.bf16.f32 "
                 "{%0,%1,%2,%3},{%4,%5,%6,%7},{%8,%9},{%0,%1,%2,%3};"
                 : "+f"(d[0]), "+f"(d[1]), "+f"(d[2]), "+f"(d[3])
                 : "r"(a[0]), "r"(a[1]), "r"(a[2]), "r"(a[3]), "r"(b0), "r"(b1));
}

// =====================================================================
// s1 weight prep (3 layers/launch)
// =====================================================================
__global__ void prep_many(const float* __restrict__ w0, const float* __restrict__ w1,
                          const float* __restrict__ w2, uint4* __restrict__ dstb,
                          int off0, int off1, int off2,
                          int C0, int OC0, int C1, int OC1, int C2, int OC2)
{
    int layer = blockIdx.y;
    const float* w = layer == 0 ? w0 : layer == 1 ? w1 : w2;
    uint4* dst = dstb + (layer == 0 ? off0 : layer == 1 ? off1 : off2);
    int C = layer == 0 ? C0 : layer == 1 ? C1 : C2;
    int OC = layer == 0 ? OC0 : layer == 1 ? OC1 : OC2;
    int OCg = OC >> 3;
    int total = (C >> 4) * 9 * OCg * 32;
    int idx = blockIdx.x * 256 + threadIdx.x;
    if (idx >= total) return;
    int l = idx & 31;
    int q = idx >> 5;
    int og = q % OCg; q /= OCg;
    int t = q % 9;
    int kc = q / 9;
    int tg = l & 3, gg = l >> 2;
    int n = og * 8 + gg;
    float h[4], lo[4];
#pragma unroll
    for (int kk = 0; kk < 4; kk++) {
        int k = (kk < 2) ? (2 * tg + kk) : (2 * tg + 8 + (kk - 2));
        int ic = (kc << 4) + k;
        float e = w[((size_t)n * C + ic) * 9 + t];
        unsigned hb = (unsigned)__bfloat16_as_ushort(__float2bfloat16(e)) << 16;
        h[kk] = __uint_as_float(hb);
        lo[kk] = e - h[kk];
    }
    uint4 r;
    r.x = pack2_bf16(h[0], h[1]);
    r.y = pack2_bf16(h[2], h[3]);
    r.z = pack2_bf16(lo[0], lo[1]);
    r.w = pack2_bf16(lo[2], lo[3]);
    dst[idx] = r;
}

// =====================================================================
// s2c weight prep: stride-2 3x3 -> 2x2 over 4C phase channels (q*C+c).
// =====================================================================
__global__ void prep_s2c(const float* __restrict__ w0, const float* __restrict__ w1,
                         const float* __restrict__ w2, uint4* __restrict__ dstb,
                         int off0, int off1, int off2,
                         int C0, int OC0, int C1, int OC1, int C2, int OC2)
{
    int layer = blockIdx.y;
    const float* w = layer == 0 ? w0 : layer == 1 ? w1 : w2;
    uint4* dst = dstb + (layer == 0 ? off0 : layer == 1 ? off1 : off2);
    int C = layer == 0 ? C0 : layer == 1 ? C1 : C2;
    int OC = layer == 0 ? OC0 : layer == 1 ? OC1 : OC2;
    int OCg = OC >> 3;
    int KC = (4 * C) >> 4;
    int total = KC * 4 * OCg * 32;
    int idx = blockIdx.x * 256 + threadIdx.x;
    if (idx >= total) return;
    int l = idx & 31;
    int q = idx >> 5;
    int og = q % OCg; q /= OCg;
    int t = q % 4;
    int kc = q / 4;
    int dy = t >> 1, dx = t & 1;
    int tg = l & 3, gg = l >> 2;
    int n = og * 8 + gg;
    float h[4], lo[4];
#pragma unroll
    for (int kk = 0; kk < 4; kk++) {
        int k = (kk < 2) ? (2 * tg + kk) : (2 * tg + 8 + (kk - 2));
        int ch = (kc << 4) + k;
        int qph = ch / C, c = ch - qph * C;
        int a = qph >> 1, bph = qph & 1;
        int ky = 2 * dy + a, kx = 2 * dx + bph;
        float e = (ky < 3 && kx < 3) ? w[((size_t)n * C + c) * 9 + ky * 3 + kx] : 0.f;
        unsigned hb = (unsigned)__bfloat16_as_ushort(__float2bfloat16(e)) << 16;
        h[kk] = __uint_as_float(hb);
        lo[kk] = e - h[kk];
    }
    uint4 r;
    r.x = pack2_bf16(h[0], h[1]);
    r.y = pack2_bf16(h[2], h[3]);
    r.z = pack2_bf16(lo[0], lo[1]);
    r.w = pack2_bf16(lo[2], lo[3]);
    dst[idx] = r;
}

// =====================================================================
// t2c weight prep: transposed stride-2 3x3 -> 2x2 conv over input grid,
// N = 4*OC phase channels: n = q*OC + oc, q = 2a+b.
// out[2i+a,2j+b] = sum_{u,v} w[oc,c,2u-a,2v-b] * X[i-1+u, j-1+v]
// =====================================================================
__global__ void prep_t2c(const float* __restrict__ w0, const float* __restrict__ w1,
                         const float* __restrict__ w2, uint4* __restrict__ dstb,
                         int off0, int off1, int off2,
                         int C0, int OC0, int C1, int OC1, int C2, int OC2)
{
    int layer = blockIdx.y;
    const float* w = layer == 0 ? w0 : layer == 1 ? w1 : w2;
    uint4* dst = dstb + (layer == 0 ? off0 : layer == 1 ? off1 : off2);
    int C = layer == 0 ? C0 : layer == 1 ? C1 : C2;
    int OC = layer == 0 ? OC0 : layer == 1 ? OC1 : OC2;
    int NN = 4 * OC;
    int OCgN = NN >> 3;
    int KC = C >> 4;
    int total = KC * 4 * OCgN * 32;
    int idx = blockIdx.x * 256 + threadIdx.x;
    if (idx >= total) return;
    int l = idx & 31;
    int q = idx >> 5;
    int og = q % OCgN; q /= OCgN;
    int t = q % 4;
    int kc = q / 4;
    int u = t >> 1, v = t & 1;
    int tg = l & 3, gg = l >> 2;
    int n = og * 8 + gg;
    int qph = n / OC, oc = n - qph * OC;
    int a = qph >> 1, bph = qph & 1;
    int ky = 2 * u - a, kx = 2 * v - bph;
    float h[4], lo[4];
#pragma unroll
    for (int kk = 0; kk < 4; kk++) {
        int k = (kk < 2) ? (2 * tg + kk) : (2 * tg + 8 + (kk - 2));
        int c = (kc << 4) + k;
        float e = (ky >= 0 && kx >= 0) ? w[((size_t)oc * C + c) * 9 + ky * 3 + kx] : 0.f;
        unsigned hb = (unsigned)__bfloat16_as_ushort(__float2bfloat16(e)) << 16;
        h[kk] = __uint_as_float(hb);
        lo[kk] = e - h[kk];
    }
    uint4 r;
    r.x = pack2_bf16(h[0], h[1]);
    r.y = pack2_bf16(h[2], h[3]);
    r.z = pack2_bf16(lo[0], lo[1]);
    r.w = pack2_bf16(lo[2], lo[3]);
    dst[idx] = r;
}

// =====================================================================
// tensor-core stride-1 3x3 SAME conv (bf16x3 split). Templated NF.
// in: std bf16 planes [px][2][C].
// out mode 0: fp32 NCHW; mode 1: std bf16 planes.
// =====================================================================
#define SINW (324 * 12)
#define MMA_SW (9 * 4 * 32)
#define MMA_SMEM (2 * 2 * SINW * 4 + 2 * MMA_SW * 16)

template <int NF>
__global__ void __launch_bounds__(256, 2) conv_mma_s1(
    const unsigned short* __restrict__ in, const uint4* __restrict__ wp,
    const float* __restrict__ bias, float* __restrict__ fout,
    unsigned short* __restrict__ bout, int C, int OC, int H, int W, int act, int mode)
{
    const int KC = C >> 4;
    const int tilesX = W >> 4;
    const int x0 = (blockIdx.x % tilesX) << 4;
    const int y0 = (blockIdx.x / tilesX) << 4;
    const int oc0 = blockIdx.y * (NF * 8);
    const int b = blockIdx.z;
    const int OCg = OC >> 3;

    extern __shared__ __align__(16) unsigned char dsm[];
    unsigned* s_hi = (unsigned*)dsm;
    unsigned* s_lo = s_hi + 2 * SINW;
    uint4* s_w = (uint4*)(dsm + 4 * 4 * SINW);

    const unsigned short* inb = in + (size_t)b * H * W * 2 * C;
    const int tid = threadIdx.x, lane = tid & 31, wid = tid >> 5;
    const int g = lane >> 2, tg = lane & 3;

    float d[2][NF][4];
#pragma unroll
    for (int i = 0; i < 2; i++)
#pragma unroll
        for (int j = 0; j < NF; j++)
#pragma unroll
            for (int r = 0; r < 4; r++) d[i][j][r] = 0.f;

    auto stage = [&](int buf, int kc) {
        unsigned* hi = s_hi + buf * SINW;
        unsigned* lo = s_lo + buf * SINW;
        for (int i = tid; i < 648; i += 256) {
            int sp = i >> 1, q = i & 1;
            int r = sp / 18, c = sp - r * 18;
            int iy = y0 - 1 + r, ix = x0 - 1 + c;
            bool p = (unsigned)iy < (unsigned)H && (unsigned)ix < (unsigned)W;
            const unsigned short* src = inb + ((size_t)iy * W + ix) * 2 * C + (kc << 4) + (q << 3);
            cp_async16(hi + sp * 12 + q * 4, src, p);
            cp_async16(lo + sp * 12 + q * 4, src + C, p);
        }
        uint4* sw = s_w + buf * MMA_SW;
        const uint4* wsrc = wp + (size_t)kc * 9 * OCg * 32;
        const int tot = 9 * NF * 32;
        for (int i = tid; i < tot; i += 256) {
            int l = i & 31;
            int q = i >> 5;
            int ogl = q % NF;
            int t = q / NF;
            cp_async16(sw + (t * 4 + ogl) * 32 + l,
                       wsrc + ((size_t)t * OCg + (oc0 >> 3) + ogl) * 32 + l, true);
        }
    };

    auto compute = [&](int buf) {
        unsigned* hi = s_hi + buf * SINW;
        unsigned* lo = s_lo + buf * SINW;
        uint4* sw = s_w + buf * MMA_SW;
#pragma unroll
        for (int t = 0; t < 9; t++) {
            const int dy = t / 3, dx = t - 3 * (t / 3);
            unsigned ah[2][4], al[2][4];
#pragma unroll
            for (int i = 0; i < 2; i++) {
                int sp0 = (2 * wid + i + dy) * 18 + g + dx;
                const unsigned* h0 = hi + sp0 * 12;
                const unsigned* l0 = lo + sp0 * 12;
                ah[i][0] = h0[tg];       ah[i][1] = h0[96 + tg];
                ah[i][2] = h0[tg + 4];   ah[i][3] = h0[96 + tg + 4];
                al[i][0] = l0[tg];       al[i][1] = l0[96 + tg];
                al[i][2] = l0[tg + 4];   al[i][3] = l0[96 + tg + 4];
            }
#pragma unroll
            for (int j = 0; j < NF; j++) {
                uint4 bw = sw[(t * 4 + j) * 32 + lane];
#pragma unroll
                for (int i = 0; i < 2; i++) {
                    mma16816(d[i][j], ah[i], bw.x, bw.y);
                    mma16816(d[i][j], al[i], bw.x, bw.y);
                    mma16816(d[i][j], ah[i], bw.z, bw.w);
                }
            }
        }
    };

    stage(0, 0);
    cp_commit();
    for (int kc = 0; kc < KC; kc++) {
        int buf = kc & 1;
        cp_wait0();
        __syncthreads();
        if (kc + 1 < KC) stage(buf ^ 1, kc + 1);
        cp_commit();
        compute(buf);
    }

    if (mode == 0) {
#pragma unroll
        for (int i = 0; i < 2; i++) {
            int y = y0 + 2 * wid + i;
#pragma unroll
            for (int j = 0; j < NF; j++) {
                int oc = oc0 + 8 * j + 2 * tg;
                float b0 = bias[oc], b1 = bias[oc + 1];
                size_t base0 = (((size_t)b * OC + oc) * H + y) * W + x0;
                size_t base1 = base0 + (size_t)H * W;
                fout[base0 + g]     = activate(d[i][j][0] + b0, act);
                fout[base1 + g]     = activate(d[i][j][1] + b1, act);
                fout[base0 + g + 8] = activate(d[i][j][2] + b0, act);
                fout[base1 + g + 8] = activate(d[i][j][3] + b1, act);
            }
        }
    } else {
        unsigned short* bo = bout + (size_t)b * H * W * 2 * OC;
#pragma unroll
        for (int i = 0; i < 2; i++) {
            int y = y0 + 2 * wid + i;
#pragma unroll
            for (int j = 0; j < NF; j++) {
                int oc = oc0 + 8 * j + 2 * tg;
                float b0 = bias[oc], b1 = bias[oc + 1];
                float v0 = activate(d[i][j][0] + b0, act);
                float v1 = activate(d[i][j][1] + b1, act);
                float v2 = activate(d[i][j][2] + b0, act);
                float v3 = activate(d[i][j][3] + b1, act);
                size_t px0 = (size_t)y * W + x0 + g;
                size_t px1 = px0 + 8;
                unsigned short h0, l0, h1, l1;
                split_bf16(v0, h0, l0); split_bf16(v1, h1, l1);
                size_t a0 = px0 * 2 * OC + oc;
                *(unsigned*)(bo + a0) = pack_us(h0, h1);
                *(unsigned*)(bo + a0 + OC) = pack_us(l0, l1);
                split_bf16(v2, h0, l0); split_bf16(v3, h1, l1);
                size_t a1 = px1 * 2 * OC + oc;
                *(unsigned*)(bo + a1) = pack_us(h0, h1);
                *(unsigned*)(bo + a1 + OC) = pack_us(l0, l1);
            }
        }
    }
}

// =====================================================================
// tensor-core stride-2 conv as 2x2 s2c over CC=4C channels. Templated NF.
// in: STD bf16 planes at Hin=2Hout x Win=2Wout (phase gather in staging).
// out mode 0: fp32 NCHW (+act). mode 1: std bf16 planes.
// =====================================================================
#define SINW2 (289 * 12)
#define MMA_SW2 (4 * 4 * 32)
#define MMA_SMEM2 (2 * 2 * SINW2 * 4 + 2 * MMA_SW2 * 16)

template <int NF>
__global__ void __launch_bounds__(256, 2) conv_mma_s2c(
    const unsigned short* __restrict__ in, const uint4* __restrict__ wp,
    const float* __restrict__ bias, float* __restrict__ fout,
    unsigned short* __restrict__ bout, int C, int OC, int Hout, int Wout,
    int act, int mode)
{
    const int CC = 4 * C;
    const int KC = CC >> 4;
    const int Hin = Hout * 2, Win = Wout * 2;
    const int tilesX = Wout >> 4;
    const int x0 = (blockIdx.x % tilesX) << 4;
    const int y0 = (blockIdx.x / tilesX) << 4;
    const int oc0 = blockIdx.y * (NF * 8);
    const int b = blockIdx.z;
    const int OCg = OC >> 3;

    extern __shared__ __align__(16) unsigned char dsm[];
    unsigned* s_hi = (unsigned*)dsm;
    unsigned* s_lo = s_hi + 2 * SINW2;
    uint4* s_w = (uint4*)(dsm + 4 * 4 * SINW2);

    const unsigned short* inb = in + (size_t)b * Hin * Win * 2 * C;
    const int tid = threadIdx.x, lane = tid & 31, wid = tid >> 5;
    const int g = lane >> 2, tg = lane & 3;

    float d[2][NF][4];
#pragma unroll
    for (int i = 0; i < 2; i++)
#pragma unroll
        for (int j = 0; j < NF; j++)
#pragma unroll
            for (int r = 0; r < 4; r++) d[i][j][r] = 0.f;

    auto stage = [&](int buf, int kc) {
        unsigned* hi = s_hi + buf * SINW2;
        unsigned* lo = s_lo + buf * SINW2;
        int qph = (kc << 4) / C;
        int c0 = (kc << 4) - qph * C;
        int pa = qph >> 1, pb = qph & 1;
        for (int i = tid; i < 578; i += 256) {
            int sp = i >> 1, q = i & 1;
            int r = sp / 17, c = sp - r * 17;
            int sy = 2 * (y0 + r) + pa, sx = 2 * (x0 + c) + pb;
            bool p = sy < Hin && sx < Win;
            const unsigned short* src = inb + ((size_t)sy * Win + sx) * 2 * C + c0 + (q << 3);
            cp_async16(hi + sp * 12 + q * 4, src, p);
            cp_async16(lo + sp * 12 + q * 4, src + C, p);
        }
        uint4* sw = s_w + buf * MMA_SW2;
        const uint4* wsrc = wp + (size_t)kc * 4 * OCg * 32;
        const int tot = 4 * NF * 32;
        for (int i = tid; i < tot; i += 256) {
            int l = i & 31;
            int q = i >> 5;
            int ogl = q % NF;
            int t = q / NF;
            cp_async16(sw + (t * 4 + ogl) * 32 + l,
                       wsrc + ((size_t)t * OCg + (oc0 >> 3) + ogl) * 32 + l, true);
        }
    };

    auto compute = [&](int buf) {
        unsigned* hi = s_hi + buf * SINW2;
        unsigned* lo = s_lo + buf * SINW2;
        uint4* sw = s_w + buf * MMA_SW2;
#pragma unroll
        for (int t = 0; t < 4; t++) {
            const int dy = t >> 1, dx = t & 1;
            unsigned ah[2][4], al[2][4];
#pragma unroll
            for (int i = 0; i < 2; i++) {
                int sp0 = (2 * wid + i + dy) * 17 + g + dx;
                const unsigned* h0 = hi + sp0 * 12;
                const unsigned* l0 = lo + sp0 * 12;
                ah[i][0] = h0[tg];       ah[i][1] = h0[96 + tg];
                ah[i][2] = h0[tg + 4];   ah[i][3] = h0[96 + tg + 4];
                al[i][0] = l0[tg];       al[i][1] = l0[96 + tg];
                al[i][2] = l0[tg + 4];   al[i][3] = l0[96 + tg + 4];
            }
#pragma unroll
            for (int j = 0; j < NF; j++) {
                uint4 bw = sw[(t * 4 + j) * 32 + lane];
#pragma unroll
                for (int i = 0; i < 2; i++) {
                    mma16816(d[i][j], ah[i], bw.x, bw.y);
                    mma16816(d[i][j], al[i], bw.x, bw.y);
                    mma16816(d[i][j], ah[i], bw.z, bw.w);
                }
            }
        }
    };

    stage(0, 0);
    cp_commit();
    for (int kc = 0; kc < KC; kc++) {
        int buf = kc & 1;
        cp_wait0();
        __syncthreads();
        if (kc + 1 < KC) stage(buf ^ 1, kc + 1);
        cp_commit();
        compute(buf);
    }

    if (mode == 0) {
#pragma unroll
        for (int i = 0; i < 2; i++) {
            int y = y0 + 2 * wid + i;
#pragma unroll
            for (int j = 0; j < NF; j++) {
                int oc = oc0 + 8 * j + 2 * tg;
                float b0 = bias[oc], b1 = bias[oc + 1];
                size_t base0 = (((size_t)b * OC + oc) * Hout + y) * Wout + x0;
                size_t base1 = base0 + (size_t)Hout * Wout;
                fout[base0 + g]     = activate(d[i][j][0] + b0, act);
                fout[base1 + g]     = activate(d[i][j][1] + b1, act);
                fout[base0 + g + 8] = activate(d[i][j][2] + b0, act);
                fout[base1 + g + 8] = activate(d[i][j][3] + b1, act);
            }
        }
    } else {
        unsigned short* bo = bout + (size_t)b * Hout * Wout * 2 * OC;
#pragma unroll
        for (int i = 0; i < 2; i++) {
            int y = y0 + 2 * wid + i;
#pragma unroll
            for (int j = 0; j < NF; j++) {
                int oc = oc0 + 8 * j + 2 * tg;
                float b0 = bias[oc], b1 = bias[oc + 1];
                float v0 = activate(d[i][j][0] + b0, act);
                float v1 = activate(d[i][j][1] + b1, act);
                float v2 = activate(d[i][j][2] + b0, act);
                float v3 = activate(d[i][j][3] + b1, act);
                size_t px0 = (size_t)y * Wout + x0 + g;
                size_t px1 = px0 + 8;
                unsigned short h0, l0, h1, l1;
                split_bf16(v0, h0, l0); split_bf16(v1, h1, l1);
                size_t a0 = px0 * 2 * OC + oc;
                *(unsigned*)(bo + a0) = pack_us(h0, h1);
                *(unsigned*)(bo + a0 + OC) = pack_us(l0, l1);
                split_bf16(v2, h0, l0); split_bf16(v3, h1, l1);
                size_t a1 = px1 * 2 * OC + oc;
                *(unsigned*)(bo + a1) = pack_us(h0, h1);
                *(unsigned*)(bo + a1 + OC) = pack_us(l0, l1);
            }
        }
    }
}

// =====================================================================
// tensor-core transposed conv (t2c): 2x2 conv over input grid, N=4*OC
// phase channels. in: std bf16 planes at Hin x Win (input grid).
// out: std bf16 planes at 2Hin x 2Win. relu.
// =====================================================================
template <int NF>
__global__ void __launch_bounds__(256, 2) conv_mma_t2c(
    const unsigned short* __restrict__ in, const uint4* __restrict__ wp,
    const float* __restrict__ bias, unsigned short* __restrict__ bout,
    int C, int OC, int Hin, int Win)
{
    const int KC = C >> 4;
    const int NN = 4 * OC;
    const int OCgN = NN >> 3;
    const int Wout = Win * 2;
    const int tilesX = Win >> 4;
    const int x0 = (blockIdx.x % tilesX) << 4;
    const int y0 = (blockIdx.x / tilesX) << 4;
    const int oc0 = blockIdx.y * (NF * 8);
    const int b = blockIdx.z;

    extern __shared__ __align__(16) unsigned char dsm[];
    unsigned* s_hi = (unsigned*)dsm;
    unsigned* s_lo = s_hi + 2 * SINW2;
    uint4* s_w = (uint4*)(dsm + 4 * 4 * SINW2);

    const unsigned short* inb = in + (size_t)b * Hin * Win * 2 * C;
    const int tid = threadIdx.x, lane = tid & 31, wid = tid >> 5;
    const int g = lane >> 2, tg = lane & 3;

    float d[2][NF][4];
#pragma unroll
    for (int i = 0; i < 2; i++)
#pragma unroll
        for (int j = 0; j < NF; j++)
#pragma unroll
            for (int r = 0; r < 4; r++) d[i][j][r] = 0.f;

    auto stage = [&](int buf, int kc) {
        unsigned* hi = s_hi + buf * SINW2;
        unsigned* lo = s_lo + buf * SINW2;
        for (int i = tid; i < 578; i += 256) {
            int sp = i >> 1, q = i & 1;
            int r = sp / 17, c = sp - r * 17;
            int iy = y0 - 1 + r, ix = x0 - 1 + c;
            bool p = (unsigned)iy < (unsigned)Hin && (unsigned)ix < (unsigned)Win;
            const unsigned short* src = inb + ((size_t)iy * Win + ix) * 2 * C + (kc << 4) + (q << 3);
            cp_async16(hi + sp * 12 + q * 4, src, p);
            cp_async16(lo + sp * 12 + q * 4, src + C, p);
        }
        uint4* sw = s_w + buf * MMA_SW2;
        const uint4* wsrc = wp + (size_t)kc * 4 * OCgN * 32;
        const int tot = 4 * NF * 32;
        for (int i = tid; i < tot; i += 256) {
            int l = i & 31;
            int q = i >> 5;
            int ogl = q % NF;
            int t = q / NF;
            cp_async16(sw + (t * 4 + ogl) * 32 + l,
                       wsrc + ((size_t)t * OCgN + (oc0 >> 3) + ogl) * 32 + l, true);
        }
    };

    auto compute = [&](int buf) {
        unsigned* hi = s_hi + buf * SINW2;
        unsigned* lo = s_lo + buf * SINW2;
        uint4* sw = s_w + buf * MMA_SW2;
#pragma unroll
        for (int t = 0; t < 4; t++) {
            const int dy = t >> 1, dx = t & 1;
            unsigned ah[2][4], al[2][4];
#pragma unroll
            for (int i = 0; i < 2; i++) {
                int sp0 = (2 * wid + i + dy) * 17 + g + dx;
                const unsigned* h0 = hi + sp0 * 12;
                const unsigned* l0 = lo + sp0 * 12;
                ah[i][0] = h0[tg];       ah[i][1] = h0[96 + tg];
                ah[i][2] = h0[tg + 4];   ah[i][3] = h0[96 + tg + 4];
                al[i][0] = l0[tg];       al[i][1] = l0[96 + tg];
                al[i][2] = l0[tg + 4];   al[i][3] = l0[96 + tg + 4];
            }
#pragma unroll
            for (int j = 0; j < NF; j++) {
                uint4 bw = sw[(t * 4 + j) * 32 + lane];
#pragma unroll
                for (int i = 0; i < 2; i++) {
                    mma16816(d[i][j], ah[i], bw.x, bw.y);
                    mma16816(d[i][j], al[i], bw.x, bw.y);
                    mma16816(d[i][j], ah[i], bw.z, bw.w);
                }
            }
        }
    };

    stage(0, 0);
    cp_commit();
    for (int kc = 0; kc < KC; kc++) {
        int buf = kc & 1;
        cp_wait0();
        __syncthreads();
        if (kc + 1 < KC) stage(buf ^ 1, kc + 1);
        cp_commit();
        compute(buf);
    }

    // epilogue: input px row y0+2wid+i, cols x0+g / x0+g+8;
    // n-channel = oc0+8j+2tg -> phase q, out px (2y+a, 2x+b), relu.
    unsigned short* bo2 = bout + (size_t)b * (2 * Hin) * Wout * 2 * OC;
#pragma unroll
    for (int i = 0; i < 2; i++) {
        int yin = y0 + 2 * wid + i;
#pragma unroll
        for (int j = 0; j < NF; j++) {
            int n0 = oc0 + 8 * j + 2 * tg;
            int q = n0 / OC;
            int oc = n0 - q * OC;
            int a = q >> 1, bph = q & 1;
            int oy = 2 * yin + a;
            float b0 = bias[oc], b1 = bias[oc + 1];
            float v0 = d[i][j][0] + b0; v0 = v0 > 0.f ? v0 : 0.f;
            float v1 = d[i][j][1] + b1; v1 = v1 > 0.f ? v1 : 0.f;
            float v2 = d[i][j][2] + b0; v2 = v2 > 0.f ? v2 : 0.f;
            float v3 = d[i][j][3] + b1; v3 = v3 > 0.f ? v3 : 0.f;
            size_t px0 = (size_t)oy * Wout + 2 * (x0 + g) + bph;
            size_t px1 = (size_t)oy * Wout + 2 * (x0 + g + 8) + bph;
            unsigned short h0, l0, h1, l1;
            split_bf16(v0, h0, l0); split_bf16(v1, h1, l1);
            size_t a0 = px0 * 2 * OC + oc;
            *(unsigned*)(bo2 + a0) = pack_us(h0, h1);
            *(unsigned*)(bo2 + a0 + OC) = pack_us(l0, l1);
            split_bf16(v2, h0, l0); split_bf16(v3, h1, l1);
            size_t a1 = px1 * 2 * OC + oc;
            *(unsigned*)(bo2 + a1) = pack_us(h0, h1);
            *(unsigned*)(bo2 + a1 + OC) = pack_us(l0, l1);
        }
    }
}

// =====================================================================
// e0: fp32 NCHW in (C=3) -> std bf16 planes.
// =====================================================================
__global__ void __launch_bounds__(256, 2) conv_e0(
    const float* __restrict__ in, const float* __restrict__ wgt,
    const float* __restrict__ bias, unsigned short* __restrict__ bout,
    int C, int OC, int H, int W, int act)
{
    constexpr int NT = 256;
    constexpr int ICB = 4;
    constexpr int SROW = 34;
    constexpr int SIN = 18 * SROW;

    const int tilesX = W >> 5;
    const int x0 = (blockIdx.x % tilesX) << 5;
    const int y0 = (blockIdx.x / tilesX) << 4;
    const int oc0 = blockIdx.y * 32;
    const int b = blockIdx.z;

    __shared__ __align__(16) float s_in[2][ICB][SIN];
    __shared__ __align__(16) float s_w[2][ICB][32 * 12];

    const int tid = threadIdx.x;
    const int g = tid >> 6;
    const int sp = tid & 63;
    const int ty = sp >> 3, tx = sp & 7;

    float acc[8][2][4];
#pragma unroll
    for (int o = 0; o < 8; o++)
#pragma unroll
        for (int dy = 0; dy < 2; dy++)
#pragma unroll
            for (int dx = 0; dx < 4; dx++) acc[o][dy][dx] = 0.f;

    const float* inb = in + (size_t)b * C * H * W;
    const float* wb = wgt + (size_t)oc0 * C * 9;

    auto stage_copy = [&](int buf, int ic0, int cnt) {
        const float* ins = inb + (size_t)ic0 * H * W;
        for (int i = tid; i < cnt * SIN; i += NT) {
            int ch = i / SIN, r2 = i - ch * SIN;
            int r = r2 / SROW, c2 = r2 - r * SROW;
            int iy = y0 - 1 + r, ix = x0 - 1 + c2;
            bool p = (unsigned)iy < (unsigned)H && (unsigned)ix < (unsigned)W;
            cp_async4(&s_in[buf][ch][r2], ins + (size_t)ch * H * W + (size_t)iy * W + ix, p);
        }
        for (int i = tid; i < cnt * 32 * 9; i += NT) {
            int ch = i / (32 * 9), r2 = i - ch * (32 * 9);
            int o = r2 / 9, j2 = r2 - o * 9;
            cp_async4(&s_w[buf][ch][o * 12 + j2],
                      wb + ((size_t)o * C + ic0 + ch) * 9 + j2, true);
        }
    };

    const int sbase = (2 * ty) * SROW + 4 * tx;

    auto compute_ch = [&](int buf, int ch) {
        float rr[4][6];
        const float* si = &s_in[buf][ch][sbase];
#pragma unroll
        for (int r = 0; r < 4; r++) {
            const float2* p = (const float2*)(si + r * SROW);
            float2 a = p[0], b2 = p[1], c2 = p[2];
            rr[r][0] = a.x; rr[r][1] = a.y; rr[r][2] = b2.x;
            rr[r][3] = b2.y; rr[r][4] = c2.x; rr[r][5] = c2.y;
        }
#pragma unroll
        for (int o = 0; o < 8; o++) {
            const float4* wp = (const float4*)&s_w[buf][ch][(g * 8 + o) * 12];
            float4 wa = wp[0];
            float4 wc = wp[1];
            float w8 = ((const float*)wp)[8];
#pragma unroll
            for (int dy = 0; dy < 2; dy++)
#pragma unroll
                for (int dx = 0; dx < 4; dx++) {
                    float s = acc[o][dy][dx];
                    s += wa.x * rr[dy + 0][dx + 0];
                    s += wa.y * rr[dy + 0][dx + 1];
                    s += wa.z * rr[dy + 0][dx + 2];
                    s += wa.w * rr[dy + 1][dx + 0];
                    s += wc.x * rr[dy + 1][dx + 1];
                    s += wc.y * rr[dy + 1][dx + 2];
                    s += wc.z * rr[dy + 2][dx + 0];
                    s += wc.w * rr[dy + 2][dx + 1];
                    s += w8   * rr[dy + 2][dx + 2];
                    acc[o][dy][dx] = s;
                }
        }
    };

    const int nst = (C + ICB - 1) / ICB;
    stage_copy(0, 0, C < ICB ? C : ICB);
    cp_commit();
    for (int s = 0; s < nst; s++) {
        int buf = s & 1;
        cp_wait0();
        __syncthreads();
        int icn = (s + 1) * ICB;
        if (icn < C) {
            int cn = C - icn; if (cn > ICB) cn = ICB;
            stage_copy(buf ^ 1, icn, cn);
        }
        cp_commit();
        int cnt = C - s * ICB; if (cnt > ICB) cnt = ICB;
        for (int j = 0; j < cnt; j++) compute_ch(buf, j);
    }

    float bv[8];
#pragma unroll
    for (int o = 0; o < 8; o++) bv[o] = bias[oc0 + g * 8 + o];
    unsigned short* bo = bout + (size_t)b * H * W * 2 * OC;
#pragma unroll
    for (int dy = 0; dy < 2; dy++)
#pragma unroll
        for (int dx = 0; dx < 4; dx++) {
            int y = y0 + 2 * ty + dy, x = x0 + 4 * tx + dx;
            float v[8];
            unsigned short h[8], l[8];
#pragma unroll
            for (int o = 0; o < 8; o++) {
                v[o] = activate(acc[o][dy][dx] + bv[o], act);
                split_bf16(v[o], h[o], l[o]);
            }
            unsigned short* bb = bo + ((size_t)y * W + x) * 2 * OC + oc0 + g * 8;
            uint4 H4, L4;
            H4.x = pack_us(h[0], h[1]); H4.y = pack_us(h[2], h[3]);
            H4.z = pack_us(h[4], h[5]); H4.w = pack_us(h[6], h[7]);
            L4.x = pack_us(l[0], l[1]); L4.y = pack_us(l[2], l[3]);
            L4.z = pack_us(l[4], l[5]); L4.w = pack_us(l[6], l[7]);
            *(uint4*)bb = H4;
            *(uint4*)(bb + OC) = L4;
        }
}

// ---------------- keypoint bottleneck ----------------
__global__ void bn_stats(const float* __restrict__ R, float* __restrict__ S,
                         float* __restrict__ Sh, float* __restrict__ Sw)
{
    int bk = blockIdx.x;
    int t = threadIdx.x;
    float v = R[(size_t)bk * 256 + t];
    float a = v;
    float bsum = v * (float)(t >> 4);
    float c = v * (float)(t & 15);
#pragma unroll
    for (int off = 16; off > 0; off >>= 1) {
        a += __shfl_down_sync(0xffffffffu, a, off);
        bsum += __shfl_down_sync(0xffffffffu, bsum, off);
        c += __shfl_down_sync(0xffffffffu, c, off);
    }
    __shared__ float sa[8], sb[8], sc[8];
    int wid = t >> 5;
    if ((t & 31) == 0) { sa[wid] = a; sb[wid] = bsum; sc[wid] = c; }
    __syncthreads();
    if (t == 0) {
        float ta = 0.f, tb = 0.f, tc = 0.f;
        for (int i = 0; i < 8; i++) { ta += sa[i]; tb += sb[i]; tc += sc[i]; }
        S[bk] = ta; Sh[bk] = tb; Sw[bk] = tc;
    }
}

// maps -> std bf16 planes [px][2][128]
__global__ void bn_maps(const float* __restrict__ S, const float* __restrict__ Sh,
                        const float* __restrict__ Sw, unsigned short* __restrict__ bout)
{
    int b = blockIdx.x;
    int k = threadIdx.x;     // 128 channels
    float s = S[b * 128 + k];
    float denom = S[b * 128 + 127];
    float mu = s * (1.f / 256.f);
    float inv = 1.f / denom;
    float c0 = Sh[b * 128 + k] * inv;
    float c1 = Sw[b * 128 + k] * inv;
    unsigned short* bo = bout + (size_t)b * 256 * 256;
    for (int sp = 0; sp < 256; sp++) {
        float dh = (float)(sp >> 4) - c0;
        float dw = (float)(sp & 15) - c1;
        float v = mu * expf(-0.5f * (dh * dh + dw * dw));
        unsigned short h, l;
        split_bf16(v, h, l);
        bo[sp * 256 + k] = h;
        bo[sp * 256 + 128 + k] = l;
    }
}

// ---------------- launch ----------------
extern "C" void kernel_launch(void* const* d_in, const int* in_sizes, int n_in,
                              void* d_out, int out_size)
{
    (void)in_sizes; (void)n_in; (void)out_size;
    const float* x = (const float*)d_in[0];
    const float* ew[7]; const float* eb[7];
    for (int j = 0; j < 7; j++) {
        ew[j] = (const float*)d_in[1 + 2 * j];
        eb[j] = (const float*)d_in[2 + 2 * j];
    }
    const float* dw[6]; const float* db[6];
    for (int j = 0; j < 6; j++) {
        dw[j] = (const float*)d_in[15 + 2 * j];
        db[j] = (const float*)d_in[16 + 2 * j];
    }
    float* out = (float*)d_out;

    float *F1, *S, *Sh, *Sw;
    unsigned short *B0, *B1;
    uint4 *wprep, *wprep2, *wprep3;
    cudaGetSymbolAddress((void**)&F1, g_f1);
    cudaGetSymbolAddress((void**)&B0, g_b0);
    cudaGetSymbolAddress((void**)&B1, g_b1);
    cudaGetSymbolAddress((void**)&wprep, g_wprep);
    cudaGetSymbolAddress((void**)&wprep2, g_wprep2);
    cudaGetSymbolAddress((void**)&wprep3, g_wprep3);
    cudaGetSymbolAddress((void**)&S, g_S);
    cudaGetSymbolAddress((void**)&Sh, g_Sh);
    cudaGetSymbolAddress((void**)&Sw, g_Sw);

    static bool attr_set = false;
    if (!attr_set) {
        cudaFuncSetAttribute(conv_mma_s1<4>, cudaFuncAttributeMaxDynamicSharedMemorySize, MMA_SMEM);
        cudaFuncSetAttribute(conv_mma_s1<2>, cudaFuncAttributeMaxDynamicSharedMemorySize, MMA_SMEM);
        cudaFuncSetAttribute(conv_mma_s2c<4>, cudaFuncAttributeMaxDynamicSharedMemorySize, MMA_SMEM2);
        cudaFuncSetAttribute(conv_mma_s2c<2>, cudaFuncAttributeMaxDynamicSharedMemorySize, MMA_SMEM2);
        cudaFuncSetAttribute(conv_mma_t2c<4>, cudaFuncAttributeMaxDynamicSharedMemorySize, MMA_SMEM2);
        attr_set = true;
    }

    const int B = 32;
    const int OFF_E1 = 0, OFF_E3 = 2304, OFF_E5 = 11520;
    const int OFF_D1 = 48384, OFF_D3 = 57600, OFF_D5 = 59904;
    const int OFF2_E2 = 0, OFF2_E4 = 8192, OFF2_E6 = 40960;
    const int OFF3_D0 = 0, OFF3_D2 = 32768, OFF3_D4 = 40960;

    // weight preps
    prep_many<<<dim3(144, 3, 1), 256>>>(ew[1], ew[3], ew[5], wprep,
                                        OFF_E1, OFF_E3, OFF_E5, 32, 32, 64, 64, 128, 128);
    prep_many<<<dim3(36, 3, 1), 256>>>(dw[1], dw[3], dw[5], wprep,
                                       OFF_D1, OFF_D3, OFF_D5, 64, 64, 32, 32, 16, 16);
    prep_s2c<<<dim3(256, 3, 1), 256>>>(ew[2], ew[4], ew[6], wprep2,
                                       OFF2_E2, OFF2_E4, OFF2_E6,
                                       32, 64, 64, 128, 128, 128);
    prep_t2c<<<dim3(128, 3, 1), 256>>>(dw[0], dw[2], dw[4], wprep3,
                                       OFF3_D0, OFF3_D2, OFF3_D4,
                                       128, 64, 64, 32, 32, 16);

    // ---- encoder ----
    conv_e0<<<dim3(32, 1, B), 256>>>(x, ew[0], eb[0], B0, 3, 32, 128, 128, 0);
    conv_mma_s1<4><<<dim3(64, 1, B), 256, MMA_SMEM>>>(B0, wprep + OFF_E1, eb[1],
                                                      nullptr, B1, 32, 32, 128, 128, 0, 1);
    conv_mma_s2c<4><<<dim3(16, 2, B), 256, MMA_SMEM2>>>(B1, wprep2 + OFF2_E2, eb[2],
                                                        nullptr, B0, 32, 64, 64, 64, 1, 1);
    conv_mma_s1<4><<<dim3(16, 2, B), 256, MMA_SMEM>>>(B0, wprep + OFF_E3, eb[3],
                                                      nullptr, B1, 64, 64, 64, 64, 1, 1);
    conv_mma_s2c<4><<<dim3(4, 4, B), 256, MMA_SMEM2>>>(B1, wprep2 + OFF2_E4, eb[4],
                                                       nullptr, B0, 64, 128, 32, 32, 1, 1);
    conv_mma_s1<4><<<dim3(4, 4, B), 256, MMA_SMEM>>>(B0, wprep + OFF_E5, eb[5],
                                                     nullptr, B1, 128, 128, 32, 32, 1, 1);
    conv_mma_s2c<2><<<dim3(1, 8, B), 256, MMA_SMEM2>>>(B1, wprep2 + OFF2_E6, eb[6],
                                                       F1, nullptr, 128, 128, 16, 16, 3, 0);
    // ---- keypoint bottleneck ----
    bn_stats<<<4096, 256>>>(F1, S, Sh, Sw);
    bn_maps<<<32, 128>>>(S, Sh, Sw, B0);       // -> std planes, 16x16, C=128
    // ---- decoder ----
    conv_mma_t2c<4><<<dim3(1, 8, B), 256, MMA_SMEM2>>>(B0, wprep3 + OFF3_D0, db[0],
                                                       B1, 128, 64, 16, 16);
    conv_mma_s1<4><<<dim3(4, 2, B), 256, MMA_SMEM>>>(B1, wprep + OFF_D1, db[1],
                                                     nullptr, B0, 64, 64, 32, 32, 2, 1);
    conv_mma_t2c<4><<<dim3(4, 4, B), 256, MMA_SMEM2>>>(B0, wprep3 + OFF3_D2, db[2],
                                                       B1, 64, 32, 32, 32);
    conv_mma_s1<4><<<dim3(16, 1, B), 256, MMA_SMEM>>>(B1, wprep + OFF_D3, db[3],
                                                      nullptr, B0, 32, 32, 64, 64, 2, 1);
    conv_mma_t2c<4><<<dim3(16, 2, B), 256, MMA_SMEM2>>>(B0, wprep3 + OFF3_D4, db[4],
                                                        B1, 32, 16, 64, 64);
    conv_mma_s1<2><<<dim3(64, 1, B), 256, MMA_SMEM>>>(B1, wprep + OFF_D5, db[5],
                                                      out, nullptr, 16, 16, 128, 128, 2, 0);
}

// round 14
// speedup vs baseline: 2.2253x; 1.0796x over previous
#include <cuda_runtime.h>
#include <cuda_bf16.h>
#include <math.h>

// ---------------- scratch ----------------
__device__ float g_f1[32u * 32 * 128 * 128];              // fp32 NCHW (e6 out)
__device__ unsigned short g_b0[33554432];                 // bf16 std planes ping
__device__ unsigned short g_b1[33554432];                 // bf16 std planes pong
__device__ uint4 g_wprep[60480];                          // s1 mma weights
__device__ uint4 g_wprep2[106496];                        // s2c mma weights
__device__ uint4 g_wprep3[43008];                         // t2c mma weights
__device__ float g_S[4096];
__device__ float g_Sh[4096];
__device__ float g_Sw[4096];

__device__ __forceinline__ float activate(float v, int act) {
    switch (act) {
        case 1: return v > 0.f ? v : 0.2f * v;
        case 2: return v > 0.f ? v : 0.f;
        case 3: return fmaxf(v, 0.f) + log1pf(expf(-fabsf(v)));
        default: return v;
    }
}

__device__ __forceinline__ void split_bf16(float x, unsigned short& h, unsigned short& l) {
    h = __bfloat16_as_ushort(__float2bfloat16(x));
    float hf = __uint_as_float((unsigned)h << 16);
    l = __bfloat16_as_ushort(__float2bfloat16(x - hf));
}
__device__ __forceinline__ unsigned pack_us(unsigned short a, unsigned short b) {
    return ((unsigned)b << 16) | (unsigned)a;
}
__device__ __forceinline__ unsigned pack2_bf16(float e_lo, float e_hi) {
    return ((unsigned)__bfloat16_as_ushort(__float2bfloat16(e_hi)) << 16)
         | (unsigned)__bfloat16_as_ushort(__float2bfloat16(e_lo));
}

__device__ __forceinline__ void cp_async4(void* sdst, const void* gsrc, bool pred) {
    unsigned saddr = (unsigned)__cvta_generic_to_shared(sdst);
    int sz = pred ? 4 : 0;
    asm volatile("cp.async.ca.shared.global [%0], [%1], 4, %2;\n"
                 :: "r"(saddr), "l"(gsrc), "r"(sz));
}
__device__ __forceinline__ void cp_async16(void* sdst, const void* gsrc, bool pred) {
    unsigned saddr = (unsigned)__cvta_generic_to_shared(sdst);
    int sz = pred ? 16 : 0;
    asm volatile("cp.async.cg.shared.global [%0], [%1], 16, %2;\n"
                 :: "r"(saddr), "l"(gsrc), "r"(sz));
}
__device__ __forceinline__ void cp_commit() { asm volatile("cp.async.commit_group;\n"); }
__device__ __forceinline__ void cp_wait0() { asm volatile("cp.async.wait_group 0;\n"); }

__device__ __forceinline__ void mma16816(float* d, const unsigned* a, unsigned b0, unsigned b1) {
    asm volatile("mma.sync.aligned.m16n8k16.row.col.f32.bf16.bf16.f32 "
                 "{%0,%1,%2,%3},{%4,%5,%6,%7},{%8,%9},{%0,%1,%2,%3};"
                 : "+f"(d[0]), "+f"(d[1]), "+f"(d[2]), "+f"(d[3])
                 : "r"(a[0]), "r"(a[1]), "r"(a[2]), "r"(a[3]), "r"(b0), "r"(b1));
}

// =====================================================================
// s1 weight prep (3 layers/launch)
// =====================================================================
__global__ void prep_many(const float* __restrict__ w0, const float* __restrict__ w1,
                          const float* __restrict__ w2, uint4* __restrict__ dstb,
                          int off0, int off1, int off2,
                          int C0, int OC0, int C1, int OC1, int C2, int OC2)
{
    int layer = blockIdx.y;
    const float* w = layer == 0 ? w0 : layer == 1 ? w1 : w2;
    uint4* dst = dstb + (layer == 0 ? off0 : layer == 1 ? off1 : off2);
    int C = layer == 0 ? C0 : layer == 1 ? C1 : C2;
    int OC = layer == 0 ? OC0 : layer == 1 ? OC1 : OC2;
    int OCg = OC >> 3;
    int total = (C >> 4) * 9 * OCg * 32;
    int idx = blockIdx.x * 256 + threadIdx.x;
    if (idx >= total) return;
    int l = idx & 31;
    int q = idx >> 5;
    int og = q % OCg; q /= OCg;
    int t = q % 9;
    int kc = q / 9;
    int tg = l & 3, gg = l >> 2;
    int n = og * 8 + gg;
    float h[4], lo[4];
#pragma unroll
    for (int kk = 0; kk < 4; kk++) {
        int k = (kk < 2) ? (2 * tg + kk) : (2 * tg + 8 + (kk - 2));
        int ic = (kc << 4) + k;
        float e = w[((size_t)n * C + ic) * 9 + t];
        unsigned hb = (unsigned)__bfloat16_as_ushort(__float2bfloat16(e)) << 16;
        h[kk] = __uint_as_float(hb);
        lo[kk] = e - h[kk];
    }
    uint4 r;
    r.x = pack2_bf16(h[0], h[1]);
    r.y = pack2_bf16(h[2], h[3]);
    r.z = pack2_bf16(lo[0], lo[1]);
    r.w = pack2_bf16(lo[2], lo[3]);
    dst[idx] = r;
}

// =====================================================================
// s2c weight prep: stride-2 3x3 -> 2x2 over 4C phase channels (q*C+c).
// =====================================================================
__global__ void prep_s2c(const float* __restrict__ w0, const float* __restrict__ w1,
                         const float* __restrict__ w2, uint4* __restrict__ dstb,
                         int off0, int off1, int off2,
                         int C0, int OC0, int C1, int OC1, int C2, int OC2)
{
    int layer = blockIdx.y;
    const float* w = layer == 0 ? w0 : layer == 1 ? w1 : w2;
    uint4* dst = dstb + (layer == 0 ? off0 : layer == 1 ? off1 : off2);
    int C = layer == 0 ? C0 : layer == 1 ? C1 : C2;
    int OC = layer == 0 ? OC0 : layer == 1 ? OC1 : OC2;
    int OCg = OC >> 3;
    int KC = (4 * C) >> 4;
    int total = KC * 4 * OCg * 32;
    int idx = blockIdx.x * 256 + threadIdx.x;
    if (idx >= total) return;
    int l = idx & 31;
    int q = idx >> 5;
    int og = q % OCg; q /= OCg;
    int t = q % 4;
    int kc = q / 4;
    int dy = t >> 1, dx = t & 1;
    int tg = l & 3, gg = l >> 2;
    int n = og * 8 + gg;
    float h[4], lo[4];
#pragma unroll
    for (int kk = 0; kk < 4; kk++) {
        int k = (kk < 2) ? (2 * tg + kk) : (2 * tg + 8 + (kk - 2));
        int ch = (kc << 4) + k;
        int qph = ch / C, c = ch - qph * C;
        int a = qph >> 1, bph = qph & 1;
        int ky = 2 * dy + a, kx = 2 * dx + bph;
        float e = (ky < 3 && kx < 3) ? w[((size_t)n * C + c) * 9 + ky * 3 + kx] : 0.f;
        unsigned hb = (unsigned)__bfloat16_as_ushort(__float2bfloat16(e)) << 16;
        h[kk] = __uint_as_float(hb);
        lo[kk] = e - h[kk];
    }
    uint4 r;
    r.x = pack2_bf16(h[0], h[1]);
    r.y = pack2_bf16(h[2], h[3]);
    r.z = pack2_bf16(lo[0], lo[1]);
    r.w = pack2_bf16(lo[2], lo[3]);
    dst[idx] = r;
}

// =====================================================================
// t2c weight prep: transposed stride-2 3x3 -> 2x2 conv over input grid,
// N = 4*OC phase channels: n = q*OC + oc, q = 2a+b.
// =====================================================================
__global__ void prep_t2c(const float* __restrict__ w0, const float* __restrict__ w1,
                         const float* __restrict__ w2, uint4* __restrict__ dstb,
                         int off0, int off1, int off2,
                         int C0, int OC0, int C1, int OC1, int C2, int OC2)
{
    int layer = blockIdx.y;
    const float* w = layer == 0 ? w0 : layer == 1 ? w1 : w2;
    uint4* dst = dstb + (layer == 0 ? off0 : layer == 1 ? off1 : off2);
    int C = layer == 0 ? C0 : layer == 1 ? C1 : C2;
    int OC = layer == 0 ? OC0 : layer == 1 ? OC1 : OC2;
    int NN = 4 * OC;
    int OCgN = NN >> 3;
    int KC = C >> 4;
    int total = KC * 4 * OCgN * 32;
    int idx = blockIdx.x * 256 + threadIdx.x;
    if (idx >= total) return;
    int l = idx & 31;
    int q = idx >> 5;
    int og = q % OCgN; q /= OCgN;
    int t = q % 4;
    int kc = q / 4;
    int u = t >> 1, v = t & 1;
    int tg = l & 3, gg = l >> 2;
    int n = og * 8 + gg;
    int qph = n / OC, oc = n - qph * OC;
    int a = qph >> 1, bph = qph & 1;
    int ky = 2 * u - a, kx = 2 * v - bph;
    float h[4], lo[4];
#pragma unroll
    for (int kk = 0; kk < 4; kk++) {
        int k = (kk < 2) ? (2 * tg + kk) : (2 * tg + 8 + (kk - 2));
        int c = (kc << 4) + k;
        float e = (ky >= 0 && kx >= 0) ? w[((size_t)oc * C + c) * 9 + ky * 3 + kx] : 0.f;
        unsigned hb = (unsigned)__bfloat16_as_ushort(__float2bfloat16(e)) << 16;
        h[kk] = __uint_as_float(hb);
        lo[kk] = e - h[kk];
    }
    uint4 r;
    r.x = pack2_bf16(h[0], h[1]);
    r.y = pack2_bf16(h[2], h[3]);
    r.z = pack2_bf16(lo[0], lo[1]);
    r.w = pack2_bf16(lo[2], lo[3]);
    dst[idx] = r;
}

// =====================================================================
// tensor-core stride-1 3x3 SAME conv (bf16x3 split). Templated NF.
// =====================================================================
#define SINW (324 * 12)
#define MMA_SW (9 * 4 * 32)
#define MMA_SMEM (2 * 2 * SINW * 4 + 2 * MMA_SW * 16)

template <int NF>
__global__ void __launch_bounds__(256, 2) conv_mma_s1(
    const unsigned short* __restrict__ in, const uint4* __restrict__ wp,
    const float* __restrict__ bias, float* __restrict__ fout,
    unsigned short* __restrict__ bout, int C, int OC, int H, int W, int act, int mode)
{
    const int KC = C >> 4;
    const int tilesX = W >> 4;
    const int x0 = (blockIdx.x % tilesX) << 4;
    const int y0 = (blockIdx.x / tilesX) << 4;
    const int oc0 = blockIdx.y * (NF * 8);
    const int b = blockIdx.z;
    const int OCg = OC >> 3;

    extern __shared__ __align__(16) unsigned char dsm[];
    unsigned* s_hi = (unsigned*)dsm;
    unsigned* s_lo = s_hi + 2 * SINW;
    uint4* s_w = (uint4*)(dsm + 4 * 4 * SINW);

    const unsigned short* inb = in + (size_t)b * H * W * 2 * C;
    const int tid = threadIdx.x, lane = tid & 31, wid = tid >> 5;
    const int g = lane >> 2, tg = lane & 3;

    float d[2][NF][4];
#pragma unroll
    for (int i = 0; i < 2; i++)
#pragma unroll
        for (int j = 0; j < NF; j++)
#pragma unroll
            for (int r = 0; r < 4; r++) d[i][j][r] = 0.f;

    auto stage = [&](int buf, int kc) {
        unsigned* hi = s_hi + buf * SINW;
        unsigned* lo = s_lo + buf * SINW;
        for (int i = tid; i < 648; i += 256) {
            int sp = i >> 1, q = i & 1;
            int r = sp / 18, c = sp - r * 18;
            int iy = y0 - 1 + r, ix = x0 - 1 + c;
            bool p = (unsigned)iy < (unsigned)H && (unsigned)ix < (unsigned)W;
            const unsigned short* src = inb + ((size_t)iy * W + ix) * 2 * C + (kc << 4) + (q << 3);
            cp_async16(hi + sp * 12 + q * 4, src, p);
            cp_async16(lo + sp * 12 + q * 4, src + C, p);
        }
        uint4* sw = s_w + buf * MMA_SW;
        const uint4* wsrc = wp + (size_t)kc * 9 * OCg * 32;
        const int tot = 9 * NF * 32;
        for (int i = tid; i < tot; i += 256) {
            int l = i & 31;
            int q = i >> 5;
            int ogl = q % NF;
            int t = q / NF;
            cp_async16(sw + (t * 4 + ogl) * 32 + l,
                       wsrc + ((size_t)t * OCg + (oc0 >> 3) + ogl) * 32 + l, true);
        }
    };

    auto compute = [&](int buf) {
        unsigned* hi = s_hi + buf * SINW;
        unsigned* lo = s_lo + buf * SINW;
        uint4* sw = s_w + buf * MMA_SW;
#pragma unroll
        for (int t = 0; t < 9; t++) {
            const int dy = t / 3, dx = t - 3 * (t / 3);
            unsigned ah[2][4], al[2][4];
#pragma unroll
            for (int i = 0; i < 2; i++) {
                int sp0 = (2 * wid + i + dy) * 18 + g + dx;
                const unsigned* h0 = hi + sp0 * 12;
                const unsigned* l0 = lo + sp0 * 12;
                ah[i][0] = h0[tg];       ah[i][1] = h0[96 + tg];
                ah[i][2] = h0[tg + 4];   ah[i][3] = h0[96 + tg + 4];
                al[i][0] = l0[tg];       al[i][1] = l0[96 + tg];
                al[i][2] = l0[tg + 4];   al[i][3] = l0[96 + tg + 4];
            }
#pragma unroll
            for (int j = 0; j < NF; j++) {
                uint4 bw = sw[(t * 4 + j) * 32 + lane];
#pragma unroll
                for (int i = 0; i < 2; i++) {
                    mma16816(d[i][j], ah[i], bw.x, bw.y);
                    mma16816(d[i][j], al[i], bw.x, bw.y);
                    mma16816(d[i][j], ah[i], bw.z, bw.w);
                }
            }
        }
    };

    stage(0, 0);
    cp_commit();
    for (int kc = 0; kc < KC; kc++) {
        int buf = kc & 1;
        cp_wait0();
        __syncthreads();
        if (kc + 1 < KC) stage(buf ^ 1, kc + 1);
        cp_commit();
        compute(buf);
    }

    if (mode == 0) {
#pragma unroll
        for (int i = 0; i < 2; i++) {
            int y = y0 + 2 * wid + i;
#pragma unroll
            for (int j = 0; j < NF; j++) {
                int oc = oc0 + 8 * j + 2 * tg;
                float b0 = bias[oc], b1 = bias[oc + 1];
                size_t base0 = (((size_t)b * OC + oc) * H + y) * W + x0;
                size_t base1 = base0 + (size_t)H * W;
                fout[base0 + g]     = activate(d[i][j][0] + b0, act);
                fout[base1 + g]     = activate(d[i][j][1] + b1, act);
                fout[base0 + g + 8] = activate(d[i][j][2] + b0, act);
                fout[base1 + g + 8] = activate(d[i][j][3] + b1, act);
            }
        }
    } else {
        unsigned short* bo = bout + (size_t)b * H * W * 2 * OC;
#pragma unroll
        for (int i = 0; i < 2; i++) {
            int y = y0 + 2 * wid + i;
#pragma unroll
            for (int j = 0; j < NF; j++) {
                int oc = oc0 + 8 * j + 2 * tg;
                float b0 = bias[oc], b1 = bias[oc + 1];
                float v0 = activate(d[i][j][0] + b0, act);
                float v1 = activate(d[i][j][1] + b1, act);
                float v2 = activate(d[i][j][2] + b0, act);
                float v3 = activate(d[i][j][3] + b1, act);
                size_t px0 = (size_t)y * W + x0 + g;
                size_t px1 = px0 + 8;
                unsigned short h0, l0, h1, l1;
                split_bf16(v0, h0, l0); split_bf16(v1, h1, l1);
                size_t a0 = px0 * 2 * OC + oc;
                *(unsigned*)(bo + a0) = pack_us(h0, h1);
                *(unsigned*)(bo + a0 + OC) = pack_us(l0, l1);
                split_bf16(v2, h0, l0); split_bf16(v3, h1, l1);
                size_t a1 = px1 * 2 * OC + oc;
                *(unsigned*)(bo + a1) = pack_us(h0, h1);
                *(unsigned*)(bo + a1 + OC) = pack_us(l0, l1);
            }
        }
    }
}

// =====================================================================
// tensor-core stride-2 conv as 2x2 s2c over CC=4C channels. Templated NF.
// Tap skip: weight is zero when (dy==1 && a) or (dx==1 && b) for the
// current k-chunk's phase (a,b) -> skip those MMAs.
// =====================================================================
#define SINW2 (289 * 12)
#define MMA_SW2 (4 * 4 * 32)
#define MMA_SMEM2 (2 * 2 * SINW2 * 4 + 2 * MMA_SW2 * 16)

template <int NF>
__global__ void __launch_bounds__(256, 2) conv_mma_s2c(
    const unsigned short* __restrict__ in, const uint4* __restrict__ wp,
    const float* __restrict__ bias, float* __restrict__ fout,
    unsigned short* __restrict__ bout, int C, int OC, int Hout, int Wout,
    int act, int mode)
{
    const int CC = 4 * C;
    const int KC = CC >> 4;
    const int Hin = Hout * 2, Win = Wout * 2;
    const int tilesX = Wout >> 4;
    const int x0 = (blockIdx.x % tilesX) << 4;
    const int y0 = (blockIdx.x / tilesX) << 4;
    const int oc0 = blockIdx.y * (NF * 8);
    const int b = blockIdx.z;
    const int OCg = OC >> 3;

    extern __shared__ __align__(16) unsigned char dsm[];
    unsigned* s_hi = (unsigned*)dsm;
    unsigned* s_lo = s_hi + 2 * SINW2;
    uint4* s_w = (uint4*)(dsm + 4 * 4 * SINW2);

    const unsigned short* inb = in + (size_t)b * Hin * Win * 2 * C;
    const int tid = threadIdx.x, lane = tid & 31, wid = tid >> 5;
    const int g = lane >> 2, tg = lane & 3;

    float d[2][NF][4];
#pragma unroll
    for (int i = 0; i < 2; i++)
#pragma unroll
        for (int j = 0; j < NF; j++)
#pragma unroll
            for (int r = 0; r < 4; r++) d[i][j][r] = 0.f;

    auto stage = [&](int buf, int kc) {
        unsigned* hi = s_hi + buf * SINW2;
        unsigned* lo = s_lo + buf * SINW2;
        int qph = (kc << 4) / C;
        int c0 = (kc << 4) - qph * C;
        int pa = qph >> 1, pb = qph & 1;
        for (int i = tid; i < 578; i += 256) {
            int sp = i >> 1, q = i & 1;
            int r = sp / 17, c = sp - r * 17;
            int sy = 2 * (y0 + r) + pa, sx = 2 * (x0 + c) + pb;
            bool p = sy < Hin && sx < Win;
            const unsigned short* src = inb + ((size_t)sy * Win + sx) * 2 * C + c0 + (q << 3);
            cp_async16(hi + sp * 12 + q * 4, src, p);
            cp_async16(lo + sp * 12 + q * 4, src + C, p);
        }
        uint4* sw = s_w + buf * MMA_SW2;
        const uint4* wsrc = wp + (size_t)kc * 4 * OCg * 32;
        const int tot = 4 * NF * 32;
        for (int i = tid; i < tot; i += 256) {
            int l = i & 31;
            int q = i >> 5;
            int ogl = q % NF;
            int t = q / NF;
            cp_async16(sw + (t * 4 + ogl) * 32 + l,
                       wsrc + ((size_t)t * OCg + (oc0 >> 3) + ogl) * 32 + l, true);
        }
    };

    auto compute = [&](int buf, int pa, int pb) {
        unsigned* hi = s_hi + buf * SINW2;
        unsigned* lo = s_lo + buf * SINW2;
        uint4* sw = s_w + buf * MMA_SW2;
#pragma unroll
        for (int t = 0; t < 4; t++) {
            const int dy = t >> 1, dx = t & 1;
            if ((dy && pa) || (dx && pb)) continue;   // zero-weight tap for this phase
            unsigned ah[2][4], al[2][4];
#pragma unroll
            for (int i = 0; i < 2; i++) {
                int sp0 = (2 * wid + i + dy) * 17 + g + dx;
                const unsigned* h0 = hi + sp0 * 12;
                const unsigned* l0 = lo + sp0 * 12;
                ah[i][0] = h0[tg];       ah[i][1] = h0[96 + tg];
                ah[i][2] = h0[tg + 4];   ah[i][3] = h0[96 + tg + 4];
                al[i][0] = l0[tg];       al[i][1] = l0[96 + tg];
                al[i][2] = l0[tg + 4];   al[i][3] = l0[96 + tg + 4];
            }
#pragma unroll
            for (int j = 0; j < NF; j++) {
                uint4 bw = sw[(t * 4 + j) * 32 + lane];
#pragma unroll
                for (int i = 0; i < 2; i++) {
                    mma16816(d[i][j], ah[i], bw.x, bw.y);
                    mma16816(d[i][j], al[i], bw.x, bw.y);
                    mma16816(d[i][j], ah[i], bw.z, bw.w);
                }
            }
        }
    };

    stage(0, 0);
    cp_commit();
    for (int kc = 0; kc < KC; kc++) {
        int buf = kc & 1;
        cp_wait0();
        __syncthreads();
        if (kc + 1 < KC) stage(buf ^ 1, kc + 1);
        cp_commit();
        int qc = (kc << 4) / C;
        compute(buf, qc >> 1, qc & 1);
    }

    if (mode == 0) {
#pragma unroll
        for (int i = 0; i < 2; i++) {
            int y = y0 + 2 * wid + i;
#pragma unroll
            for (int j = 0; j < NF; j++) {
                int oc = oc0 + 8 * j + 2 * tg;
                float b0 = bias[oc], b1 = bias[oc + 1];
                size_t base0 = (((size_t)b * OC + oc) * Hout + y) * Wout + x0;
                size_t base1 = base0 + (size_t)Hout * Wout;
                fout[base0 + g]     = activate(d[i][j][0] + b0, act);
                fout[base1 + g]     = activate(d[i][j][1] + b1, act);
                fout[base0 + g + 8] = activate(d[i][j][2] + b0, act);
                fout[base1 + g + 8] = activate(d[i][j][3] + b1, act);
            }
        }
    } else {
        unsigned short* bo = bout + (size_t)b * Hout * Wout * 2 * OC;
#pragma unroll
        for (int i = 0; i < 2; i++) {
            int y = y0 + 2 * wid + i;
#pragma unroll
            for (int j = 0; j < NF; j++) {
                int oc = oc0 + 8 * j + 2 * tg;
                float b0 = bias[oc], b1 = bias[oc + 1];
                float v0 = activate(d[i][j][0] + b0, act);
                float v1 = activate(d[i][j][1] + b1, act);
                float v2 = activate(d[i][j][2] + b0, act);
                float v3 = activate(d[i][j][3] + b1, act);
                size_t px0 = (size_t)y * Wout + x0 + g;
                size_t px1 = px0 + 8;
                unsigned short h0, l0, h1, l1;
                split_bf16(v0, h0, l0); split_bf16(v1, h1, l1);
                size_t a0 = px0 * 2 * OC + oc;
                *(unsigned*)(bo + a0) = pack_us(h0, h1);
                *(unsigned*)(bo + a0 + OC) = pack_us(l0, l1);
                split_bf16(v2, h0, l0); split_bf16(v3, h1, l1);
                size_t a1 = px1 * 2 * OC + oc;
                *(unsigned*)(bo + a1) = pack_us(h0, h1);
                *(unsigned*)(bo + a1 + OC) = pack_us(l0, l1);
            }
        }
    }
}

// =====================================================================
// tensor-core transposed conv (t2c): 2x2 conv over input grid, N=4*OC
// phase channels. Tap skip: weight zero when (dy==0 && a_j) or
// (dx==0 && b_j) for fragment j's phase. relu.
// =====================================================================
template <int NF>
__global__ void __launch_bounds__(256, 2) conv_mma_t2c(
    const unsigned short* __restrict__ in, const uint4* __restrict__ wp,
    const float* __restrict__ bias, unsigned short* __restrict__ bout,
    int C, int OC, int Hin, int Win)
{
    const int KC = C >> 4;
    const int NN = 4 * OC;
    const int OCgN = NN >> 3;
    const int Wout = Win * 2;
    const int tilesX = Win >> 4;
    const int x0 = (blockIdx.x % tilesX) << 4;
    const int y0 = (blockIdx.x / tilesX) << 4;
    const int oc0 = blockIdx.y * (NF * 8);
    const int b = blockIdx.z;

    extern __shared__ __align__(16) unsigned char dsm[];
    unsigned* s_hi = (unsigned*)dsm;
    unsigned* s_lo = s_hi + 2 * SINW2;
    uint4* s_w = (uint4*)(dsm + 4 * 4 * SINW2);

    const unsigned short* inb = in + (size_t)b * Hin * Win * 2 * C;
    const int tid = threadIdx.x, lane = tid & 31, wid = tid >> 5;
    const int g = lane >> 2, tg = lane & 3;

    // per-fragment phase (8 | OC so each j is single-phase)
    int aj[NF], bj[NF];
#pragma unroll
    for (int j = 0; j < NF; j++) {
        int qj = (oc0 + 8 * j) / OC;
        aj[j] = qj >> 1;
        bj[j] = qj & 1;
    }

    float d[2][NF][4];
#pragma unroll
    for (int i = 0; i < 2; i++)
#pragma unroll
        for (int j = 0; j < NF; j++)
#pragma unroll
            for (int r = 0; r < 4; r++) d[i][j][r] = 0.f;

    auto stage = [&](int buf, int kc) {
        unsigned* hi = s_hi + buf * SINW2;
        unsigned* lo = s_lo + buf * SINW2;
        for (int i = tid; i < 578; i += 256) {
            int sp = i >> 1, q = i & 1;
            int r = sp / 17, c = sp - r * 17;
            int iy = y0 - 1 + r, ix = x0 - 1 + c;
            bool p = (unsigned)iy < (unsigned)Hin && (unsigned)ix < (unsigned)Win;
            const unsigned short* src = inb + ((size_t)iy * Win + ix) * 2 * C + (kc << 4) + (q << 3);
            cp_async16(hi + sp * 12 + q * 4, src, p);
            cp_async16(lo + sp * 12 + q * 4, src + C, p);
        }
        uint4* sw = s_w + buf * MMA_SW2;
        const uint4* wsrc = wp + (size_t)kc * 4 * OCgN * 32;
        const int tot = 4 * NF * 32;
        for (int i = tid; i < tot; i += 256) {
            int l = i & 31;
            int q = i >> 5;
            int ogl = q % NF;
            int t = q / NF;
            cp_async16(sw + (t * 4 + ogl) * 32 + l,
                       wsrc + ((size_t)t * OCgN + (oc0 >> 3) + ogl) * 32 + l, true);
        }
    };

    auto compute = [&](int buf) {
        unsigned* hi = s_hi + buf * SINW2;
        unsigned* lo = s_lo + buf * SINW2;
        uint4* sw = s_w + buf * MMA_SW2;
#pragma unroll
        for (int t = 0; t < 4; t++) {
            const int dy = t >> 1, dx = t & 1;
            unsigned ah[2][4], al[2][4];
#pragma unroll
            for (int i = 0; i < 2; i++) {
                int sp0 = (2 * wid + i + dy) * 17 + g + dx;
                const unsigned* h0 = hi + sp0 * 12;
                const unsigned* l0 = lo + sp0 * 12;
                ah[i][0] = h0[tg];       ah[i][1] = h0[96 + tg];
                ah[i][2] = h0[tg + 4];   ah[i][3] = h0[96 + tg + 4];
                al[i][0] = l0[tg];       al[i][1] = l0[96 + tg];
                al[i][2] = l0[tg + 4];   al[i][3] = l0[96 + tg + 4];
            }
#pragma unroll
            for (int j = 0; j < NF; j++) {
                if ((dy == 0 && aj[j]) || (dx == 0 && bj[j])) continue;  // zero tap
                uint4 bw = sw[(t * 4 + j) * 32 + lane];
#pragma unroll
                for (int i = 0; i < 2; i++) {
                    mma16816(d[i][j], ah[i], bw.x, bw.y);
                    mma16816(d[i][j], al[i], bw.x, bw.y);
                    mma16816(d[i][j], ah[i], bw.z, bw.w);
                }
            }
        }
    };

    stage(0, 0);
    cp_commit();
    for (int kc = 0; kc < KC; kc++) {
        int buf = kc & 1;
        cp_wait0();
        __syncthreads();
        if (kc + 1 < KC) stage(buf ^ 1, kc + 1);
        cp_commit();
        compute(buf);
    }

    // epilogue: input px row y0+2wid+i, cols x0+g / x0+g+8;
    unsigned short* bo2 = bout + (size_t)b * (2 * Hin) * Wout * 2 * OC;
#pragma unroll
    for (int i = 0; i < 2; i++) {
        int yin = y0 + 2 * wid + i;
#pragma unroll
        for (int j = 0; j < NF; j++) {
            int n0 = oc0 + 8 * j + 2 * tg;
            int q = n0 / OC;
            int oc = n0 - q * OC;
            int a = q >> 1, bph = q & 1;
            int oy = 2 * yin + a;
            float b0 = bias[oc], b1 = bias[oc + 1];
            float v0 = d[i][j][0] + b0; v0 = v0 > 0.f ? v0 : 0.f;
            float v1 = d[i][j][1] + b1; v1 = v1 > 0.f ? v1 : 0.f;
            float v2 = d[i][j][2] + b0; v2 = v2 > 0.f ? v2 : 0.f;
            float v3 = d[i][j][3] + b1; v3 = v3 > 0.f ? v3 : 0.f;
            size_t px0 = (size_t)oy * Wout + 2 * (x0 + g) + bph;
            size_t px1 = (size_t)oy * Wout + 2 * (x0 + g + 8) + bph;
            unsigned short h0, l0, h1, l1;
            split_bf16(v0, h0, l0); split_bf16(v1, h1, l1);
            size_t a0 = px0 * 2 * OC + oc;
            *(unsigned*)(bo2 + a0) = pack_us(h0, h1);
            *(unsigned*)(bo2 + a0 + OC) = pack_us(l0, l1);
            split_bf16(v2, h0, l0); split_bf16(v3, h1, l1);
            size_t a1 = px1 * 2 * OC + oc;
            *(unsigned*)(bo2 + a1) = pack_us(h0, h1);
            *(unsigned*)(bo2 + a1 + OC) = pack_us(l0, l1);
        }
    }
}

// =====================================================================
// e0: fp32 NCHW in (C=3) -> std bf16 planes.
// =====================================================================
__global__ void __launch_bounds__(256, 2) conv_e0(
    const float* __restrict__ in, const float* __restrict__ wgt,
    const float* __restrict__ bias, unsigned short* __restrict__ bout,
    int C, int OC, int H, int W, int act)
{
    constexpr int NT = 256;
    constexpr int ICB = 4;
    constexpr int SROW = 34;
    constexpr int SIN = 18 * SROW;

    const int tilesX = W >> 5;
    const int x0 = (blockIdx.x % tilesX) << 5;
    const int y0 = (blockIdx.x / tilesX) << 4;
    const int oc0 = blockIdx.y * 32;
    const int b = blockIdx.z;

    __shared__ __align__(16) float s_in[2][ICB][SIN];
    __shared__ __align__(16) float s_w[2][ICB][32 * 12];

    const int tid = threadIdx.x;
    const int g = tid >> 6;
    const int sp = tid & 63;
    const int ty = sp >> 3, tx = sp & 7;

    float acc[8][2][4];
#pragma unroll
    for (int o = 0; o < 8; o++)
#pragma unroll
        for (int dy = 0; dy < 2; dy++)
#pragma unroll
            for (int dx = 0; dx < 4; dx++) acc[o][dy][dx] = 0.f;

    const float* inb = in + (size_t)b * C * H * W;
    const float* wb = wgt + (size_t)oc0 * C * 9;

    auto stage_copy = [&](int buf, int ic0, int cnt) {
        const float* ins = inb + (size_t)ic0 * H * W;
        for (int i = tid; i < cnt * SIN; i += NT) {
            int ch = i / SIN, r2 = i - ch * SIN;
            int r = r2 / SROW, c2 = r2 - r * SROW;
            int iy = y0 - 1 + r, ix = x0 - 1 + c2;
            bool p = (unsigned)iy < (unsigned)H && (unsigned)ix < (unsigned)W;
            cp_async4(&s_in[buf][ch][r2], ins + (size_t)ch * H * W + (size_t)iy * W + ix, p);
        }
        for (int i = tid; i < cnt * 32 * 9; i += NT) {
            int ch = i / (32 * 9), r2 = i - ch * (32 * 9);
            int o = r2 / 9, j2 = r2 - o * 9;
            cp_async4(&s_w[buf][ch][o * 12 + j2],
                      wb + ((size_t)o * C + ic0 + ch) * 9 + j2, true);
        }
    };

    const int sbase = (2 * ty) * SROW + 4 * tx;

    auto compute_ch = [&](int buf, int ch) {
        float rr[4][6];
        const float* si = &s_in[buf][ch][sbase];
#pragma unroll
        for (int r = 0; r < 4; r++) {
            const float2* p = (const float2*)(si + r * SROW);
            float2 a = p[0], b2 = p[1], c2 = p[2];
            rr[r][0] = a.x; rr[r][1] = a.y; rr[r][2] = b2.x;
            rr[r][3] = b2.y; rr[r][4] = c2.x; rr[r][5] = c2.y;
        }
#pragma unroll
        for (int o = 0; o < 8; o++) {
            const float4* wp = (const float4*)&s_w[buf][ch][(g * 8 + o) * 12];
            float4 wa = wp[0];
            float4 wc = wp[1];
            float w8 = ((const float*)wp)[8];
#pragma unroll
            for (int dy = 0; dy < 2; dy++)
#pragma unroll
                for (int dx = 0; dx < 4; dx++) {
                    float s = acc[o][dy][dx];
                    s += wa.x * rr[dy + 0][dx + 0];
                    s += wa.y * rr[dy + 0][dx + 1];
                    s += wa.z * rr[dy + 0][dx + 2];
                    s += wa.w * rr[dy + 1][dx + 0];
                    s += wc.x * rr[dy + 1][dx + 1];
                    s += wc.y * rr[dy + 1][dx + 2];
                    s += wc.z * rr[dy + 2][dx + 0];
                    s += wc.w * rr[dy + 2][dx + 1];
                    s += w8   * rr[dy + 2][dx + 2];
                    acc[o][dy][dx] = s;
                }
        }
    };

    const int nst = (C + ICB - 1) / ICB;
    stage_copy(0, 0, C < ICB ? C : ICB);
    cp_commit();
    for (int s = 0; s < nst; s++) {
        int buf = s & 1;
        cp_wait0();
        __syncthreads();
        int icn = (s + 1) * ICB;
        if (icn < C) {
            int cn = C - icn; if (cn > ICB) cn = ICB;
            stage_copy(buf ^ 1, icn, cn);
        }
        cp_commit();
        int cnt = C - s * ICB; if (cnt > ICB) cnt = ICB;
        for (int j = 0; j < cnt; j++) compute_ch(buf, j);
    }

    float bv[8];
#pragma unroll
    for (int o = 0; o < 8; o++) bv[o] = bias[oc0 + g * 8 + o];
    unsigned short* bo = bout + (size_t)b * H * W * 2 * OC;
#pragma unroll
    for (int dy = 0; dy < 2; dy++)
#pragma unroll
        for (int dx = 0; dx < 4; dx++) {
            int y = y0 + 2 * ty + dy, x = x0 + 4 * tx + dx;
            float v[8];
            unsigned short h[8], l[8];
#pragma unroll
            for (int o = 0; o < 8; o++) {
                v[o] = activate(acc[o][dy][dx] + bv[o], act);
                split_bf16(v[o], h[o], l[o]);
            }
            unsigned short* bb = bo + ((size_t)y * W + x) * 2 * OC + oc0 + g * 8;
            uint4 H4, L4;
            H4.x = pack_us(h[0], h[1]); H4.y = pack_us(h[2], h[3]);
            H4.z = pack_us(h[4], h[5]); H4.w = pack_us(h[6], h[7]);
            L4.x = pack_us(l[0], l[1]); L4.y = pack_us(l[2], l[3]);
            L4.z = pack_us(l[4], l[5]); L4.w = pack_us(l[6], l[7]);
            *(uint4*)bb = H4;
            *(uint4*)(bb + OC) = L4;
        }
}

// ---------------- keypoint bottleneck ----------------
__global__ void bn_stats(const float* __restrict__ R, float* __restrict__ S,
                         float* __restrict__ Sh, float* __restrict__ Sw)
{
    int bk = blockIdx.x;
    int t = threadIdx.x;
    float v = R[(size_t)bk * 256 + t];
    float a = v;
    float bsum = v * (float)(t >> 4);
    float c = v * (float)(t & 15);
#pragma unroll
    for (int off = 16; off > 0; off >>= 1) {
        a += __shfl_down_sync(0xffffffffu, a, off);
        bsum += __shfl_down_sync(0xffffffffu, bsum, off);
        c += __shfl_down_sync(0xffffffffu, c, off);
    }
    __shared__ float sa[8], sb[8], sc[8];
    int wid = t >> 5;
    if ((t & 31) == 0) { sa[wid] = a; sb[wid] = bsum; sc[wid] = c; }
    __syncthreads();
    if (t == 0) {
        float ta = 0.f, tb = 0.f, tc = 0.f;
        for (int i = 0; i < 8; i++) { ta += sa[i]; tb += sb[i]; tc += sc[i]; }
        S[bk] = ta; Sh[bk] = tb; Sw[bk] = tc;
    }
}

// maps -> std bf16 planes [px][2][128]; grid (32, 16), block 256
__global__ void bn_maps(const float* __restrict__ S, const float* __restrict__ Sh,
                        const float* __restrict__ Sw, unsigned short* __restrict__ bout)
{
    int b = blockIdx.x;
    int spc = blockIdx.y;            // 16 sp per block
    int k = threadIdx.x & 127;
    int half = threadIdx.x >> 7;     // 0/1 -> 8 sp each
    float s = S[b * 128 + k];
    float denom = S[b * 128 + 127];
    float mu = s * (1.f / 256.f);
    float inv = 1.f / denom;
    float c0 = Sh[b * 128 + k] * inv;
    float c1 = Sw[b * 128 + k] * inv;
    unsigned short* bo = bout + (size_t)b * 256 * 256;
#pragma unroll
    for (int i = 0; i < 8; i++) {
        int sp = spc * 16 + half * 8 + i;
        float dh = (float)(sp >> 4) - c0;
        float dw = (float)(sp & 15) - c1;
        float v = mu * expf(-0.5f * (dh * dh + dw * dw));
        unsigned short h, l;
        split_bf16(v, h, l);
        bo[sp * 256 + k] = h;
        bo[sp * 256 + 128 + k] = l;
    }
}

// ---------------- launch ----------------
extern "C" void kernel_launch(void* const* d_in, const int* in_sizes, int n_in,
                              void* d_out, int out_size)
{
    (void)in_sizes; (void)n_in; (void)out_size;
    const float* x = (const float*)d_in[0];
    const float* ew[7]; const float* eb[7];
    for (int j = 0; j < 7; j++) {
        ew[j] = (const float*)d_in[1 + 2 * j];
        eb[j] = (const float*)d_in[2 + 2 * j];
    }
    const float* dw[6]; const float* db[6];
    for (int j = 0; j < 6; j++) {
        dw[j] = (const float*)d_in[15 + 2 * j];
        db[j] = (const float*)d_in[16 + 2 * j];
    }
    float* out = (float*)d_out;

    float *F1, *S, *Sh, *Sw;
    unsigned short *B0, *B1;
    uint4 *wprep, *wprep2, *wprep3;
    cudaGetSymbolAddress((void**)&F1, g_f1);
    cudaGetSymbolAddress((void**)&B0, g_b0);
    cudaGetSymbolAddress((void**)&B1, g_b1);
    cudaGetSymbolAddress((void**)&wprep, g_wprep);
    cudaGetSymbolAddress((void**)&wprep2, g_wprep2);
    cudaGetSymbolAddress((void**)&wprep3, g_wprep3);
    cudaGetSymbolAddress((void**)&S, g_S);
    cudaGetSymbolAddress((void**)&Sh, g_Sh);
    cudaGetSymbolAddress((void**)&Sw, g_Sw);

    static bool attr_set = false;
    if (!attr_set) {
        cudaFuncSetAttribute(conv_mma_s1<4>, cudaFuncAttributeMaxDynamicSharedMemorySize, MMA_SMEM);
        cudaFuncSetAttribute(conv_mma_s1<2>, cudaFuncAttributeMaxDynamicSharedMemorySize, MMA_SMEM);
        cudaFuncSetAttribute(conv_mma_s2c<4>, cudaFuncAttributeMaxDynamicSharedMemorySize, MMA_SMEM2);
        cudaFuncSetAttribute(conv_mma_s2c<2>, cudaFuncAttributeMaxDynamicSharedMemorySize, MMA_SMEM2);
        cudaFuncSetAttribute(conv_mma_t2c<4>, cudaFuncAttributeMaxDynamicSharedMemorySize, MMA_SMEM2);
        attr_set = true;
    }

    const int B = 32;
    const int OFF_E1 = 0, OFF_E3 = 2304, OFF_E5 = 11520;
    const int OFF_D1 = 48384, OFF_D3 = 57600, OFF_D5 = 59904;
    const int OFF2_E2 = 0, OFF2_E4 = 8192, OFF2_E6 = 40960;
    const int OFF3_D0 = 0, OFF3_D2 = 32768, OFF3_D4 = 40960;

    // weight preps
    prep_many<<<dim3(144, 3, 1), 256>>>(ew[1], ew[3], ew[5], wprep,
                                        OFF_E1, OFF_E3, OFF_E5, 32, 32, 64, 64, 128, 128);
    prep_many<<<dim3(36, 3, 1), 256>>>(dw[1], dw[3], dw[5], wprep,
                                       OFF_D1, OFF_D3, OFF_D5, 64, 64, 32, 32, 16, 16);
    prep_s2c<<<dim3(256, 3, 1), 256>>>(ew[2], ew[4], ew[6], wprep2,
                                       OFF2_E2, OFF2_E4, OFF2_E6,
                                       32, 64, 64, 128, 128, 128);
    prep_t2c<<<dim3(128, 3, 1), 256>>>(dw[0], dw[2], dw[4], wprep3,
                                       OFF3_D0, OFF3_D2, OFF3_D4,
                                       128, 64, 64, 32, 32, 16);

    // ---- encoder ----
    conv_e0<<<dim3(32, 1, B), 256>>>(x, ew[0], eb[0], B0, 3, 32, 128, 128, 0);
    conv_mma_s1<4><<<dim3(64, 1, B), 256, MMA_SMEM>>>(B0, wprep + OFF_E1, eb[1],
                                                      nullptr, B1, 32, 32, 128, 128, 0, 1);
    conv_mma_s2c<4><<<dim3(16, 2, B), 256, MMA_SMEM2>>>(B1, wprep2 + OFF2_E2, eb[2],
                                                        nullptr, B0, 32, 64, 64, 64, 1, 1);
    conv_mma_s1<4><<<dim3(16, 2, B), 256, MMA_SMEM>>>(B0, wprep + OFF_E3, eb[3],
                                                      nullptr, B1, 64, 64, 64, 64, 1, 1);
    conv_mma_s2c<4><<<dim3(4, 4, B), 256, MMA_SMEM2>>>(B1, wprep2 + OFF2_E4, eb[4],
                                                       nullptr, B0, 64, 128, 32, 32, 1, 1);
    conv_mma_s1<4><<<dim3(4, 4, B), 256, MMA_SMEM>>>(B0, wprep + OFF_E5, eb[5],
                                                     nullptr, B1, 128, 128, 32, 32, 1, 1);
    conv_mma_s2c<2><<<dim3(1, 8, B), 256, MMA_SMEM2>>>(B1, wprep2 + OFF2_E6, eb[6],
                                                       F1, nullptr, 128, 128, 16, 16, 3, 0);
    // ---- keypoint bottleneck ----
    bn_stats<<<4096, 256>>>(F1, S, Sh, Sw);
    bn_maps<<<dim3(32, 16, 1), 256>>>(S, Sh, Sw, B0);   // -> std planes, 16x16, C=128
    // ---- decoder ----
    conv_mma_t2c<4><<<dim3(1, 8, B), 256, MMA_SMEM2>>>(B0, wprep3 + OFF3_D0, db[0],
                                                       B1, 128, 64, 16, 16);
    conv_mma_s1<4><<<dim3(4, 2, B), 256, MMA_SMEM>>>(B1, wprep + OFF_D1, db[1],
                                                     nullptr, B0, 64, 64, 32, 32, 2, 1);
    conv_mma_t2c<4><<<dim3(4, 4, B), 256, MMA_SMEM2>>>(B0, wprep3 + OFF3_D2, db[2],
                                                       B1, 64, 32, 32, 32);
    conv_mma_s1<4><<<dim3(16, 1, B), 256, MMA_SMEM>>>(B1, wprep + OFF_D3, db[3],
                                                      nullptr, B0, 32, 32, 64, 64, 2, 1);
    conv_mma_t2c<4><<<dim3(16, 2, B), 256, MMA_SMEM2>>>(B0, wprep3 + OFF3_D4, db[4],
                                                        B1, 32, 16, 64, 64);
    conv_mma_s1<2><<<dim3(64, 1, B), 256, MMA_SMEM>>>(B1, wprep + OFF_D5, db[5],
                                                      out, nullptr, 16, 16, 128, 128, 2, 0);
}

// round 15
// speedup vs baseline: 3.3516x; 1.5061x over previous
#include <cuda_runtime.h>
#include <cuda_fp16.h>
#include <math.h>

// ---------------- scratch ----------------
__device__ float g_f1[32u * 32 * 128 * 128];              // fp32 NCHW (e6 out)
__device__ unsigned short g_b0[33554432];                 // fp16 planes ping [px][C]
__device__ unsigned short g_b1[33554432];                 // fp16 planes pong
__device__ uint4 g_wprep[60480];                          // s1 mma weights (fp16 hi/lo)
__device__ uint4 g_wprep2[106496];                        // s2c mma weights
__device__ uint4 g_wprep3[43008];                         // t2c mma weights
__device__ float g_S[4096];
__device__ float g_Sh[4096];
__device__ float g_Sw[4096];

__device__ __forceinline__ float activate(float v, int act) {
    switch (act) {
        case 1: return v > 0.f ? v : 0.2f * v;
        case 2: return v > 0.f ? v : 0.f;
        case 3: return fmaxf(v, 0.f) + log1pf(expf(-fabsf(v)));
        default: return v;
    }
}

__device__ __forceinline__ unsigned pack2_f16(float lo, float hi) {
    __half2 h = __floats2half2_rn(lo, hi);
    return *(unsigned*)&h;
}
__device__ __forceinline__ unsigned short f16_us(float x) {
    __half h = __float2half_rn(x);
    return *(unsigned short*)&h;
}

__device__ __forceinline__ void cp_async4(void* sdst, const void* gsrc, bool pred) {
    unsigned saddr = (unsigned)__cvta_generic_to_shared(sdst);
    int sz = pred ? 4 : 0;
    asm volatile("cp.async.ca.shared.global [%0], [%1], 4, %2;\n"
                 :: "r"(saddr), "l"(gsrc), "r"(sz));
}
__device__ __forceinline__ void cp_async16(void* sdst, const void* gsrc, bool pred) {
    unsigned saddr = (unsigned)__cvta_generic_to_shared(sdst);
    int sz = pred ? 16 : 0;
    asm volatile("cp.async.cg.shared.global [%0], [%1], 16, %2;\n"
                 :: "r"(saddr), "l"(gsrc), "r"(sz));
}
__device__ __forceinline__ void cp_commit() { asm volatile("cp.async.commit_group;\n"); }
__device__ __forceinline__ void cp_wait0() { asm volatile("cp.async.wait_group 0;\n"); }

__device__ __forceinline__ void mma16816(float* d, const unsigned* a, unsigned b0, unsigned b1) {
    asm volatile("mma.sync.aligned.m16n8k16.row.col.f32.f16.f16.f32 "
                 "{%0,%1,%2,%3},{%4,%5,%6,%7},{%8,%9},{%0,%1,%2,%3};"
                 : "+f"(d[0]), "+f"(d[1]), "+f"(d[2]), "+f"(d[3])
                 : "r"(a[0]), "r"(a[1]), "r"(a[2]), "r"(a[3]), "r"(b0), "r"(b1));
}

// =====================================================================
// s1 weight prep (3 layers/launch): fp16 hi + fp16 residual lo
// =====================================================================
__global__ void prep_many(const float* __restrict__ w0, const float* __restrict__ w1,
                          const float* __restrict__ w2, uint4* __restrict__ dstb,
                          int off0, int off1, int off2,
                          int C0, int OC0, int C1, int OC1, int C2, int OC2)
{
    int layer = blockIdx.y;
    const float* w = layer == 0 ? w0 : layer == 1 ? w1 : w2;
    uint4* dst = dstb + (layer == 0 ? off0 : layer == 1 ? off1 : off2);
    int C = layer == 0 ? C0 : layer == 1 ? C1 : C2;
    int OC = layer == 0 ? OC0 : layer == 1 ? OC1 : OC2;
    int OCg = OC >> 3;
    int total = (C >> 4) * 9 * OCg * 32;
    int idx = blockIdx.x * 256 + threadIdx.x;
    if (idx >= total) return;
    int l = idx & 31;
    int q = idx >> 5;
    int og = q % OCg; q /= OCg;
    int t = q % 9;
    int kc = q / 9;
    int tg = l & 3, gg = l >> 2;
    int n = og * 8 + gg;
    float h[4], lo[4];
#pragma unroll
    for (int kk = 0; kk < 4; kk++) {
        int k = (kk < 2) ? (2 * tg + kk) : (2 * tg + 8 + (kk - 2));
        int ic = (kc << 4) + k;
        float e = w[((size_t)n * C + ic) * 9 + t];
        h[kk] = __half2float(__float2half_rn(e));
        lo[kk] = e - h[kk];
    }
    uint4 r;
    r.x = pack2_f16(h[0], h[1]);
    r.y = pack2_f16(h[2], h[3]);
    r.z = pack2_f16(lo[0], lo[1]);
    r.w = pack2_f16(lo[2], lo[3]);
    dst[idx] = r;
}

// =====================================================================
// s2c weight prep
// =====================================================================
__global__ void prep_s2c(const float* __restrict__ w0, const float* __restrict__ w1,
                         const float* __restrict__ w2, uint4* __restrict__ dstb,
                         int off0, int off1, int off2,
                         int C0, int OC0, int C1, int OC1, int C2, int OC2)
{
    int layer = blockIdx.y;
    const float* w = layer == 0 ? w0 : layer == 1 ? w1 : w2;
    uint4* dst = dstb + (layer == 0 ? off0 : layer == 1 ? off1 : off2);
    int C = layer == 0 ? C0 : layer == 1 ? C1 : C2;
    int OC = layer == 0 ? OC0 : layer == 1 ? OC1 : OC2;
    int OCg = OC >> 3;
    int KC = (4 * C) >> 4;
    int total = KC * 4 * OCg * 32;
    int idx = blockIdx.x * 256 + threadIdx.x;
    if (idx >= total) return;
    int l = idx & 31;
    int q = idx >> 5;
    int og = q % OCg; q /= OCg;
    int t = q % 4;
    int kc = q / 4;
    int dy = t >> 1, dx = t & 1;
    int tg = l & 3, gg = l >> 2;
    int n = og * 8 + gg;
    float h[4], lo[4];
#pragma unroll
    for (int kk = 0; kk < 4; kk++) {
        int k = (kk < 2) ? (2 * tg + kk) : (2 * tg + 8 + (kk - 2));
        int ch = (kc << 4) + k;
        int qph = ch / C, c = ch - qph * C;
        int a = qph >> 1, bph = qph & 1;
        int ky = 2 * dy + a, kx = 2 * dx + bph;
        float e = (ky < 3 && kx < 3) ? w[((size_t)n * C + c) * 9 + ky * 3 + kx] : 0.f;
        h[kk] = __half2float(__float2half_rn(e));
        lo[kk] = e - h[kk];
    }
    uint4 r;
    r.x = pack2_f16(h[0], h[1]);
    r.y = pack2_f16(h[2], h[3]);
    r.z = pack2_f16(lo[0], lo[1]);
    r.w = pack2_f16(lo[2], lo[3]);
    dst[idx] = r;
}

// =====================================================================
// t2c weight prep
// =====================================================================
__global__ void prep_t2c(const float* __restrict__ w0, const float* __restrict__ w1,
                         const float* __restrict__ w2, uint4* __restrict__ dstb,
                         int off0, int off1, int off2,
                         int C0, int OC0, int C1, int OC1, int C2, int OC2)
{
    int layer = blockIdx.y;
    const float* w = layer == 0 ? w0 : layer == 1 ? w1 : w2;
    uint4* dst = dstb + (layer == 0 ? off0 : layer == 1 ? off1 : off2);
    int C = layer == 0 ? C0 : layer == 1 ? C1 : C2;
    int OC = layer == 0 ? OC0 : layer == 1 ? OC1 : OC2;
    int NN = 4 * OC;
    int OCgN = NN >> 3;
    int KC = C >> 4;
    int total = KC * 4 * OCgN * 32;
    int idx = blockIdx.x * 256 + threadIdx.x;
    if (idx >= total) return;
    int l = idx & 31;
    int q = idx >> 5;
    int og = q % OCgN; q /= OCgN;
    int t = q % 4;
    int kc = q / 4;
    int u = t >> 1, v = t & 1;
    int tg = l & 3, gg = l >> 2;
    int n = og * 8 + gg;
    int qph = n / OC, oc = n - qph * OC;
    int a = qph >> 1, bph = qph & 1;
    int ky = 2 * u - a, kx = 2 * v - bph;
    float h[4], lo[4];
#pragma unroll
    for (int kk = 0; kk < 4; kk++) {
        int k = (kk < 2) ? (2 * tg + kk) : (2 * tg + 8 + (kk - 2));
        int c = (kc << 4) + k;
        float e = (ky >= 0 && kx >= 0) ? w[((size_t)oc * C + c) * 9 + ky * 3 + kx] : 0.f;
        h[kk] = __half2float(__float2half_rn(e));
        lo[kk] = e - h[kk];
    }
    uint4 r;
    r.x = pack2_f16(h[0], h[1]);
    r.y = pack2_f16(h[2], h[3]);
    r.z = pack2_f16(lo[0], lo[1]);
    r.w = pack2_f16(lo[2], lo[3]);
    dst[idx] = r;
}

// =====================================================================
// tensor-core stride-1 3x3 SAME conv (fp16x2 split). Templated NF.
// in: fp16 planes [px][C]. out mode 0: fp32 NCHW; mode 1: fp16 planes.
// =====================================================================
#define SINW (324 * 12)
#define MMA_SW (9 * 4 * 32)
#define MMA_SMEM (2 * SINW * 4 + 2 * MMA_SW * 16)

template <int NF>
__global__ void __launch_bounds__(256, 2) conv_mma_s1(
    const unsigned short* __restrict__ in, const uint4* __restrict__ wp,
    const float* __restrict__ bias, float* __restrict__ fout,
    unsigned short* __restrict__ bout, int C, int OC, int H, int W, int act, int mode)
{
    const int KC = C >> 4;
    const int tilesX = W >> 4;
    const int x0 = (blockIdx.x % tilesX) << 4;
    const int y0 = (blockIdx.x / tilesX) << 4;
    const int oc0 = blockIdx.y * (NF * 8);
    const int b = blockIdx.z;
    const int OCg = OC >> 3;

    extern __shared__ __align__(16) unsigned char dsm[];
    unsigned* s_in = (unsigned*)dsm;
    uint4* s_w = (uint4*)(dsm + 2 * SINW * 4);

    const unsigned short* inb = in + (size_t)b * H * W * C;
    const int tid = threadIdx.x, lane = tid & 31, wid = tid >> 5;
    const int g = lane >> 2, tg = lane & 3;

    float d[2][NF][4];
#pragma unroll
    for (int i = 0; i < 2; i++)
#pragma unroll
        for (int j = 0; j < NF; j++)
#pragma unroll
            for (int r = 0; r < 4; r++) d[i][j][r] = 0.f;

    auto stage = [&](int buf, int kc) {
        unsigned* si = s_in + buf * SINW;
        for (int i = tid; i < 648; i += 256) {
            int sp = i >> 1, q = i & 1;
            int r = sp / 18, c = sp - r * 18;
            int iy = y0 - 1 + r, ix = x0 - 1 + c;
            bool p = (unsigned)iy < (unsigned)H && (unsigned)ix < (unsigned)W;
            const unsigned short* src = inb + ((size_t)iy * W + ix) * C + (kc << 4) + (q << 3);
            cp_async16(si + sp * 12 + q * 4, src, p);
        }
        uint4* sw = s_w + buf * MMA_SW;
        const uint4* wsrc = wp + (size_t)kc * 9 * OCg * 32;
        const int tot = 9 * NF * 32;
        for (int i = tid; i < tot; i += 256) {
            int l = i & 31;
            int q = i >> 5;
            int ogl = q % NF;
            int t = q / NF;
            cp_async16(sw + (t * 4 + ogl) * 32 + l,
                       wsrc + ((size_t)t * OCg + (oc0 >> 3) + ogl) * 32 + l, true);
        }
    };

    auto compute = [&](int buf) {
        unsigned* si = s_in + buf * SINW;
        uint4* sw = s_w + buf * MMA_SW;
#pragma unroll
        for (int t = 0; t < 9; t++) {
            const int dy = t / 3, dx = t - 3 * (t / 3);
            unsigned ah[2][4];
#pragma unroll
            for (int i = 0; i < 2; i++) {
                int sp0 = (2 * wid + i + dy) * 18 + g + dx;
                const unsigned* h0 = si + sp0 * 12;
                ah[i][0] = h0[tg];       ah[i][1] = h0[96 + tg];
                ah[i][2] = h0[tg + 4];   ah[i][3] = h0[96 + tg + 4];
            }
#pragma unroll
            for (int j = 0; j < NF; j++) {
                uint4 bw = sw[(t * 4 + j) * 32 + lane];
#pragma unroll
                for (int i = 0; i < 2; i++) {
                    mma16816(d[i][j], ah[i], bw.x, bw.y);
                    mma16816(d[i][j], ah[i], bw.z, bw.w);
                }
            }
        }
    };

    stage(0, 0);
    cp_commit();
    for (int kc = 0; kc < KC; kc++) {
        int buf = kc & 1;
        cp_wait0();
        __syncthreads();
        if (kc + 1 < KC) stage(buf ^ 1, kc + 1);
        cp_commit();
        compute(buf);
    }

    if (mode == 0) {
#pragma unroll
        for (int i = 0; i < 2; i++) {
            int y = y0 + 2 * wid + i;
#pragma unroll
            for (int j = 0; j < NF; j++) {
                int oc = oc0 + 8 * j + 2 * tg;
                float b0 = bias[oc], b1 = bias[oc + 1];
                size_t base0 = (((size_t)b * OC + oc) * H + y) * W + x0;
                size_t base1 = base0 + (size_t)H * W;
                fout[base0 + g]     = activate(d[i][j][0] + b0, act);
                fout[base1 + g]     = activate(d[i][j][1] + b1, act);
                fout[base0 + g + 8] = activate(d[i][j][2] + b0, act);
                fout[base1 + g + 8] = activate(d[i][j][3] + b1, act);
            }
        }
    } else {
        unsigned short* bo = bout + (size_t)b * H * W * OC;
#pragma unroll
        for (int i = 0; i < 2; i++) {
            int y = y0 + 2 * wid + i;
#pragma unroll
            for (int j = 0; j < NF; j++) {
                int oc = oc0 + 8 * j + 2 * tg;
                float b0 = bias[oc], b1 = bias[oc + 1];
                float v0 = activate(d[i][j][0] + b0, act);
                float v1 = activate(d[i][j][1] + b1, act);
                float v2 = activate(d[i][j][2] + b0, act);
                float v3 = activate(d[i][j][3] + b1, act);
                size_t px0 = (size_t)y * W + x0 + g;
                size_t px1 = px0 + 8;
                *(unsigned*)(bo + px0 * OC + oc) = pack2_f16(v0, v1);
                *(unsigned*)(bo + px1 * OC + oc) = pack2_f16(v2, v3);
            }
        }
    }
}

// =====================================================================
// s2c stride-2 conv (fp16x2). Tap skip by k-chunk phase.
// =====================================================================
#define SINW2 (289 * 12)
#define MMA_SW2 (4 * 4 * 32)
#define MMA_SMEM2 (2 * SINW2 * 4 + 2 * MMA_SW2 * 16)

template <int NF>
__global__ void __launch_bounds__(256, 2) conv_mma_s2c(
    const unsigned short* __restrict__ in, const uint4* __restrict__ wp,
    const float* __restrict__ bias, float* __restrict__ fout,
    unsigned short* __restrict__ bout, int C, int OC, int Hout, int Wout,
    int act, int mode)
{
    const int CC = 4 * C;
    const int KC = CC >> 4;
    const int Hin = Hout * 2, Win = Wout * 2;
    const int tilesX = Wout >> 4;
    const int x0 = (blockIdx.x % tilesX) << 4;
    const int y0 = (blockIdx.x / tilesX) << 4;
    const int oc0 = blockIdx.y * (NF * 8);
    const int b = blockIdx.z;
    const int OCg = OC >> 3;

    extern __shared__ __align__(16) unsigned char dsm[];
    unsigned* s_in = (unsigned*)dsm;
    uint4* s_w = (uint4*)(dsm + 2 * SINW2 * 4);

    const unsigned short* inb = in + (size_t)b * Hin * Win * C;
    const int tid = threadIdx.x, lane = tid & 31, wid = tid >> 5;
    const int g = lane >> 2, tg = lane & 3;

    float d[2][NF][4];
#pragma unroll
    for (int i = 0; i < 2; i++)
#pragma unroll
        for (int j = 0; j < NF; j++)
#pragma unroll
            for (int r = 0; r < 4; r++) d[i][j][r] = 0.f;

    auto stage = [&](int buf, int kc) {
        unsigned* si = s_in + buf * SINW2;
        int qph = (kc << 4) / C;
        int c0 = (kc << 4) - qph * C;
        int pa = qph >> 1, pb = qph & 1;
        for (int i = tid; i < 578; i += 256) {
            int sp = i >> 1, q = i & 1;
            int r = sp / 17, c = sp - r * 17;
            int sy = 2 * (y0 + r) + pa, sx = 2 * (x0 + c) + pb;
            bool p = sy < Hin && sx < Win;
            const unsigned short* src = inb + ((size_t)sy * Win + sx) * C + c0 + (q << 3);
            cp_async16(si + sp * 12 + q * 4, src, p);
        }
        uint4* sw = s_w + buf * MMA_SW2;
        const uint4* wsrc = wp + (size_t)kc * 4 * OCg * 32;
        const int tot = 4 * NF * 32;
        for (int i = tid; i < tot; i += 256) {
            int l = i & 31;
            int q = i >> 5;
            int ogl = q % NF;
            int t = q / NF;
            cp_async16(sw + (t * 4 + ogl) * 32 + l,
                       wsrc + ((size_t)t * OCg + (oc0 >> 3) + ogl) * 32 + l, true);
        }
    };

    auto compute = [&](int buf, int pa, int pb) {
        unsigned* si = s_in + buf * SINW2;
        uint4* sw = s_w + buf * MMA_SW2;
#pragma unroll
        for (int t = 0; t < 4; t++) {
            const int dy = t >> 1, dx = t & 1;
            if ((dy && pa) || (dx && pb)) continue;
            unsigned ah[2][4];
#pragma unroll
            for (int i = 0; i < 2; i++) {
                int sp0 = (2 * wid + i + dy) * 17 + g + dx;
                const unsigned* h0 = si + sp0 * 12;
                ah[i][0] = h0[tg];       ah[i][1] = h0[96 + tg];
                ah[i][2] = h0[tg + 4];   ah[i][3] = h0[96 + tg + 4];
            }
#pragma unroll
            for (int j = 0; j < NF; j++) {
                uint4 bw = sw[(t * 4 + j) * 32 + lane];
#pragma unroll
                for (int i = 0; i < 2; i++) {
                    mma16816(d[i][j], ah[i], bw.x, bw.y);
                    mma16816(d[i][j], ah[i], bw.z, bw.w);
                }
            }
        }
    };

    stage(0, 0);
    cp_commit();
    for (int kc = 0; kc < KC; kc++) {
        int buf = kc & 1;
        cp_wait0();
        __syncthreads();
        if (kc + 1 < KC) stage(buf ^ 1, kc + 1);
        cp_commit();
        int qc = (kc << 4) / C;
        compute(buf, qc >> 1, qc & 1);
    }

    if (mode == 0) {
#pragma unroll
        for (int i = 0; i < 2; i++) {
            int y = y0 + 2 * wid + i;
#pragma unroll
            for (int j = 0; j < NF; j++) {
                int oc = oc0 + 8 * j + 2 * tg;
                float b0 = bias[oc], b1 = bias[oc + 1];
                size_t base0 = (((size_t)b * OC + oc) * Hout + y) * Wout + x0;
                size_t base1 = base0 + (size_t)Hout * Wout;
                fout[base0 + g]     = activate(d[i][j][0] + b0, act);
                fout[base1 + g]     = activate(d[i][j][1] + b1, act);
                fout[base0 + g + 8] = activate(d[i][j][2] + b0, act);
                fout[base1 + g + 8] = activate(d[i][j][3] + b1, act);
            }
        }
    } else {
        unsigned short* bo = bout + (size_t)b * Hout * Wout * OC;
#pragma unroll
        for (int i = 0; i < 2; i++) {
            int y = y0 + 2 * wid + i;
#pragma unroll
            for (int j = 0; j < NF; j++) {
                int oc = oc0 + 8 * j + 2 * tg;
                float b0 = bias[oc], b1 = bias[oc + 1];
                float v0 = activate(d[i][j][0] + b0, act);
                float v1 = activate(d[i][j][1] + b1, act);
                float v2 = activate(d[i][j][2] + b0, act);
                float v3 = activate(d[i][j][3] + b1, act);
                size_t px0 = (size_t)y * Wout + x0 + g;
                size_t px1 = px0 + 8;
                *(unsigned*)(bo + px0 * OC + oc) = pack2_f16(v0, v1);
                *(unsigned*)(bo + px1 * OC + oc) = pack2_f16(v2, v3);
            }
        }
    }
}

// =====================================================================
// t2c transposed conv (fp16x2). Tap skip per fragment phase. relu.
// =====================================================================
template <int NF>
__global__ void __launch_bounds__(256, 2) conv_mma_t2c(
    const unsigned short* __restrict__ in, const uint4* __restrict__ wp,
    const float* __restrict__ bias, unsigned short* __restrict__ bout,
    int C, int OC, int Hin, int Win)
{
    const int KC = C >> 4;
    const int NN = 4 * OC;
    const int OCgN = NN >> 3;
    const int Wout = Win * 2;
    const int tilesX = Win >> 4;
    const int x0 = (blockIdx.x % tilesX) << 4;
    const int y0 = (blockIdx.x / tilesX) << 4;
    const int oc0 = blockIdx.y * (NF * 8);
    const int b = blockIdx.z;

    extern __shared__ __align__(16) unsigned char dsm[];
    unsigned* s_in = (unsigned*)dsm;
    uint4* s_w = (uint4*)(dsm + 2 * SINW2 * 4);

    const unsigned short* inb = in + (size_t)b * Hin * Win * C;
    const int tid = threadIdx.x, lane = tid & 31, wid = tid >> 5;
    const int g = lane >> 2, tg = lane & 3;

    int aj[NF], bj[NF];
#pragma unroll
    for (int j = 0; j < NF; j++) {
        int qj = (oc0 + 8 * j) / OC;
        aj[j] = qj >> 1;
        bj[j] = qj & 1;
    }

    float d[2][NF][4];
#pragma unroll
    for (int i = 0; i < 2; i++)
#pragma unroll
        for (int j = 0; j < NF; j++)
#pragma unroll
            for (int r = 0; r < 4; r++) d[i][j][r] = 0.f;

    auto stage = [&](int buf, int kc) {
        unsigned* si = s_in + buf * SINW2;
        for (int i = tid; i < 578; i += 256) {
            int sp = i >> 1, q = i & 1;
            int r = sp / 17, c = sp - r * 17;
            int iy = y0 - 1 + r, ix = x0 - 1 + c;
            bool p = (unsigned)iy < (unsigned)Hin && (unsigned)ix < (unsigned)Win;
            const unsigned short* src = inb + ((size_t)iy * Win + ix) * C + (kc << 4) + (q << 3);
            cp_async16(si + sp * 12 + q * 4, src, p);
        }
        uint4* sw = s_w + buf * MMA_SW2;
        const uint4* wsrc = wp + (size_t)kc * 4 * OCgN * 32;
        const int tot = 4 * NF * 32;
        for (int i = tid; i < tot; i += 256) {
            int l = i & 31;
            int q = i >> 5;
            int ogl = q % NF;
            int t = q / NF;
            cp_async16(sw + (t * 4 + ogl) * 32 + l,
                       wsrc + ((size_t)t * OCgN + (oc0 >> 3) + ogl) * 32 + l, true);
        }
    };

    auto compute = [&](int buf) {
        unsigned* si = s_in + buf * SINW2;
        uint4* sw = s_w + buf * MMA_SW2;
#pragma unroll
        for (int t = 0; t < 4; t++) {
            const int dy = t >> 1, dx = t & 1;
            unsigned ah[2][4];
#pragma unroll
            for (int i = 0; i < 2; i++) {
                int sp0 = (2 * wid + i + dy) * 17 + g + dx;
                const unsigned* h0 = si + sp0 * 12;
                ah[i][0] = h0[tg];       ah[i][1] = h0[96 + tg];
                ah[i][2] = h0[tg + 4];   ah[i][3] = h0[96 + tg + 4];
            }
#pragma unroll
            for (int j = 0; j < NF; j++) {
                if ((dy == 0 && aj[j]) || (dx == 0 && bj[j])) continue;
                uint4 bw = sw[(t * 4 + j) * 32 + lane];
#pragma unroll
                for (int i = 0; i < 2; i++) {
                    mma16816(d[i][j], ah[i], bw.x, bw.y);
                    mma16816(d[i][j], ah[i], bw.z, bw.w);
                }
            }
        }
    };

    stage(0, 0);
    cp_commit();
    for (int kc = 0; kc < KC; kc++) {
        int buf = kc & 1;
        cp_wait0();
        __syncthreads();
        if (kc + 1 < KC) stage(buf ^ 1, kc + 1);
        cp_commit();
        compute(buf);
    }

    unsigned short* bo2 = bout + (size_t)b * (2 * Hin) * Wout * OC;
#pragma unroll
    for (int i = 0; i < 2; i++) {
        int yin = y0 + 2 * wid + i;
#pragma unroll
        for (int j = 0; j < NF; j++) {
            int n0 = oc0 + 8 * j + 2 * tg;
            int q = n0 / OC;
            int oc = n0 - q * OC;
            int a = q >> 1, bph = q & 1;
            int oy = 2 * yin + a;
            float b0 = bias[oc], b1 = bias[oc + 1];
            float v0 = d[i][j][0] + b0; v0 = v0 > 0.f ? v0 : 0.f;
            float v1 = d[i][j][1] + b1; v1 = v1 > 0.f ? v1 : 0.f;
            float v2 = d[i][j][2] + b0; v2 = v2 > 0.f ? v2 : 0.f;
            float v3 = d[i][j][3] + b1; v3 = v3 > 0.f ? v3 : 0.f;
            size_t px0 = (size_t)oy * Wout + 2 * (x0 + g) + bph;
            size_t px1 = (size_t)oy * Wout + 2 * (x0 + g + 8) + bph;
            *(unsigned*)(bo2 + px0 * OC + oc) = pack2_f16(v0, v1);
            *(unsigned*)(bo2 + px1 * OC + oc) = pack2_f16(v2, v3);
        }
    }
}

// =====================================================================
// e0: fp32 NCHW in (C=3) -> fp16 planes.
// =====================================================================
__global__ void __launch_bounds__(256, 2) conv_e0(
    const float* __restrict__ in, const float* __restrict__ wgt,
    const float* __restrict__ bias, unsigned short* __restrict__ bout,
    int C, int OC, int H, int W, int act)
{
    constexpr int NT = 256;
    constexpr int ICB = 4;
    constexpr int SROW = 34;
    constexpr int SIN = 18 * SROW;

    const int tilesX = W >> 5;
    const int x0 = (blockIdx.x % tilesX) << 5;
    const int y0 = (blockIdx.x / tilesX) << 4;
    const int oc0 = blockIdx.y * 32;
    const int b = blockIdx.z;

    __shared__ __align__(16) float s_in[2][ICB][SIN];
    __shared__ __align__(16) float s_w[2][ICB][32 * 12];

    const int tid = threadIdx.x;
    const int g = tid >> 6;
    const int sp = tid & 63;
    const int ty = sp >> 3, tx = sp & 7;

    float acc[8][2][4];
#pragma unroll
    for (int o = 0; o < 8; o++)
#pragma unroll
        for (int dy = 0; dy < 2; dy++)
#pragma unroll
            for (int dx = 0; dx < 4; dx++) acc[o][dy][dx] = 0.f;

    const float* inb = in + (size_t)b * C * H * W;
    const float* wb = wgt + (size_t)oc0 * C * 9;

    auto stage_copy = [&](int buf, int ic0, int cnt) {
        const float* ins = inb + (size_t)ic0 * H * W;
        for (int i = tid; i < cnt * SIN; i += NT) {
            int ch = i / SIN, r2 = i - ch * SIN;
            int r = r2 / SROW, c2 = r2 - r * SROW;
            int iy = y0 - 1 + r, ix = x0 - 1 + c2;
            bool p = (unsigned)iy < (unsigned)H && (unsigned)ix < (unsigned)W;
            cp_async4(&s_in[buf][ch][r2], ins + (size_t)ch * H * W + (size_t)iy * W + ix, p);
        }
        for (int i = tid; i < cnt * 32 * 9; i += NT) {
            int ch = i / (32 * 9), r2 = i - ch * (32 * 9);
            int o = r2 / 9, j2 = r2 - o * 9;
            cp_async4(&s_w[buf][ch][o * 12 + j2],
                      wb + ((size_t)o * C + ic0 + ch) * 9 + j2, true);
        }
    };

    const int sbase = (2 * ty) * SROW + 4 * tx;

    auto compute_ch = [&](int buf, int ch) {
        float rr[4][6];
        const float* si = &s_in[buf][ch][sbase];
#pragma unroll
        for (int r = 0; r < 4; r++) {
            const float2* p = (const float2*)(si + r * SROW);
            float2 a = p[0], b2 = p[1], c2 = p[2];
            rr[r][0] = a.x; rr[r][1] = a.y; rr[r][2] = b2.x;
            rr[r][3] = b2.y; rr[r][4] = c2.x; rr[r][5] = c2.y;
        }
#pragma unroll
        for (int o = 0; o < 8; o++) {
            const float4* wp = (const float4*)&s_w[buf][ch][(g * 8 + o) * 12];
            float4 wa = wp[0];
            float4 wc = wp[1];
            float w8 = ((const float*)wp)[8];
#pragma unroll
            for (int dy = 0; dy < 2; dy++)
#pragma unroll
                for (int dx = 0; dx < 4; dx++) {
                    float s = acc[o][dy][dx];
                    s += wa.x * rr[dy + 0][dx + 0];
                    s += wa.y * rr[dy + 0][dx + 1];
                    s += wa.z * rr[dy + 0][dx + 2];
                    s += wa.w * rr[dy + 1][dx + 0];
                    s += wc.x * rr[dy + 1][dx + 1];
                    s += wc.y * rr[dy + 1][dx + 2];
                    s += wc.z * rr[dy + 2][dx + 0];
                    s += wc.w * rr[dy + 2][dx + 1];
                    s += w8   * rr[dy + 2][dx + 2];
                    acc[o][dy][dx] = s;
                }
        }
    };

    const int nst = (C + ICB - 1) / ICB;
    stage_copy(0, 0, C < ICB ? C : ICB);
    cp_commit();
    for (int s = 0; s < nst; s++) {
        int buf = s & 1;
        cp_wait0();
        __syncthreads();
        int icn = (s + 1) * ICB;
        if (icn < C) {
            int cn = C - icn; if (cn > ICB) cn = ICB;
            stage_copy(buf ^ 1, icn, cn);
        }
        cp_commit();
        int cnt = C - s * ICB; if (cnt > ICB) cnt = ICB;
        for (int j = 0; j < cnt; j++) compute_ch(buf, j);
    }

    float bv[8];
#pragma unroll
    for (int o = 0; o < 8; o++) bv[o] = bias[oc0 + g * 8 + o];
    unsigned short* bo = bout + (size_t)b * H * W * OC;
#pragma unroll
    for (int dy = 0; dy < 2; dy++)
#pragma unroll
        for (int dx = 0; dx < 4; dx++) {
            int y = y0 + 2 * ty + dy, x = x0 + 4 * tx + dx;
            float v[8];
#pragma unroll
            for (int o = 0; o < 8; o++) v[o] = activate(acc[o][dy][dx] + bv[o], act);
            uint4 u;
            u.x = pack2_f16(v[0], v[1]);
            u.y = pack2_f16(v[2], v[3]);
            u.z = pack2_f16(v[4], v[5]);
            u.w = pack2_f16(v[6], v[7]);
            *(uint4*)(bo + ((size_t)y * W + x) * OC + oc0 + g * 8) = u;
        }
}

// ---------------- keypoint bottleneck ----------------
__global__ void bn_stats(const float* __restrict__ R, float* __restrict__ S,
                         float* __restrict__ Sh, float* __restrict__ Sw)
{
    int bk = blockIdx.x;
    int t = threadIdx.x;
    float v = R[(size_t)bk * 256 + t];
    float a = v;
    float bsum = v * (float)(t >> 4);
    float c = v * (float)(t & 15);
#pragma unroll
    for (int off = 16; off > 0; off >>= 1) {
        a += __shfl_down_sync(0xffffffffu, a, off);
        bsum += __shfl_down_sync(0xffffffffu, bsum, off);
        c += __shfl_down_sync(0xffffffffu, c, off);
    }
    __shared__ float sa[8], sb[8], sc[8];
    int wid = t >> 5;
    if ((t & 31) == 0) { sa[wid] = a; sb[wid] = bsum; sc[wid] = c; }
    __syncthreads();
    if (t == 0) {
        float ta = 0.f, tb = 0.f, tc = 0.f;
        for (int i = 0; i < 8; i++) { ta += sa[i]; tb += sb[i]; tc += sc[i]; }
        S[bk] = ta; Sh[bk] = tb; Sw[bk] = tc;
    }
}

// maps -> fp16 planes [px][128]; grid (32, 16), block 256
__global__ void bn_maps(const float* __restrict__ S, const float* __restrict__ Sh,
                        const float* __restrict__ Sw, unsigned short* __restrict__ bout)
{
    int b = blockIdx.x;
    int spc = blockIdx.y;
    int k = threadIdx.x & 127;
    int half = threadIdx.x >> 7;
    float s = S[b * 128 + k];
    float denom = S[b * 128 + 127];
    float mu = s * (1.f / 256.f);
    float inv = 1.f / denom;
    float c0 = Sh[b * 128 + k] * inv;
    float c1 = Sw[b * 128 + k] * inv;
    unsigned short* bo = bout + (size_t)b * 256 * 128;
#pragma unroll
    for (int i = 0; i < 8; i++) {
        int sp = spc * 16 + half * 8 + i;
        float dh = (float)(sp >> 4) - c0;
        float dw = (float)(sp & 15) - c1;
        float v = mu * expf(-0.5f * (dh * dh + dw * dw));
        bo[sp * 128 + k] = f16_us(v);
    }
}

// ---------------- launch ----------------
extern "C" void kernel_launch(void* const* d_in, const int* in_sizes, int n_in,
                              void* d_out, int out_size)
{
    (void)in_sizes; (void)n_in; (void)out_size;
    const float* x = (const float*)d_in[0];
    const float* ew[7]; const float* eb[7];
    for (int j = 0; j < 7; j++) {
        ew[j] = (const float*)d_in[1 + 2 * j];
        eb[j] = (const float*)d_in[2 + 2 * j];
    }
    const float* dw[6]; const float* db[6];
    for (int j = 0; j < 6; j++) {
        dw[j] = (const float*)d_in[15 + 2 * j];
        db[j] = (const float*)d_in[16 + 2 * j];
    }
    float* out = (float*)d_out;

    float *F1, *S, *Sh, *Sw;
    unsigned short *B0, *B1;
    uint4 *wprep, *wprep2, *wprep3;
    cudaGetSymbolAddress((void**)&F1, g_f1);
    cudaGetSymbolAddress((void**)&B0, g_b0);
    cudaGetSymbolAddress((void**)&B1, g_b1);
    cudaGetSymbolAddress((void**)&wprep, g_wprep);
    cudaGetSymbolAddress((void**)&wprep2, g_wprep2);
    cudaGetSymbolAddress((void**)&wprep3, g_wprep3);
    cudaGetSymbolAddress((void**)&S, g_S);
    cudaGetSymbolAddress((void**)&Sh, g_Sh);
    cudaGetSymbolAddress((void**)&Sw, g_Sw);

    static bool attr_set = false;
    if (!attr_set) {
        cudaFuncSetAttribute(conv_mma_s1<4>, cudaFuncAttributeMaxDynamicSharedMemorySize, MMA_SMEM);
        cudaFuncSetAttribute(conv_mma_s1<2>, cudaFuncAttributeMaxDynamicSharedMemorySize, MMA_SMEM);
        cudaFuncSetAttribute(conv_mma_s2c<4>, cudaFuncAttributeMaxDynamicSharedMemorySize, MMA_SMEM2);
        cudaFuncSetAttribute(conv_mma_s2c<2>, cudaFuncAttributeMaxDynamicSharedMemorySize, MMA_SMEM2);
        cudaFuncSetAttribute(conv_mma_t2c<4>, cudaFuncAttributeMaxDynamicSharedMemorySize, MMA_SMEM2);
        attr_set = true;
    }

    const int B = 32;
    const int OFF_E1 = 0, OFF_E3 = 2304, OFF_E5 = 11520;
    const int OFF_D1 = 48384, OFF_D3 = 57600, OFF_D5 = 59904;
    const int OFF2_E2 = 0, OFF2_E4 = 8192, OFF2_E6 = 40960;
    const int OFF3_D0 = 0, OFF3_D2 = 32768, OFF3_D4 = 40960;

    prep_many<<<dim3(144, 3, 1), 256>>>(ew[1], ew[3], ew[5], wprep,
                                        OFF_E1, OFF_E3, OFF_E5, 32, 32, 64, 64, 128, 128);
    prep_many<<<dim3(36, 3, 1), 256>>>(dw[1], dw[3], dw[5], wprep,
                                       OFF_D1, OFF_D3, OFF_D5, 64, 64, 32, 32, 16, 16);
    prep_s2c<<<dim3(256, 3, 1), 256>>>(ew[2], ew[4], ew[6], wprep2,
                                       OFF2_E2, OFF2_E4, OFF2_E6,
                                       32, 64, 64, 128, 128, 128);
    prep_t2c<<<dim3(128, 3, 1), 256>>>(dw[0], dw[2], dw[4], wprep3,
                                       OFF3_D0, OFF3_D2, OFF3_D4,
                                       128, 64, 64, 32, 32, 16);

    // ---- encoder ----
    conv_e0<<<dim3(32, 1, B), 256>>>(x, ew[0], eb[0], B0, 3, 32, 128, 128, 0);
    conv_mma_s1<4><<<dim3(64, 1, B), 256, MMA_SMEM>>>(B0, wprep + OFF_E1, eb[1],
                                                      nullptr, B1, 32, 32, 128, 128, 0, 1);
    conv_mma_s2c<4><<<dim3(16, 2, B), 256, MMA_SMEM2>>>(B1, wprep2 + OFF2_E2, eb[2],
                                                        nullptr, B0, 32, 64, 64, 64, 1, 1);
    conv_mma_s1<4><<<dim3(16, 2, B), 256, MMA_SMEM>>>(B0, wprep + OFF_E3, eb[3],
                                                      nullptr, B1, 64, 64, 64, 64, 1, 1);
    conv_mma_s2c<4><<<dim3(4, 4, B), 256, MMA_SMEM2>>>(B1, wprep2 + OFF2_E4, eb[4],
                                                       nullptr, B0, 64, 128, 32, 32, 1, 1);
    conv_mma_s1<4><<<dim3(4, 4, B), 256, MMA_SMEM>>>(B0, wprep + OFF_E5, eb[5],
                                                     nullptr, B1, 128, 128, 32, 32, 1, 1);
    conv_mma_s2c<2><<<dim3(1, 8, B), 256, MMA_SMEM2>>>(B1, wprep2 + OFF2_E6, eb[6],
                                                       F1, nullptr, 128, 128, 16, 16, 3, 0);
    // ---- keypoint bottleneck ----
    bn_stats<<<4096, 256>>>(F1, S, Sh, Sw);
    bn_maps<<<dim3(32, 16, 1), 256>>>(S, Sh, Sw, B0);
    // ---- decoder ----
    conv_mma_t2c<4><<<dim3(1, 8, B), 256, MMA_SMEM2>>>(B0, wprep3 + OFF3_D0, db[0],
                                                       B1, 128, 64, 16, 16);
    conv_mma_s1<4><<<dim3(4, 2, B), 256, MMA_SMEM>>>(B1, wprep + OFF_D1, db[1],
                                                     nullptr, B0, 64, 64, 32, 32, 2, 1);
    conv_mma_t2c<4><<<dim3(4, 4, B), 256, MMA_SMEM2>>>(B0, wprep3 + OFF3_D2, db[2],
                                                       B1, 64, 32, 32, 32);
    conv_mma_s1<4><<<dim3(16, 1, B), 256, MMA_SMEM>>>(B1, wprep + OFF_D3, db[3],
                                                      nullptr, B0, 32, 32, 64, 64, 2, 1);
    conv_mma_t2c<4><<<dim3(16, 2, B), 256, MMA_SMEM2>>>(B0, wprep3 + OFF3_D4, db[4],
                                                        B1, 32, 16, 64, 64);
    conv_mma_s1<2><<<dim3(64, 1, B), 256, MMA_SMEM>>>(B1, wprep + OFF_D5, db[5],
                                                      out, nullptr, 16, 16, 128, 128, 2, 0);
}

// round 16
// speedup vs baseline: 3.9943x; 1.1918x over previous
#include <cuda_runtime.h>
#include <cuda_fp16.h>
#include <math.h>

// ---------------- scratch ----------------
__device__ float g_f1[32u * 32 * 128 * 128];              // fp32 NCHW (e6 out)
__device__ unsigned short g_b0[33554432];                 // fp16 planes ping [px][C]
__device__ unsigned short g_b1[33554432];                 // fp16 planes pong
__device__ uint4 g_wprep[60480];                          // s1 mma weights (fp16 hi/lo)
__device__ uint4 g_wprep2[106496];                        // s2c mma weights
__device__ uint4 g_wprep3[43008];                         // t2c mma weights
__device__ float g_S[4096];
__device__ float g_Sh[4096];
__device__ float g_Sw[4096];

__device__ __forceinline__ float activate(float v, int act) {
    switch (act) {
        case 1: return v > 0.f ? v : 0.2f * v;
        case 2: return v > 0.f ? v : 0.f;
        case 3: return fmaxf(v, 0.f) + log1pf(expf(-fabsf(v)));
        default: return v;
    }
}

__device__ __forceinline__ unsigned pack2_f16(float lo, float hi) {
    __half2 h = __floats2half2_rn(lo, hi);
    return *(unsigned*)&h;
}
__device__ __forceinline__ unsigned short f16_us(float x) {
    __half h = __float2half_rn(x);
    return *(unsigned short*)&h;
}

__device__ __forceinline__ void cp_async4(void* sdst, const void* gsrc, bool pred) {
    unsigned saddr = (unsigned)__cvta_generic_to_shared(sdst);
    int sz = pred ? 4 : 0;
    asm volatile("cp.async.ca.shared.global [%0], [%1], 4, %2;\n"
                 :: "r"(saddr), "l"(gsrc), "r"(sz));
}
__device__ __forceinline__ void cp_async16(void* sdst, const void* gsrc, bool pred) {
    unsigned saddr = (unsigned)__cvta_generic_to_shared(sdst);
    int sz = pred ? 16 : 0;
    asm volatile("cp.async.cg.shared.global [%0], [%1], 16, %2;\n"
                 :: "r"(saddr), "l"(gsrc), "r"(sz));
}
__device__ __forceinline__ void cp_commit() { asm volatile("cp.async.commit_group;\n"); }
__device__ __forceinline__ void cp_wait0() { asm volatile("cp.async.wait_group 0;\n"); }

__device__ __forceinline__ void mma16816(float* d, const unsigned* a, unsigned b0, unsigned b1) {
    asm volatile("mma.sync.aligned.m16n8k16.row.col.f32.f16.f16.f32 "
                 "{%0,%1,%2,%3},{%4,%5,%6,%7},{%8,%9},{%0,%1,%2,%3};"
                 : "+f"(d[0]), "+f"(d[1]), "+f"(d[2]), "+f"(d[3])
                 : "r"(a[0]), "r"(a[1]), "r"(a[2]), "r"(a[3]), "r"(b0), "r"(b1));
}

// =====================================================================
// s1 weight prep (3 layers/launch): fp16 hi + fp16 residual lo
// =====================================================================
__global__ void prep_many(const float* __restrict__ w0, const float* __restrict__ w1,
                          const float* __restrict__ w2, uint4* __restrict__ dstb,
                          int off0, int off1, int off2,
                          int C0, int OC0, int C1, int OC1, int C2, int OC2)
{
    int layer = blockIdx.y;
    const float* w = layer == 0 ? w0 : layer == 1 ? w1 : w2;
    uint4* dst = dstb + (layer == 0 ? off0 : layer == 1 ? off1 : off2);
    int C = layer == 0 ? C0 : layer == 1 ? C1 : C2;
    int OC = layer == 0 ? OC0 : layer == 1 ? OC1 : OC2;
    int OCg = OC >> 3;
    int total = (C >> 4) * 9 * OCg * 32;
    int idx = blockIdx.x * 256 + threadIdx.x;
    if (idx >= total) return;
    int l = idx & 31;
    int q = idx >> 5;
    int og = q % OCg; q /= OCg;
    int t = q % 9;
    int kc = q / 9;
    int tg = l & 3, gg = l >> 2;
    int n = og * 8 + gg;
    float h[4], lo[4];
#pragma unroll
    for (int kk = 0; kk < 4; kk++) {
        int k = (kk < 2) ? (2 * tg + kk) : (2 * tg + 8 + (kk - 2));
        int ic = (kc << 4) + k;
        float e = w[((size_t)n * C + ic) * 9 + t];
        h[kk] = __half2float(__float2half_rn(e));
        lo[kk] = e - h[kk];
    }
    uint4 r;
    r.x = pack2_f16(h[0], h[1]);
    r.y = pack2_f16(h[2], h[3]);
    r.z = pack2_f16(lo[0], lo[1]);
    r.w = pack2_f16(lo[2], lo[3]);
    dst[idx] = r;
}

// =====================================================================
// s2c weight prep
// =====================================================================
__global__ void prep_s2c(const float* __restrict__ w0, const float* __restrict__ w1,
                         const float* __restrict__ w2, uint4* __restrict__ dstb,
                         int off0, int off1, int off2,
                         int C0, int OC0, int C1, int OC1, int C2, int OC2)
{
    int layer = blockIdx.y;
    const float* w = layer == 0 ? w0 : layer == 1 ? w1 : w2;
    uint4* dst = dstb + (layer == 0 ? off0 : layer == 1 ? off1 : off2);
    int C = layer == 0 ? C0 : layer == 1 ? C1 : C2;
    int OC = layer == 0 ? OC0 : layer == 1 ? OC1 : OC2;
    int OCg = OC >> 3;
    int KC = (4 * C) >> 4;
    int total = KC * 4 * OCg * 32;
    int idx = blockIdx.x * 256 + threadIdx.x;
    if (idx >= total) return;
    int l = idx & 31;
    int q = idx >> 5;
    int og = q % OCg; q /= OCg;
    int t = q % 4;
    int kc = q / 4;
    int dy = t >> 1, dx = t & 1;
    int tg = l & 3, gg = l >> 2;
    int n = og * 8 + gg;
    float h[4], lo[4];
#pragma unroll
    for (int kk = 0; kk < 4; kk++) {
        int k = (kk < 2) ? (2 * tg + kk) : (2 * tg + 8 + (kk - 2));
        int ch = (kc << 4) + k;
        int qph = ch / C, c = ch - qph * C;
        int a = qph >> 1, bph = qph & 1;
        int ky = 2 * dy + a, kx = 2 * dx + bph;
        float e = (ky < 3 && kx < 3) ? w[((size_t)n * C + c) * 9 + ky * 3 + kx] : 0.f;
        h[kk] = __half2float(__float2half_rn(e));
        lo[kk] = e - h[kk];
    }
    uint4 r;
    r.x = pack2_f16(h[0], h[1]);
    r.y = pack2_f16(h[2], h[3]);
    r.z = pack2_f16(lo[0], lo[1]);
    r.w = pack2_f16(lo[2], lo[3]);
    dst[idx] = r;
}

// =====================================================================
// t2c weight prep
// =====================================================================
__global__ void prep_t2c(const float* __restrict__ w0, const float* __restrict__ w1,
                         const float* __restrict__ w2, uint4* __restrict__ dstb,
                         int off0, int off1, int off2,
                         int C0, int OC0, int C1, int OC1, int C2, int OC2)
{
    int layer = blockIdx.y;
    const float* w = layer == 0 ? w0 : layer == 1 ? w1 : w2;
    uint4* dst = dstb + (layer == 0 ? off0 : layer == 1 ? off1 : off2);
    int C = layer == 0 ? C0 : layer == 1 ? C1 : C2;
    int OC = layer == 0 ? OC0 : layer == 1 ? OC1 : OC2;
    int NN = 4 * OC;
    int OCgN = NN >> 3;
    int KC = C >> 4;
    int total = KC * 4 * OCgN * 32;
    int idx = blockIdx.x * 256 + threadIdx.x;
    if (idx >= total) return;
    int l = idx & 31;
    int q = idx >> 5;
    int og = q % OCgN; q /= OCgN;
    int t = q % 4;
    int kc = q / 4;
    int u = t >> 1, v = t & 1;
    int tg = l & 3, gg = l >> 2;
    int n = og * 8 + gg;
    int qph = n / OC, oc = n - qph * OC;
    int a = qph >> 1, bph = qph & 1;
    int ky = 2 * u - a, kx = 2 * v - bph;
    float h[4], lo[4];
#pragma unroll
    for (int kk = 0; kk < 4; kk++) {
        int k = (kk < 2) ? (2 * tg + kk) : (2 * tg + 8 + (kk - 2));
        int c = (kc << 4) + k;
        float e = (ky >= 0 && kx >= 0) ? w[((size_t)oc * C + c) * 9 + ky * 3 + kx] : 0.f;
        h[kk] = __half2float(__float2half_rn(e));
        lo[kk] = e - h[kk];
    }
    uint4 r;
    r.x = pack2_f16(h[0], h[1]);
    r.y = pack2_f16(h[2], h[3]);
    r.z = pack2_f16(lo[0], lo[1]);
    r.w = pack2_f16(lo[2], lo[3]);
    dst[idx] = r;
}

// =====================================================================
// tensor-core stride-1 3x3 SAME conv (fp16 single-term). Templated NF.
// in: fp16 planes [px][C]. out mode 0: fp32 NCHW; mode 1: fp16 planes.
// =====================================================================
#define SINW (324 * 12)
#define MMA_SW (9 * 4 * 32)
#define MMA_SMEM (2 * SINW * 4 + 2 * MMA_SW * 16)

template <int NF>
__global__ void __launch_bounds__(256, 2) conv_mma_s1(
    const unsigned short* __restrict__ in, const uint4* __restrict__ wp,
    const float* __restrict__ bias, float* __restrict__ fout,
    unsigned short* __restrict__ bout, int C, int OC, int H, int W, int act, int mode)
{
    const int KC = C >> 4;
    const int tilesX = W >> 4;
    const int x0 = (blockIdx.x % tilesX) << 4;
    const int y0 = (blockIdx.x / tilesX) << 4;
    const int oc0 = blockIdx.y * (NF * 8);
    const int b = blockIdx.z;
    const int OCg = OC >> 3;

    extern __shared__ __align__(16) unsigned char dsm[];
    unsigned* s_in = (unsigned*)dsm;
    uint4* s_w = (uint4*)(dsm + 2 * SINW * 4);

    const unsigned short* inb = in + (size_t)b * H * W * C;
    const int tid = threadIdx.x, lane = tid & 31, wid = tid >> 5;
    const int g = lane >> 2, tg = lane & 3;

    float d[2][NF][4];
#pragma unroll
    for (int i = 0; i < 2; i++)
#pragma unroll
        for (int j = 0; j < NF; j++)
#pragma unroll
            for (int r = 0; r < 4; r++) d[i][j][r] = 0.f;

    auto stage = [&](int buf, int kc) {
        unsigned* si = s_in + buf * SINW;
        for (int i = tid; i < 648; i += 256) {
            int sp = i >> 1, q = i & 1;
            int r = sp / 18, c = sp - r * 18;
            int iy = y0 - 1 + r, ix = x0 - 1 + c;
            bool p = (unsigned)iy < (unsigned)H && (unsigned)ix < (unsigned)W;
            const unsigned short* src = inb + ((size_t)iy * W + ix) * C + (kc << 4) + (q << 3);
            cp_async16(si + sp * 12 + q * 4, src, p);
        }
        uint4* sw = s_w + buf * MMA_SW;
        const uint4* wsrc = wp + (size_t)kc * 9 * OCg * 32;
        const int tot = 9 * NF * 32;
        for (int i = tid; i < tot; i += 256) {
            int l = i & 31;
            int q = i >> 5;
            int ogl = q % NF;
            int t = q / NF;
            cp_async16(sw + (t * 4 + ogl) * 32 + l,
                       wsrc + ((size_t)t * OCg + (oc0 >> 3) + ogl) * 32 + l, true);
        }
    };

    auto compute = [&](int buf) {
        unsigned* si = s_in + buf * SINW;
        uint4* sw = s_w + buf * MMA_SW;
#pragma unroll
        for (int t = 0; t < 9; t++) {
            const int dy = t / 3, dx = t - 3 * (t / 3);
            unsigned ah[2][4];
#pragma unroll
            for (int i = 0; i < 2; i++) {
                int sp0 = (2 * wid + i + dy) * 18 + g + dx;
                const unsigned* h0 = si + sp0 * 12;
                ah[i][0] = h0[tg];       ah[i][1] = h0[96 + tg];
                ah[i][2] = h0[tg + 4];   ah[i][3] = h0[96 + tg + 4];
            }
#pragma unroll
            for (int j = 0; j < NF; j++) {
                uint4 bw = sw[(t * 4 + j) * 32 + lane];
#pragma unroll
                for (int i = 0; i < 2; i++) {
                    mma16816(d[i][j], ah[i], bw.x, bw.y);   // single fp16 term
                }
            }
        }
    };

    stage(0, 0);
    cp_commit();
    for (int kc = 0; kc < KC; kc++) {
        int buf = kc & 1;
        cp_wait0();
        __syncthreads();
        if (kc + 1 < KC) stage(buf ^ 1, kc + 1);
        cp_commit();
        compute(buf);
    }

    if (mode == 0) {
#pragma unroll
        for (int i = 0; i < 2; i++) {
            int y = y0 + 2 * wid + i;
#pragma unroll
            for (int j = 0; j < NF; j++) {
                int oc = oc0 + 8 * j + 2 * tg;
                float b0 = bias[oc], b1 = bias[oc + 1];
                size_t base0 = (((size_t)b * OC + oc) * H + y) * W + x0;
                size_t base1 = base0 + (size_t)H * W;
                fout[base0 + g]     = activate(d[i][j][0] + b0, act);
                fout[base1 + g]     = activate(d[i][j][1] + b1, act);
                fout[base0 + g + 8] = activate(d[i][j][2] + b0, act);
                fout[base1 + g + 8] = activate(d[i][j][3] + b1, act);
            }
        }
    } else {
        unsigned short* bo = bout + (size_t)b * H * W * OC;
#pragma unroll
        for (int i = 0; i < 2; i++) {
            int y = y0 + 2 * wid + i;
#pragma unroll
            for (int j = 0; j < NF; j++) {
                int oc = oc0 + 8 * j + 2 * tg;
                float b0 = bias[oc], b1 = bias[oc + 1];
                float v0 = activate(d[i][j][0] + b0, act);
                float v1 = activate(d[i][j][1] + b1, act);
                float v2 = activate(d[i][j][2] + b0, act);
                float v3 = activate(d[i][j][3] + b1, act);
                size_t px0 = (size_t)y * W + x0 + g;
                size_t px1 = px0 + 8;
                *(unsigned*)(bo + px0 * OC + oc) = pack2_f16(v0, v1);
                *(unsigned*)(bo + px1 * OC + oc) = pack2_f16(v2, v3);
            }
        }
    }
}

// =====================================================================
// s2c stride-2 conv (fp16 single-term). Tap skip by k-chunk phase.
// =====================================================================
#define SINW2 (289 * 12)
#define MMA_SW2 (4 * 4 * 32)
#define MMA_SMEM2 (2 * SINW2 * 4 + 2 * MMA_SW2 * 16)

template <int NF>
__global__ void __launch_bounds__(256, 2) conv_mma_s2c(
    const unsigned short* __restrict__ in, const uint4* __restrict__ wp,
    const float* __restrict__ bias, float* __restrict__ fout,
    unsigned short* __restrict__ bout, int C, int OC, int Hout, int Wout,
    int act, int mode)
{
    const int CC = 4 * C;
    const int KC = CC >> 4;
    const int Hin = Hout * 2, Win = Wout * 2;
    const int tilesX = Wout >> 4;
    const int x0 = (blockIdx.x % tilesX) << 4;
    const int y0 = (blockIdx.x / tilesX) << 4;
    const int oc0 = blockIdx.y * (NF * 8);
    const int b = blockIdx.z;
    const int OCg = OC >> 3;

    extern __shared__ __align__(16) unsigned char dsm[];
    unsigned* s_in = (unsigned*)dsm;
    uint4* s_w = (uint4*)(dsm + 2 * SINW2 * 4);

    const unsigned short* inb = in + (size_t)b * Hin * Win * C;
    const int tid = threadIdx.x, lane = tid & 31, wid = tid >> 5;
    const int g = lane >> 2, tg = lane & 3;

    float d[2][NF][4];
#pragma unroll
    for (int i = 0; i < 2; i++)
#pragma unroll
        for (int j = 0; j < NF; j++)
#pragma unroll
            for (int r = 0; r < 4; r++) d[i][j][r] = 0.f;

    auto stage = [&](int buf, int kc) {
        unsigned* si = s_in + buf * SINW2;
        int qph = (kc << 4) / C;
        int c0 = (kc << 4) - qph * C;
        int pa = qph >> 1, pb = qph & 1;
        for (int i = tid; i < 578; i += 256) {
            int sp = i >> 1, q = i & 1;
            int r = sp / 17, c = sp - r * 17;
            int sy = 2 * (y0 + r) + pa, sx = 2 * (x0 + c) + pb;
            bool p = sy < Hin && sx < Win;
            const unsigned short* src = inb + ((size_t)sy * Win + sx) * C + c0 + (q << 3);
            cp_async16(si + sp * 12 + q * 4, src, p);
        }
        uint4* sw = s_w + buf * MMA_SW2;
        const uint4* wsrc = wp + (size_t)kc * 4 * OCg * 32;
        const int tot = 4 * NF * 32;
        for (int i = tid; i < tot; i += 256) {
            int l = i & 31;
            int q = i >> 5;
            int ogl = q % NF;
            int t = q / NF;
            cp_async16(sw + (t * 4 + ogl) * 32 + l,
                       wsrc + ((size_t)t * OCg + (oc0 >> 3) + ogl) * 32 + l, true);
        }
    };

    auto compute = [&](int buf, int pa, int pb) {
        unsigned* si = s_in + buf * SINW2;
        uint4* sw = s_w + buf * MMA_SW2;
#pragma unroll
        for (int t = 0; t < 4; t++) {
            const int dy = t >> 1, dx = t & 1;
            if ((dy && pa) || (dx && pb)) continue;
            unsigned ah[2][4];
#pragma unroll
            for (int i = 0; i < 2; i++) {
                int sp0 = (2 * wid + i + dy) * 17 + g + dx;
                const unsigned* h0 = si + sp0 * 12;
                ah[i][0] = h0[tg];       ah[i][1] = h0[96 + tg];
                ah[i][2] = h0[tg + 4];   ah[i][3] = h0[96 + tg + 4];
            }
#pragma unroll
            for (int j = 0; j < NF; j++) {
                uint4 bw = sw[(t * 4 + j) * 32 + lane];
#pragma unroll
                for (int i = 0; i < 2; i++) {
                    mma16816(d[i][j], ah[i], bw.x, bw.y);
                }
            }
        }
    };

    stage(0, 0);
    cp_commit();
    for (int kc = 0; kc < KC; kc++) {
        int buf = kc & 1;
        cp_wait0();
        __syncthreads();
        if (kc + 1 < KC) stage(buf ^ 1, kc + 1);
        cp_commit();
        int qc = (kc << 4) / C;
        compute(buf, qc >> 1, qc & 1);
    }

    if (mode == 0) {
#pragma unroll
        for (int i = 0; i < 2; i++) {
            int y = y0 + 2 * wid + i;
#pragma unroll
            for (int j = 0; j < NF; j++) {
                int oc = oc0 + 8 * j + 2 * tg;
                float b0 = bias[oc], b1 = bias[oc + 1];
                size_t base0 = (((size_t)b * OC + oc) * Hout + y) * Wout + x0;
                size_t base1 = base0 + (size_t)Hout * Wout;
                fout[base0 + g]     = activate(d[i][j][0] + b0, act);
                fout[base1 + g]     = activate(d[i][j][1] + b1, act);
                fout[base0 + g + 8] = activate(d[i][j][2] + b0, act);
                fout[base1 + g + 8] = activate(d[i][j][3] + b1, act);
            }
        }
    } else {
        unsigned short* bo = bout + (size_t)b * Hout * Wout * OC;
#pragma unroll
        for (int i = 0; i < 2; i++) {
            int y = y0 + 2 * wid + i;
#pragma unroll
            for (int j = 0; j < NF; j++) {
                int oc = oc0 + 8 * j + 2 * tg;
                float b0 = bias[oc], b1 = bias[oc + 1];
                float v0 = activate(d[i][j][0] + b0, act);
                float v1 = activate(d[i][j][1] + b1, act);
                float v2 = activate(d[i][j][2] + b0, act);
                float v3 = activate(d[i][j][3] + b1, act);
                size_t px0 = (size_t)y * Wout + x0 + g;
                size_t px1 = px0 + 8;
                *(unsigned*)(bo + px0 * OC + oc) = pack2_f16(v0, v1);
                *(unsigned*)(bo + px1 * OC + oc) = pack2_f16(v2, v3);
            }
        }
    }
}

// =====================================================================
// t2c transposed conv (fp16 single-term). Tap skip per fragment phase. relu.
// =====================================================================
template <int NF>
__global__ void __launch_bounds__(256, 2) conv_mma_t2c(
    const unsigned short* __restrict__ in, const uint4* __restrict__ wp,
    const float* __restrict__ bias, unsigned short* __restrict__ bout,
    int C, int OC, int Hin, int Win)
{
    const int KC = C >> 4;
    const int NN = 4 * OC;
    const int OCgN = NN >> 3;
    const int Wout = Win * 2;
    const int tilesX = Win >> 4;
    const int x0 = (blockIdx.x % tilesX) << 4;
    const int y0 = (blockIdx.x / tilesX) << 4;
    const int oc0 = blockIdx.y * (NF * 8);
    const int b = blockIdx.z;

    extern __shared__ __align__(16) unsigned char dsm[];
    unsigned* s_in = (unsigned*)dsm;
    uint4* s_w = (uint4*)(dsm + 2 * SINW2 * 4);

    const unsigned short* inb = in + (size_t)b * Hin * Win * C;
    const int tid = threadIdx.x, lane = tid & 31, wid = tid >> 5;
    const int g = lane >> 2, tg = lane & 3;

    int aj[NF], bj[NF];
#pragma unroll
    for (int j = 0; j < NF; j++) {
        int qj = (oc0 + 8 * j) / OC;
        aj[j] = qj >> 1;
        bj[j] = qj & 1;
    }

    float d[2][NF][4];
#pragma unroll
    for (int i = 0; i < 2; i++)
#pragma unroll
        for (int j = 0; j < NF; j++)
#pragma unroll
            for (int r = 0; r < 4; r++) d[i][j][r] = 0.f;

    auto stage = [&](int buf, int kc) {
        unsigned* si = s_in + buf * SINW2;
        for (int i = tid; i < 578; i += 256) {
            int sp = i >> 1, q = i & 1;
            int r = sp / 17, c = sp - r * 17;
            int iy = y0 - 1 + r, ix = x0 - 1 + c;
            bool p = (unsigned)iy < (unsigned)Hin && (unsigned)ix < (unsigned)Win;
            const unsigned short* src = inb + ((size_t)iy * Win + ix) * C + (kc << 4) + (q << 3);
            cp_async16(si + sp * 12 + q * 4, src, p);
        }
        uint4* sw = s_w + buf * MMA_SW2;
        const uint4* wsrc = wp + (size_t)kc * 4 * OCgN * 32;
        const int tot = 4 * NF * 32;
        for (int i = tid; i < tot; i += 256) {
            int l = i & 31;
            int q = i >> 5;
            int ogl = q % NF;
            int t = q / NF;
            cp_async16(sw + (t * 4 + ogl) * 32 + l,
                       wsrc + ((size_t)t * OCgN + (oc0 >> 3) + ogl) * 32 + l, true);
        }
    };

    auto compute = [&](int buf) {
        unsigned* si = s_in + buf * SINW2;
        uint4* sw = s_w + buf * MMA_SW2;
#pragma unroll
        for (int t = 0; t < 4; t++) {
            const int dy = t >> 1, dx = t & 1;
            unsigned ah[2][4];
#pragma unroll
            for (int i = 0; i < 2; i++) {
                int sp0 = (2 * wid + i + dy) * 17 + g + dx;
                const unsigned* h0 = si + sp0 * 12;
                ah[i][0] = h0[tg];       ah[i][1] = h0[96 + tg];
                ah[i][2] = h0[tg + 4];   ah[i][3] = h0[96 + tg + 4];
            }
#pragma unroll
            for (int j = 0; j < NF; j++) {
                if ((dy == 0 && aj[j]) || (dx == 0 && bj[j])) continue;
                uint4 bw = sw[(t * 4 + j) * 32 + lane];
#pragma unroll
                for (int i = 0; i < 2; i++) {
                    mma16816(d[i][j], ah[i], bw.x, bw.y);
                }
            }
        }
    };

    stage(0, 0);
    cp_commit();
    for (int kc = 0; kc < KC; kc++) {
        int buf = kc & 1;
        cp_wait0();
        __syncthreads();
        if (kc + 1 < KC) stage(buf ^ 1, kc + 1);
        cp_commit();
        compute(buf);
    }

    unsigned short* bo2 = bout + (size_t)b * (2 * Hin) * Wout * OC;
#pragma unroll
    for (int i = 0; i < 2; i++) {
        int yin = y0 + 2 * wid + i;
#pragma unroll
        for (int j = 0; j < NF; j++) {
            int n0 = oc0 + 8 * j + 2 * tg;
            int q = n0 / OC;
            int oc = n0 - q * OC;
            int a = q >> 1, bph = q & 1;
            int oy = 2 * yin + a;
            float b0 = bias[oc], b1 = bias[oc + 1];
            float v0 = d[i][j][0] + b0; v0 = v0 > 0.f ? v0 : 0.f;
            float v1 = d[i][j][1] + b1; v1 = v1 > 0.f ? v1 : 0.f;
            float v2 = d[i][j][2] + b0; v2 = v2 > 0.f ? v2 : 0.f;
            float v3 = d[i][j][3] + b1; v3 = v3 > 0.f ? v3 : 0.f;
            size_t px0 = (size_t)oy * Wout + 2 * (x0 + g) + bph;
            size_t px1 = (size_t)oy * Wout + 2 * (x0 + g + 8) + bph;
            *(unsigned*)(bo2 + px0 * OC + oc) = pack2_f16(v0, v1);
            *(unsigned*)(bo2 + px1 * OC + oc) = pack2_f16(v2, v3);
        }
    }
}

// =====================================================================
// e0: fp32 NCHW in (C=3) -> fp16 planes.
// =====================================================================
__global__ void __launch_bounds__(256, 2) conv_e0(
    const float* __restrict__ in, const float* __restrict__ wgt,
    const float* __restrict__ bias, unsigned short* __restrict__ bout,
    int C, int OC, int H, int W, int act)
{
    constexpr int NT = 256;
    constexpr int ICB = 4;
    constexpr int SROW = 34;
    constexpr int SIN = 18 * SROW;

    const int tilesX = W >> 5;
    const int x0 = (blockIdx.x % tilesX) << 5;
    const int y0 = (blockIdx.x / tilesX) << 4;
    const int oc0 = blockIdx.y * 32;
    const int b = blockIdx.z;

    __shared__ __align__(16) float s_in[2][ICB][SIN];
    __shared__ __align__(16) float s_w[2][ICB][32 * 12];

    const int tid = threadIdx.x;
    const int g = tid >> 6;
    const int sp = tid & 63;
    const int ty = sp >> 3, tx = sp & 7;

    float acc[8][2][4];
#pragma unroll
    for (int o = 0; o < 8; o++)
#pragma unroll
        for (int dy = 0; dy < 2; dy++)
#pragma unroll
            for (int dx = 0; dx < 4; dx++) acc[o][dy][dx] = 0.f;

    const float* inb = in + (size_t)b * C * H * W;
    const float* wb = wgt + (size_t)oc0 * C * 9;

    auto stage_copy = [&](int buf, int ic0, int cnt) {
        const float* ins = inb + (size_t)ic0 * H * W;
        for (int i = tid; i < cnt * SIN; i += NT) {
            int ch = i / SIN, r2 = i - ch * SIN;
            int r = r2 / SROW, c2 = r2 - r * SROW;
            int iy = y0 - 1 + r, ix = x0 - 1 + c2;
            bool p = (unsigned)iy < (unsigned)H && (unsigned)ix < (unsigned)W;
            cp_async4(&s_in[buf][ch][r2], ins + (size_t)ch * H * W + (size_t)iy * W + ix, p);
        }
        for (int i = tid; i < cnt * 32 * 9; i += NT) {
            int ch = i / (32 * 9), r2 = i - ch * (32 * 9);
            int o = r2 / 9, j2 = r2 - o * 9;
            cp_async4(&s_w[buf][ch][o * 12 + j2],
                      wb + ((size_t)o * C + ic0 + ch) * 9 + j2, true);
        }
    };

    const int sbase = (2 * ty) * SROW + 4 * tx;

    auto compute_ch = [&](int buf, int ch) {
        float rr[4][6];
        const float* si = &s_in[buf][ch][sbase];
#pragma unroll
        for (int r = 0; r < 4; r++) {
            const float2* p = (const float2*)(si + r * SROW);
            float2 a = p[0], b2 = p[1], c2 = p[2];
            rr[r][0] = a.x; rr[r][1] = a.y; rr[r][2] = b2.x;
            rr[r][3] = b2.y; rr[r][4] = c2.x; rr[r][5] = c2.y;
        }
#pragma unroll
        for (int o = 0; o < 8; o++) {
            const float4* wp = (const float4*)&s_w[buf][ch][(g * 8 + o) * 12];
            float4 wa = wp[0];
            float4 wc = wp[1];
            float w8 = ((const float*)wp)[8];
#pragma unroll
            for (int dy = 0; dy < 2; dy++)
#pragma unroll
                for (int dx = 0; dx < 4; dx++) {
                    float s = acc[o][dy][dx];
                    s += wa.x * rr[dy + 0][dx + 0];
                    s += wa.y * rr[dy + 0][dx + 1];
                    s += wa.z * rr[dy + 0][dx + 2];
                    s += wa.w * rr[dy + 1][dx + 0];
                    s += wc.x * rr[dy + 1][dx + 1];
                    s += wc.y * rr[dy + 1][dx + 2];
                    s += wc.z * rr[dy + 2][dx + 0];
                    s += wc.w * rr[dy + 2][dx + 1];
                    s += w8   * rr[dy + 2][dx + 2];
                    acc[o][dy][dx] = s;
                }
        }
    };

    const int nst = (C + ICB - 1) / ICB;
    stage_copy(0, 0, C < ICB ? C : ICB);
    cp_commit();
    for (int s = 0; s < nst; s++) {
        int buf = s & 1;
        cp_wait0();
        __syncthreads();
        int icn = (s + 1) * ICB;
        if (icn < C) {
            int cn = C - icn; if (cn > ICB) cn = ICB;
            stage_copy(buf ^ 1, icn, cn);
        }
        cp_commit();
        int cnt = C - s * ICB; if (cnt > ICB) cnt = ICB;
        for (int j = 0; j < cnt; j++) compute_ch(buf, j);
    }

    float bv[8];
#pragma unroll
    for (int o = 0; o < 8; o++) bv[o] = bias[oc0 + g * 8 + o];
    unsigned short* bo = bout + (size_t)b * H * W * OC;
#pragma unroll
    for (int dy = 0; dy < 2; dy++)
#pragma unroll
        for (int dx = 0; dx < 4; dx++) {
            int y = y0 + 2 * ty + dy, x = x0 + 4 * tx + dx;
            float v[8];
#pragma unroll
            for (int o = 0; o < 8; o++) v[o] = activate(acc[o][dy][dx] + bv[o], act);
            uint4 u;
            u.x = pack2_f16(v[0], v[1]);
            u.y = pack2_f16(v[2], v[3]);
            u.z = pack2_f16(v[4], v[5]);
            u.w = pack2_f16(v[6], v[7]);
            *(uint4*)(bo + ((size_t)y * W + x) * OC + oc0 + g * 8) = u;
        }
}

// ---------------- keypoint bottleneck ----------------
__global__ void bn_stats(const float* __restrict__ R, float* __restrict__ S,
                         float* __restrict__ Sh, float* __restrict__ Sw)
{
    int bk = blockIdx.x;
    int t = threadIdx.x;
    float v = R[(size_t)bk * 256 + t];
    float a = v;
    float bsum = v * (float)(t >> 4);
    float c = v * (float)(t & 15);
#pragma unroll
    for (int off = 16; off > 0; off >>= 1) {
        a += __shfl_down_sync(0xffffffffu, a, off);
        bsum += __shfl_down_sync(0xffffffffu, bsum, off);
        c += __shfl_down_sync(0xffffffffu, c, off);
    }
    __shared__ float sa[8], sb[8], sc[8];
    int wid = t >> 5;
    if ((t & 31) == 0) { sa[wid] = a; sb[wid] = bsum; sc[wid] = c; }
    __syncthreads();
    if (t == 0) {
        float ta = 0.f, tb = 0.f, tc = 0.f;
        for (int i = 0; i < 8; i++) { ta += sa[i]; tb += sb[i]; tc += sc[i]; }
        S[bk] = ta; Sh[bk] = tb; Sw[bk] = tc;
    }
}

// maps -> fp16 planes [px][128]; grid (32, 16), block 256
__global__ void bn_maps(const float* __restrict__ S, const float* __restrict__ Sh,
                        const float* __restrict__ Sw, unsigned short* __restrict__ bout)
{
    int b = blockIdx.x;
    int spc = blockIdx.y;
    int k = threadIdx.x & 127;
    int half = threadIdx.x >> 7;
    float s = S[b * 128 + k];
    float denom = S[b * 128 + 127];
    float mu = s * (1.f / 256.f);
    float inv = 1.f / denom;
    float c0 = Sh[b * 128 + k] * inv;
    float c1 = Sw[b * 128 + k] * inv;
    unsigned short* bo = bout + (size_t)b * 256 * 128;
#pragma unroll
    for (int i = 0; i < 8; i++) {
        int sp = spc * 16 + half * 8 + i;
        float dh = (float)(sp >> 4) - c0;
        float dw = (float)(sp & 15) - c1;
        float v = mu * expf(-0.5f * (dh * dh + dw * dw));
        bo[sp * 128 + k] = f16_us(v);
    }
}

// ---------------- launch ----------------
extern "C" void kernel_launch(void* const* d_in, const int* in_sizes, int n_in,
                              void* d_out, int out_size)
{
    (void)in_sizes; (void)n_in; (void)out_size;
    const float* x = (const float*)d_in[0];
    const float* ew[7]; const float* eb[7];
    for (int j = 0; j < 7; j++) {
        ew[j] = (const float*)d_in[1 + 2 * j];
        eb[j] = (const float*)d_in[2 + 2 * j];
    }
    const float* dw[6]; const float* db[6];
    for (int j = 0; j < 6; j++) {
        dw[j] = (const float*)d_in[15 + 2 * j];
        db[j] = (const float*)d_in[16 + 2 * j];
    }
    float* out = (float*)d_out;

    float *F1, *S, *Sh, *Sw;
    unsigned short *B0, *B1;
    uint4 *wprep, *wprep2, *wprep3;
    cudaGetSymbolAddress((void**)&F1, g_f1);
    cudaGetSymbolAddress((void**)&B0, g_b0);
    cudaGetSymbolAddress((void**)&B1, g_b1);
    cudaGetSymbolAddress((void**)&wprep, g_wprep);
    cudaGetSymbolAddress((void**)&wprep2, g_wprep2);
    cudaGetSymbolAddress((void**)&wprep3, g_wprep3);
    cudaGetSymbolAddress((void**)&S, g_S);
    cudaGetSymbolAddress((void**)&Sh, g_Sh);
    cudaGetSymbolAddress((void**)&Sw, g_Sw);

    static bool attr_set = false;
    if (!attr_set) {
        cudaFuncSetAttribute(conv_mma_s1<4>, cudaFuncAttributeMaxDynamicSharedMemorySize, MMA_SMEM);
        cudaFuncSetAttribute(conv_mma_s1<2>, cudaFuncAttributeMaxDynamicSharedMemorySize, MMA_SMEM);
        cudaFuncSetAttribute(conv_mma_s2c<4>, cudaFuncAttributeMaxDynamicSharedMemorySize, MMA_SMEM2);
        cudaFuncSetAttribute(conv_mma_s2c<2>, cudaFuncAttributeMaxDynamicSharedMemorySize, MMA_SMEM2);
        cudaFuncSetAttribute(conv_mma_t2c<4>, cudaFuncAttributeMaxDynamicSharedMemorySize, MMA_SMEM2);
        attr_set = true;
    }

    const int B = 32;
    const int OFF_E1 = 0, OFF_E3 = 2304, OFF_E5 = 11520;
    const int OFF_D1 = 48384, OFF_D3 = 57600, OFF_D5 = 59904;
    const int OFF2_E2 = 0, OFF2_E4 = 8192, OFF2_E6 = 40960;
    const int OFF3_D0 = 0, OFF3_D2 = 32768, OFF3_D4 = 40960;

    prep_many<<<dim3(144, 3, 1), 256>>>(ew[1], ew[3], ew[5], wprep,
                                        OFF_E1, OFF_E3, OFF_E5, 32, 32, 64, 64, 128, 128);
    prep_many<<<dim3(36, 3, 1), 256>>>(dw[1], dw[3], dw[5], wprep,
                                       OFF_D1, OFF_D3, OFF_D5, 64, 64, 32, 32, 16, 16);
    prep_s2c<<<dim3(256, 3, 1), 256>>>(ew[2], ew[4], ew[6], wprep2,
                                       OFF2_E2, OFF2_E4, OFF2_E6,
                                       32, 64, 64, 128, 128, 128);
    prep_t2c<<<dim3(128, 3, 1), 256>>>(dw[0], dw[2], dw[4], wprep3,
                                       OFF3_D0, OFF3_D2, OFF3_D4,
                                       128, 64, 64, 32, 32, 16);

    // ---- encoder ----
    conv_e0<<<dim3(32, 1, B), 256>>>(x, ew[0], eb[0], B0, 3, 32, 128, 128, 0);
    conv_mma_s1<4><<<dim3(64, 1, B), 256, MMA_SMEM>>>(B0, wprep + OFF_E1, eb[1],
                                                      nullptr, B1, 32, 32, 128, 128, 0, 1);
    conv_mma_s2c<4><<<dim3(16, 2, B), 256, MMA_SMEM2>>>(B1, wprep2 + OFF2_E2, eb[2],
                                                        nullptr, B0, 32, 64, 64, 64, 1, 1);
    conv_mma_s1<4><<<dim3(16, 2, B), 256, MMA_SMEM>>>(B0, wprep + OFF_E3, eb[3],
                                                      nullptr, B1, 64, 64, 64, 64, 1, 1);
    conv_mma_s2c<4><<<dim3(4, 4, B), 256, MMA_SMEM2>>>(B1, wprep2 + OFF2_E4, eb[4],
                                                       nullptr, B0, 64, 128, 32, 32, 1, 1);
    conv_mma_s1<4><<<dim3(4, 4, B), 256, MMA_SMEM>>>(B0, wprep + OFF_E5, eb[5],
                                                     nullptr, B1, 128, 128, 32, 32, 1, 1);
    conv_mma_s2c<2><<<dim3(1, 8, B), 256, MMA_SMEM2>>>(B1, wprep2 + OFF2_E6, eb[6],
                                                       F1, nullptr, 128, 128, 16, 16, 3, 0);
    // ---- keypoint bottleneck ----
    bn_stats<<<4096, 256>>>(F1, S, Sh, Sw);
    bn_maps<<<dim3(32, 16, 1), 256>>>(S, Sh, Sw, B0);
    // ---- decoder ----
    conv_mma_t2c<4><<<dim3(1, 8, B), 256, MMA_SMEM2>>>(B0, wprep3 + OFF3_D0, db[0],
                                                       B1, 128, 64, 16, 16);
    conv_mma_s1<4><<<dim3(4, 2, B), 256, MMA_SMEM>>>(B1, wprep + OFF_D1, db[1],
                                                     nullptr, B0, 64, 64, 32, 32, 2, 1);
    conv_mma_t2c<4><<<dim3(4, 4, B), 256, MMA_SMEM2>>>(B0, wprep3 + OFF3_D2, db[2],
                                                       B1, 64, 32, 32, 32);
    conv_mma_s1<4><<<dim3(16, 1, B), 256, MMA_SMEM>>>(B1, wprep + OFF_D3, db[3],
                                                      nullptr, B0, 32, 32, 64, 64, 2, 1);
    conv_mma_t2c<4><<<dim3(16, 2, B), 256, MMA_SMEM2>>>(B0, wprep3 + OFF3_D4, db[4],
                                                        B1, 32, 16, 64, 64);
    conv_mma_s1<2><<<dim3(64, 1, B), 256, MMA_SMEM>>>(B1, wprep + OFF_D5, db[5],
                                                      out, nullptr, 16, 16, 128, 128, 2, 0);
}